// round 1
// baseline (speedup 1.0000x reference)
#include <cuda_runtime.h>
#include <math.h>

// ---------------- problem constants ----------------
#define NB    8          // batch
#define NPix  1024       // H*W
#define C_IN  384
#define C_QKV 1536
#define C_MG  384
#define C_F1  768
#define C_F2  384
#define NHEAD 8
#define DK    32
#define DV    128

// ---------------- scratch (device globals; no runtime alloc) ----------------
__device__ float g_yqkv[NB * C_QKV * NPix];          // 50 MB
__device__ float g_att [64LL * 1024 * 1024];          // 268 MB
__device__ float g_obuf[NB * 1024 * NPix];            // 33 MB (gelu(attn out))
__device__ float g_y2  [NB * C_MG * NPix];
__device__ float g_xr  [NB * C_IN * NPix];
__device__ float g_h1  [NB * C_F1 * NPix];
__device__ float g_y3  [NB * C_F2 * NPix];
__device__ float g_sc_qkv[C_QKV], g_sh_qkv[C_QKV];
__device__ float g_sc_mg [C_MG ], g_sh_mg [C_MG ];
__device__ float g_sc_f1 [C_F1 ], g_sh_f1 [C_F1 ];
__device__ float g_sc_f2 [C_F2 ], g_sh_f2 [C_F2 ];

__device__ __forceinline__ float gelu_exact(float v) {
    return v * normcdff(v);
}

// ---------------- classic SGEMM: C[b] = A(MxK) * B[b](KxN) ----------------
// BM=BN=128, BK=16, TM=TN=8, 256 threads. M%128==0, N%128==0, K%16==0 (all hold).
__global__ void sgemm_batched(const float* __restrict__ A,
                              const float* __restrict__ Bg,
                              float* __restrict__ Cg,
                              int M, int N, int K)
{
    const int BM = 128, BN = 128, BK = 16;
    const float* Bp = Bg + (size_t)blockIdx.z * K * N;
    float*       Cp = Cg + (size_t)blockIdx.z * M * N;

    __shared__ float As[BK][BM];
    __shared__ float Bs[BK][BN];

    int tid   = threadIdx.x;
    int tx    = tid & 15;        // n-sub
    int ty    = tid >> 4;        // m-sub
    int mBase = blockIdx.x * BM;
    int nBase = blockIdx.y * BN;

    int aRow  = tid >> 2;            // 0..63
    int aCol4 = (tid & 3) << 2;      // 0,4,8,12
    int bRow  = tid >> 5;            // 0..7
    int bCol4 = (tid & 31) << 2;     // 0..124

    float acc[8][8];
#pragma unroll
    for (int i = 0; i < 8; ++i)
#pragma unroll
        for (int j = 0; j < 8; ++j) acc[i][j] = 0.f;

    for (int k0 = 0; k0 < K; k0 += BK) {
        // load A tile (transposed into As[k][m])
#pragma unroll
        for (int r = 0; r < 128; r += 64) {
            float4 v = *(const float4*)&A[(size_t)(mBase + aRow + r) * K + k0 + aCol4];
            As[aCol4 + 0][aRow + r] = v.x;
            As[aCol4 + 1][aRow + r] = v.y;
            As[aCol4 + 2][aRow + r] = v.z;
            As[aCol4 + 3][aRow + r] = v.w;
        }
        // load B tile
#pragma unroll
        for (int r = 0; r < 16; r += 8) {
            float4 v = *(const float4*)&Bp[(size_t)(k0 + bRow + r) * N + nBase + bCol4];
            *(float4*)&Bs[bRow + r][bCol4] = v;
        }
        __syncthreads();

#pragma unroll
        for (int kk = 0; kk < BK; ++kk) {
            float4 a0 = *(float4*)&As[kk][ty * 8];
            float4 a1 = *(float4*)&As[kk][ty * 8 + 4];
            float4 b0 = *(float4*)&Bs[kk][tx * 8];
            float4 b1 = *(float4*)&Bs[kk][tx * 8 + 4];
            float ra[8] = {a0.x,a0.y,a0.z,a0.w,a1.x,a1.y,a1.z,a1.w};
            float rb[8] = {b0.x,b0.y,b0.z,b0.w,b1.x,b1.y,b1.z,b1.w};
#pragma unroll
            for (int i = 0; i < 8; ++i)
#pragma unroll
                for (int j = 0; j < 8; ++j)
                    acc[i][j] = fmaf(ra[i], rb[j], acc[i][j]);
        }
        __syncthreads();
    }

#pragma unroll
    for (int i = 0; i < 8; ++i) {
        float* crow = &Cp[(size_t)(mBase + ty * 8 + i) * N + nBase + tx * 8];
        *(float4*)&crow[0] = make_float4(acc[i][0], acc[i][1], acc[i][2], acc[i][3]);
        *(float4*)&crow[4] = make_float4(acc[i][4], acc[i][5], acc[i][6], acc[i][7]);
    }
}

// ---------------- per-channel BN stats -> fused scale/shift ----------------
__global__ void bn_stats(const float* __restrict__ y,
                         const float* __restrict__ gamma,
                         const float* __restrict__ beta,
                         float* __restrict__ scl, float* __restrict__ shf,
                         int C)
{
    int c = blockIdx.x;
    int tid = threadIdx.x;
    float s = 0.f, s2 = 0.f;
    for (int i = tid; i < NB * NPix; i += 256) {
        int b = i >> 10, n = i & 1023;
        float v = y[((size_t)b * C + c) * NPix + n];
        s  += v;
        s2 += v * v;
    }
    __shared__ float rs[256], rs2[256];
    rs[tid] = s; rs2[tid] = s2;
    __syncthreads();
    for (int off = 128; off > 0; off >>= 1) {
        if (tid < off) { rs[tid] += rs[tid + off]; rs2[tid] += rs2[tid + off]; }
        __syncthreads();
    }
    if (tid == 0) {
        const float invN = 1.f / (NB * NPix);
        float mean = rs[0] * invN;
        float var  = rs2[0] * invN - mean * mean;
        float sc   = gamma[c] * rsqrtf(var + 1e-5f);
        scl[c] = sc;
        shf[c] = beta[c] - mean * sc;
    }
}

// ---------------- attention: S = scale * Q^T K (BN applied on load) --------
__global__ void attn_scores(const float* __restrict__ yqkv,
                            const float* __restrict__ scl,
                            const float* __restrict__ shf,
                            float* __restrict__ att)
{
    int bh = blockIdx.z, b = bh >> 3, h = bh & 7;
    int mBase = blockIdx.x * 64;   // keys
    int nBase = blockIdx.y * 64;   // queries

    __shared__ float qs[32][64];
    __shared__ float ks[32][64];
    int tid = threadIdx.x;
    const float* base = yqkv + (size_t)b * C_QKV * NPix;

    for (int i = tid; i < 2048; i += 256) {
        int d = i >> 6, c = i & 63;
        int chq = h * 192 + d;
        int chk = chq + DK;
        qs[d][c] = base[(size_t)chq * NPix + nBase + c] * scl[chq] + shf[chq];
        ks[d][c] = base[(size_t)chk * NPix + mBase + c] * scl[chk] + shf[chk];
    }
    __syncthreads();

    int tx = tid & 15, ty = tid >> 4;
    float acc[4][4];
#pragma unroll
    for (int i = 0; i < 4; ++i)
#pragma unroll
        for (int j = 0; j < 4; ++j) acc[i][j] = 0.f;

#pragma unroll 8
    for (int d = 0; d < 32; ++d) {
        float4 q = *(float4*)&qs[d][ty * 4];
        float4 k = *(float4*)&ks[d][tx * 4];
        float rq[4] = {q.x,q.y,q.z,q.w};
        float rk[4] = {k.x,k.y,k.z,k.w};
#pragma unroll
        for (int i = 0; i < 4; ++i)
#pragma unroll
            for (int j = 0; j < 4; ++j)
                acc[i][j] = fmaf(rq[i], rk[j], acc[i][j]);
    }

    const float sc = 0.17677669529663687f;   // 32^-0.5
    float* out = att + ((size_t)bh * 1024 + nBase) * 1024 + mBase;
#pragma unroll
    for (int i = 0; i < 4; ++i) {
        *(float4*)&out[(size_t)(ty * 4 + i) * 1024 + tx * 4] =
            make_float4(acc[i][0]*sc, acc[i][1]*sc, acc[i][2]*sc, acc[i][3]*sc);
    }
}

// ---------------- row softmax over 1024, in place ----------------
__global__ void softmax_rows(float* __restrict__ att)
{
    float* p = att + (size_t)blockIdx.x * 1024;
    int tid = threadIdx.x;
    float4 v = *(float4*)&p[tid * 4];

    __shared__ float red[256];
    float m = fmaxf(fmaxf(v.x, v.y), fmaxf(v.z, v.w));
    red[tid] = m; __syncthreads();
    for (int off = 128; off > 0; off >>= 1) {
        if (tid < off) red[tid] = fmaxf(red[tid], red[tid + off]);
        __syncthreads();
    }
    float M = red[0];
    __syncthreads();

    v.x = __expf(v.x - M); v.y = __expf(v.y - M);
    v.z = __expf(v.z - M); v.w = __expf(v.w - M);
    red[tid] = v.x + v.y + v.z + v.w; __syncthreads();
    for (int off = 128; off > 0; off >>= 1) {
        if (tid < off) red[tid] += red[tid + off];
        __syncthreads();
    }
    float inv = 1.f / red[0];
    v.x *= inv; v.y *= inv; v.z *= inv; v.w *= inv;
    *(float4*)&p[tid * 4] = v;
}

// ---------------- O = P * V^T, gelu on write ----------------
__global__ void attn_o(const float* __restrict__ yqkv,
                       const float* __restrict__ att,
                       const float* __restrict__ scl,
                       const float* __restrict__ shf,
                       float* __restrict__ obuf)
{
    int bh = blockIdx.z, b = bh >> 3, h = bh & 7;
    int nBase = blockIdx.x * 64;
    int dBase = blockIdx.y * 64;

    __shared__ float vs[64][65];
    __shared__ float ps[64][65];
    int tid = threadIdx.x, tx = tid & 15, ty = tid >> 4;

    float acc[4][4];
#pragma unroll
    for (int i = 0; i < 4; ++i)
#pragma unroll
        for (int j = 0; j < 4; ++j) acc[i][j] = 0.f;

    const float* vbase = yqkv + ((size_t)b * C_QKV + h * 192 + 2 * DK + dBase) * NPix;
    const float* pbase = att + ((size_t)bh * 1024 + nBase) * 1024;

    for (int m0 = 0; m0 < 1024; m0 += 64) {
        for (int i = tid; i < 4096; i += 256) {
            int r = i >> 6, c = i & 63;
            int ch = h * 192 + 2 * DK + dBase + r;
            vs[r][c] = vbase[(size_t)r * NPix + m0 + c] * scl[ch] + shf[ch];
            ps[r][c] = pbase[(size_t)r * 1024 + m0 + c];
        }
        __syncthreads();
#pragma unroll 4
        for (int m = 0; m < 64; ++m) {
            float rv[4], rp[4];
#pragma unroll
            for (int i = 0; i < 4; ++i) rv[i] = vs[ty * 4 + i][m];
#pragma unroll
            for (int j = 0; j < 4; ++j) rp[j] = ps[tx * 4 + j][m];
#pragma unroll
            for (int i = 0; i < 4; ++i)
#pragma unroll
                for (int j = 0; j < 4; ++j)
                    acc[i][j] = fmaf(rv[i], rp[j], acc[i][j]);
        }
        __syncthreads();
    }

#pragma unroll
    for (int i = 0; i < 4; ++i) {
        int ch = h * DV + dBase + ty * 4 + i;
        float* ob = obuf + ((size_t)b * 1024 + ch) * NPix + nBase + tx * 4;
#pragma unroll
        for (int j = 0; j < 4; ++j) ob[j] = gelu_exact(acc[i][j]);
    }
}

// ---------------- elementwise kernels ----------------
__global__ void resadd_bn(const float* __restrict__ x,
                          const float* __restrict__ y,
                          const float* __restrict__ scl,
                          const float* __restrict__ shf,
                          float* __restrict__ o, int C, int total)
{
    int i = blockIdx.x * 256 + threadIdx.x;
    if (i >= total) return;
    int ch = (i >> 10) % C;
    o[i] = x[i] + y[i] * scl[ch] + shf[ch];
}

__global__ void bn_gelu_inplace(float* __restrict__ y,
                                const float* __restrict__ scl,
                                const float* __restrict__ shf,
                                int C, int total)
{
    int i = blockIdx.x * 256 + threadIdx.x;
    if (i >= total) return;
    int ch = (i >> 10) % C;
    y[i] = gelu_exact(y[i] * scl[ch] + shf[ch]);
}

// ---------------- host launch ----------------
extern "C" void kernel_launch(void* const* d_in, const int* in_sizes, int n_in,
                              void* d_out, int out_size)
{
    const float* x       = (const float*)d_in[0];
    const float* w_qkv   = (const float*)d_in[1];
    const float* g_qkv   = (const float*)d_in[2];
    const float* b_qkv   = (const float*)d_in[3];
    const float* w_merge = (const float*)d_in[4];
    const float* g_merge = (const float*)d_in[5];
    const float* b_merge = (const float*)d_in[6];
    const float* w_fc1   = (const float*)d_in[7];
    const float* g_fc1   = (const float*)d_in[8];
    const float* b_fc1   = (const float*)d_in[9];
    const float* w_fc2   = (const float*)d_in[10];
    const float* g_fc2   = (const float*)d_in[11];
    const float* b_fc2   = (const float*)d_in[12];
    float* out = (float*)d_out;

    float *yqkv, *att, *obuf, *y2, *xr, *h1, *y3;
    float *sc_qkv, *sh_qkv, *sc_mg, *sh_mg, *sc_f1, *sh_f1, *sc_f2, *sh_f2;
    cudaGetSymbolAddress((void**)&yqkv, g_yqkv);
    cudaGetSymbolAddress((void**)&att,  g_att);
    cudaGetSymbolAddress((void**)&obuf, g_obuf);
    cudaGetSymbolAddress((void**)&y2,   g_y2);
    cudaGetSymbolAddress((void**)&xr,   g_xr);
    cudaGetSymbolAddress((void**)&h1,   g_h1);
    cudaGetSymbolAddress((void**)&y3,   g_y3);
    cudaGetSymbolAddress((void**)&sc_qkv, g_sc_qkv);
    cudaGetSymbolAddress((void**)&sh_qkv, g_sh_qkv);
    cudaGetSymbolAddress((void**)&sc_mg,  g_sc_mg);
    cudaGetSymbolAddress((void**)&sh_mg,  g_sh_mg);
    cudaGetSymbolAddress((void**)&sc_f1,  g_sc_f1);
    cudaGetSymbolAddress((void**)&sh_f1,  g_sh_f1);
    cudaGetSymbolAddress((void**)&sc_f2,  g_sc_f2);
    cudaGetSymbolAddress((void**)&sh_f2,  g_sh_f2);

    // 1. qkv = W_qkv * x          (M=1536, K=384)
    sgemm_batched<<<dim3(C_QKV/128, NPix/128, NB), 256>>>(w_qkv, x, yqkv, C_QKV, NPix, C_IN);
    // 2. BN stats for qkv
    bn_stats<<<C_QKV, 256>>>(yqkv, g_qkv, b_qkv, sc_qkv, sh_qkv, C_QKV);
    // 3. attention scores
    attn_scores<<<dim3(16, 16, 64), 256>>>(yqkv, sc_qkv, sh_qkv, att);
    // 4. softmax
    softmax_rows<<<64 * 1024, 256>>>(att);
    // 5. O = P V^T, gelu
    attn_o<<<dim3(16, 2, 64), 256>>>(yqkv, att, sc_qkv, sh_qkv, obuf);
    // 6. y2 = W_merge * obuf      (M=384, K=1024)
    sgemm_batched<<<dim3(C_MG/128, NPix/128, NB), 256>>>(w_merge, obuf, y2, C_MG, NPix, 1024);
    // 7. BN stats merge
    bn_stats<<<C_MG, 256>>>(y2, g_merge, b_merge, sc_mg, sh_mg, C_MG);
    // 8. xr = x + bn(y2)
    {
        int total = NB * C_IN * NPix;
        resadd_bn<<<(total + 255) / 256, 256>>>(x, y2, sc_mg, sh_mg, xr, C_MG, total);
    }
    // 9. h1 = W_fc1 * xr          (M=768, K=384)
    sgemm_batched<<<dim3(C_F1/128, NPix/128, NB), 256>>>(w_fc1, xr, h1, C_F1, NPix, C_IN);
    // 10. BN stats fc1
    bn_stats<<<C_F1, 256>>>(h1, g_fc1, b_fc1, sc_f1, sh_f1, C_F1);
    // 11. h1 = gelu(bn(h1))
    {
        int total = NB * C_F1 * NPix;
        bn_gelu_inplace<<<(total + 255) / 256, 256>>>(h1, sc_f1, sh_f1, C_F1, total);
    }
    // 12. y3 = W_fc2 * h1         (M=384, K=768)
    sgemm_batched<<<dim3(C_F2/128, NPix/128, NB), 256>>>(w_fc2, h1, y3, C_F2, NPix, C_F1);
    // 13. BN stats fc2
    bn_stats<<<C_F2, 256>>>(y3, g_fc2, b_fc2, sc_f2, sh_f2, C_F2);
    // 14. out = xr + bn(y3)
    {
        int total = NB * C_F2 * NPix;
        resadd_bn<<<(total + 255) / 256, 256>>>(xr, y3, sc_f2, sh_f2, out, C_F2, total);
    }
}

// round 2
// speedup vs baseline: 1.0012x; 1.0012x over previous
#include <cuda_runtime.h>
#include <math.h>

// ---------------- problem constants ----------------
#define NB    8          // batch
#define NPix  1024       // H*W
#define C_IN  384
#define C_QKV 1536
#define C_MG  384
#define C_F1  768
#define C_F2  384
#define NHEAD 8
#define DK    32
#define DV    128

// ---------------- scratch (device globals; no runtime alloc) ----------------
__device__ float g_yqkv[NB * C_QKV * NPix];          // 50 MB
__device__ float g_att [64LL * 1024 * 1024];          // 268 MB
__device__ float g_obuf[NB * 1024 * NPix];            // 33 MB (gelu(attn out))
__device__ float g_y2  [NB * C_MG * NPix];
__device__ float g_xr  [NB * C_IN * NPix];
__device__ float g_h1  [NB * C_F1 * NPix];
__device__ float g_y3  [NB * C_F2 * NPix];
__device__ float g_sc_qkv[C_QKV], g_sh_qkv[C_QKV];
__device__ float g_sc_mg [C_MG ], g_sh_mg [C_MG ];
__device__ float g_sc_f1 [C_F1 ], g_sh_f1 [C_F1 ];
__device__ float g_sc_f2 [C_F2 ], g_sh_f2 [C_F2 ];

__device__ __forceinline__ float gelu_exact(float v) {
    return v * normcdff(v);
}

// ---------------- classic SGEMM: C[b] = A(MxK) * B[b](KxN) ----------------
// BM=BN=128, BK=16, TM=TN=8, 256 threads. M%128==0, N%128==0, K%16==0 (all hold).
__global__ void sgemm_batched(const float* __restrict__ A,
                              const float* __restrict__ Bg,
                              float* __restrict__ Cg,
                              int M, int N, int K)
{
    const int BM = 128, BN = 128, BK = 16;
    const float* Bp = Bg + (size_t)blockIdx.z * K * N;
    float*       Cp = Cg + (size_t)blockIdx.z * M * N;

    __shared__ float As[BK][BM];
    __shared__ float Bs[BK][BN];

    int tid   = threadIdx.x;
    int tx    = tid & 15;        // n-sub
    int ty    = tid >> 4;        // m-sub
    int mBase = blockIdx.x * BM;
    int nBase = blockIdx.y * BN;

    int aRow  = tid >> 2;            // 0..63
    int aCol4 = (tid & 3) << 2;      // 0,4,8,12
    int bRow  = tid >> 5;            // 0..7
    int bCol4 = (tid & 31) << 2;     // 0..124

    float acc[8][8];
#pragma unroll
    for (int i = 0; i < 8; ++i)
#pragma unroll
        for (int j = 0; j < 8; ++j) acc[i][j] = 0.f;

    for (int k0 = 0; k0 < K; k0 += BK) {
        // load A tile (transposed into As[k][m])
#pragma unroll
        for (int r = 0; r < 128; r += 64) {
            float4 v = *(const float4*)&A[(size_t)(mBase + aRow + r) * K + k0 + aCol4];
            As[aCol4 + 0][aRow + r] = v.x;
            As[aCol4 + 1][aRow + r] = v.y;
            As[aCol4 + 2][aRow + r] = v.z;
            As[aCol4 + 3][aRow + r] = v.w;
        }
        // load B tile
#pragma unroll
        for (int r = 0; r < 16; r += 8) {
            float4 v = *(const float4*)&Bp[(size_t)(k0 + bRow + r) * N + nBase + bCol4];
            *(float4*)&Bs[bRow + r][bCol4] = v;
        }
        __syncthreads();

#pragma unroll
        for (int kk = 0; kk < BK; ++kk) {
            float4 a0 = *(float4*)&As[kk][ty * 8];
            float4 a1 = *(float4*)&As[kk][ty * 8 + 4];
            float4 b0 = *(float4*)&Bs[kk][tx * 8];
            float4 b1 = *(float4*)&Bs[kk][tx * 8 + 4];
            float ra[8] = {a0.x,a0.y,a0.z,a0.w,a1.x,a1.y,a1.z,a1.w};
            float rb[8] = {b0.x,b0.y,b0.z,b0.w,b1.x,b1.y,b1.z,b1.w};
#pragma unroll
            for (int i = 0; i < 8; ++i)
#pragma unroll
                for (int j = 0; j < 8; ++j)
                    acc[i][j] = fmaf(ra[i], rb[j], acc[i][j]);
        }
        __syncthreads();
    }

#pragma unroll
    for (int i = 0; i < 8; ++i) {
        float* crow = &Cp[(size_t)(mBase + ty * 8 + i) * N + nBase + tx * 8];
        *(float4*)&crow[0] = make_float4(acc[i][0], acc[i][1], acc[i][2], acc[i][3]);
        *(float4*)&crow[4] = make_float4(acc[i][4], acc[i][5], acc[i][6], acc[i][7]);
    }
}

// ---------------- per-channel BN stats -> fused scale/shift ----------------
__global__ void bn_stats(const float* __restrict__ y,
                         const float* __restrict__ gamma,
                         const float* __restrict__ beta,
                         float* __restrict__ scl, float* __restrict__ shf,
                         int C)
{
    int c = blockIdx.x;
    int tid = threadIdx.x;
    float s = 0.f, s2 = 0.f;
    for (int i = tid; i < NB * NPix; i += 256) {
        int b = i >> 10, n = i & 1023;
        float v = y[((size_t)b * C + c) * NPix + n];
        s  += v;
        s2 += v * v;
    }
    __shared__ float rs[256], rs2[256];
    rs[tid] = s; rs2[tid] = s2;
    __syncthreads();
    for (int off = 128; off > 0; off >>= 1) {
        if (tid < off) { rs[tid] += rs[tid + off]; rs2[tid] += rs2[tid + off]; }
        __syncthreads();
    }
    if (tid == 0) {
        const float invN = 1.f / (NB * NPix);
        float mean = rs[0] * invN;
        float var  = rs2[0] * invN - mean * mean;
        float sc   = gamma[c] * rsqrtf(var + 1e-5f);
        scl[c] = sc;
        shf[c] = beta[c] - mean * sc;
    }
}

// ---------------- attention: S = scale * Q^T K (BN applied on load) --------
__global__ void attn_scores(const float* __restrict__ yqkv,
                            const float* __restrict__ scl,
                            const float* __restrict__ shf,
                            float* __restrict__ att)
{
    int bh = blockIdx.z, b = bh >> 3, h = bh & 7;
    int mBase = blockIdx.x * 64;   // keys
    int nBase = blockIdx.y * 64;   // queries

    __shared__ float qs[32][64];
    __shared__ float ks[32][64];
    int tid = threadIdx.x;
    const float* base = yqkv + (size_t)b * C_QKV * NPix;

    for (int i = tid; i < 2048; i += 256) {
        int d = i >> 6, c = i & 63;
        int chq = h * 192 + d;
        int chk = chq + DK;
        qs[d][c] = base[(size_t)chq * NPix + nBase + c] * scl[chq] + shf[chq];
        ks[d][c] = base[(size_t)chk * NPix + mBase + c] * scl[chk] + shf[chk];
    }
    __syncthreads();

    int tx = tid & 15, ty = tid >> 4;
    float acc[4][4];
#pragma unroll
    for (int i = 0; i < 4; ++i)
#pragma unroll
        for (int j = 0; j < 4; ++j) acc[i][j] = 0.f;

#pragma unroll 8
    for (int d = 0; d < 32; ++d) {
        float4 q = *(float4*)&qs[d][ty * 4];
        float4 k = *(float4*)&ks[d][tx * 4];
        float rq[4] = {q.x,q.y,q.z,q.w};
        float rk[4] = {k.x,k.y,k.z,k.w};
#pragma unroll
        for (int i = 0; i < 4; ++i)
#pragma unroll
            for (int j = 0; j < 4; ++j)
                acc[i][j] = fmaf(rq[i], rk[j], acc[i][j]);
    }

    const float sc = 0.17677669529663687f;   // 32^-0.5
    float* out = att + ((size_t)bh * 1024 + nBase) * 1024 + mBase;
#pragma unroll
    for (int i = 0; i < 4; ++i) {
        *(float4*)&out[(size_t)(ty * 4 + i) * 1024 + tx * 4] =
            make_float4(acc[i][0]*sc, acc[i][1]*sc, acc[i][2]*sc, acc[i][3]*sc);
    }
}

// ---------------- row softmax over 1024, in place ----------------
__global__ void softmax_rows(float* __restrict__ att)
{
    float* p = att + (size_t)blockIdx.x * 1024;
    int tid = threadIdx.x;
    float4 v = *(float4*)&p[tid * 4];

    __shared__ float red[256];
    float m = fmaxf(fmaxf(v.x, v.y), fmaxf(v.z, v.w));
    red[tid] = m; __syncthreads();
    for (int off = 128; off > 0; off >>= 1) {
        if (tid < off) red[tid] = fmaxf(red[tid], red[tid + off]);
        __syncthreads();
    }
    float M = red[0];
    __syncthreads();

    v.x = __expf(v.x - M); v.y = __expf(v.y - M);
    v.z = __expf(v.z - M); v.w = __expf(v.w - M);
    red[tid] = v.x + v.y + v.z + v.w; __syncthreads();
    for (int off = 128; off > 0; off >>= 1) {
        if (tid < off) red[tid] += red[tid + off];
        __syncthreads();
    }
    float inv = 1.f / red[0];
    v.x *= inv; v.y *= inv; v.z *= inv; v.w *= inv;
    *(float4*)&p[tid * 4] = v;
}

// ---------------- O = P * V^T, gelu on write ----------------
__global__ void attn_o(const float* __restrict__ yqkv,
                       const float* __restrict__ att,
                       const float* __restrict__ scl,
                       const float* __restrict__ shf,
                       float* __restrict__ obuf)
{
    int bh = blockIdx.z, b = bh >> 3, h = bh & 7;
    int nBase = blockIdx.x * 64;
    int dBase = blockIdx.y * 64;

    __shared__ float vs[64][65];
    __shared__ float ps[64][65];
    int tid = threadIdx.x, tx = tid & 15, ty = tid >> 4;

    float acc[4][4];
#pragma unroll
    for (int i = 0; i < 4; ++i)
#pragma unroll
        for (int j = 0; j < 4; ++j) acc[i][j] = 0.f;

    const float* vbase = yqkv + ((size_t)b * C_QKV + h * 192 + 2 * DK + dBase) * NPix;
    const float* pbase = att + ((size_t)bh * 1024 + nBase) * 1024;

    for (int m0 = 0; m0 < 1024; m0 += 64) {
        for (int i = tid; i < 4096; i += 256) {
            int r = i >> 6, c = i & 63;
            int ch = h * 192 + 2 * DK + dBase + r;
            vs[r][c] = vbase[(size_t)r * NPix + m0 + c] * scl[ch] + shf[ch];
            ps[r][c] = pbase[(size_t)r * 1024 + m0 + c];
        }
        __syncthreads();
#pragma unroll 4
        for (int m = 0; m < 64; ++m) {
            float rv[4], rp[4];
#pragma unroll
            for (int i = 0; i < 4; ++i) rv[i] = vs[ty * 4 + i][m];
#pragma unroll
            for (int j = 0; j < 4; ++j) rp[j] = ps[tx * 4 + j][m];
#pragma unroll
            for (int i = 0; i < 4; ++i)
#pragma unroll
                for (int j = 0; j < 4; ++j)
                    acc[i][j] = fmaf(rv[i], rp[j], acc[i][j]);
        }
        __syncthreads();
    }

#pragma unroll
    for (int i = 0; i < 4; ++i) {
        int ch = h * DV + dBase + ty * 4 + i;
        float* ob = obuf + ((size_t)b * 1024 + ch) * NPix + nBase + tx * 4;
#pragma unroll
        for (int j = 0; j < 4; ++j) ob[j] = gelu_exact(acc[i][j]);
    }
}

// ---------------- elementwise kernels ----------------
__global__ void resadd_bn(const float* __restrict__ x,
                          const float* __restrict__ y,
                          const float* __restrict__ scl,
                          const float* __restrict__ shf,
                          float* __restrict__ o, int C, int total)
{
    int i = blockIdx.x * 256 + threadIdx.x;
    if (i >= total) return;
    int ch = (i >> 10) % C;
    o[i] = x[i] + y[i] * scl[ch] + shf[ch];
}

__global__ void bn_gelu_inplace(float* __restrict__ y,
                                const float* __restrict__ scl,
                                const float* __restrict__ shf,
                                int C, int total)
{
    int i = blockIdx.x * 256 + threadIdx.x;
    if (i >= total) return;
    int ch = (i >> 10) % C;
    y[i] = gelu_exact(y[i] * scl[ch] + shf[ch]);
}

// ---------------- host launch ----------------
extern "C" void kernel_launch(void* const* d_in, const int* in_sizes, int n_in,
                              void* d_out, int out_size)
{
    const float* x       = (const float*)d_in[0];
    const float* w_qkv   = (const float*)d_in[1];
    const float* g_qkv   = (const float*)d_in[2];
    const float* b_qkv   = (const float*)d_in[3];
    const float* w_merge = (const float*)d_in[4];
    const float* g_merge = (const float*)d_in[5];
    const float* b_merge = (const float*)d_in[6];
    const float* w_fc1   = (const float*)d_in[7];
    const float* g_fc1   = (const float*)d_in[8];
    const float* b_fc1   = (const float*)d_in[9];
    const float* w_fc2   = (const float*)d_in[10];
    const float* g_fc2   = (const float*)d_in[11];
    const float* b_fc2   = (const float*)d_in[12];
    float* out = (float*)d_out;

    float *yqkv, *att, *obuf, *y2, *xr, *h1, *y3;
    float *sc_qkv, *sh_qkv, *sc_mg, *sh_mg, *sc_f1, *sh_f1, *sc_f2, *sh_f2;
    cudaGetSymbolAddress((void**)&yqkv, g_yqkv);
    cudaGetSymbolAddress((void**)&att,  g_att);
    cudaGetSymbolAddress((void**)&obuf, g_obuf);
    cudaGetSymbolAddress((void**)&y2,   g_y2);
    cudaGetSymbolAddress((void**)&xr,   g_xr);
    cudaGetSymbolAddress((void**)&h1,   g_h1);
    cudaGetSymbolAddress((void**)&y3,   g_y3);
    cudaGetSymbolAddress((void**)&sc_qkv, g_sc_qkv);
    cudaGetSymbolAddress((void**)&sh_qkv, g_sh_qkv);
    cudaGetSymbolAddress((void**)&sc_mg,  g_sc_mg);
    cudaGetSymbolAddress((void**)&sh_mg,  g_sh_mg);
    cudaGetSymbolAddress((void**)&sc_f1,  g_sc_f1);
    cudaGetSymbolAddress((void**)&sh_f1,  g_sh_f1);
    cudaGetSymbolAddress((void**)&sc_f2,  g_sc_f2);
    cudaGetSymbolAddress((void**)&sh_f2,  g_sh_f2);

    // 1. qkv = W_qkv * x          (M=1536, K=384)
    sgemm_batched<<<dim3(C_QKV/128, NPix/128, NB), 256>>>(w_qkv, x, yqkv, C_QKV, NPix, C_IN);
    // 2. BN stats for qkv
    bn_stats<<<C_QKV, 256>>>(yqkv, g_qkv, b_qkv, sc_qkv, sh_qkv, C_QKV);
    // 3. attention scores
    attn_scores<<<dim3(16, 16, 64), 256>>>(yqkv, sc_qkv, sh_qkv, att);
    // 4. softmax
    softmax_rows<<<64 * 1024, 256>>>(att);
    // 5. O = P V^T, gelu
    attn_o<<<dim3(16, 2, 64), 256>>>(yqkv, att, sc_qkv, sh_qkv, obuf);
    // 6. y2 = W_merge * obuf      (M=384, K=1024)
    sgemm_batched<<<dim3(C_MG/128, NPix/128, NB), 256>>>(w_merge, obuf, y2, C_MG, NPix, 1024);
    // 7. BN stats merge
    bn_stats<<<C_MG, 256>>>(y2, g_merge, b_merge, sc_mg, sh_mg, C_MG);
    // 8. xr = x + bn(y2)
    {
        int total = NB * C_IN * NPix;
        resadd_bn<<<(total + 255) / 256, 256>>>(x, y2, sc_mg, sh_mg, xr, C_MG, total);
    }
    // 9. h1 = W_fc1 * xr          (M=768, K=384)
    sgemm_batched<<<dim3(C_F1/128, NPix/128, NB), 256>>>(w_fc1, xr, h1, C_F1, NPix, C_IN);
    // 10. BN stats fc1
    bn_stats<<<C_F1, 256>>>(h1, g_fc1, b_fc1, sc_f1, sh_f1, C_F1);
    // 11. h1 = gelu(bn(h1))
    {
        int total = NB * C_F1 * NPix;
        bn_gelu_inplace<<<(total + 255) / 256, 256>>>(h1, sc_f1, sh_f1, C_F1, total);
    }
    // 12. y3 = W_fc2 * h1         (M=384, K=768)
    sgemm_batched<<<dim3(C_F2/128, NPix/128, NB), 256>>>(w_fc2, h1, y3, C_F2, NPix, C_F1);
    // 13. BN stats fc2
    bn_stats<<<C_F2, 256>>>(y3, g_fc2, b_fc2, sc_f2, sh_f2, C_F2);
    // 14. out = xr + bn(y3)
    {
        int total = NB * C_F2 * NPix;
        resadd_bn<<<(total + 255) / 256, 256>>>(xr, y3, sc_f2, sh_f2, out, C_F2, total);
    }
}

// round 4
// speedup vs baseline: 1.2118x; 1.2104x over previous
#include <cuda_runtime.h>
#include <cstdint>
#include <math.h>

#define NB    8
#define NPix  1024
#define C_IN  384
#define C_QKV 1536
#define C_MG  384
#define C_F1  768
#define C_F2  384
#define DK    32
#define DV    128

__device__ float g_yqkv[NB * C_QKV * NPix];
__device__ float g_att [64LL * 1024 * 1024];
__device__ float g_obuf[NB * 1024 * NPix];
__device__ float g_y2  [NB * C_MG * NPix];
__device__ float g_xr  [NB * C_IN * NPix];
__device__ float g_h1  [NB * C_F1 * NPix];
__device__ float g_y3  [NB * C_F2 * NPix];
__device__ float g_sc_qkv[C_QKV], g_sh_qkv[C_QKV];
__device__ float g_sc_mg [C_MG ], g_sh_mg [C_MG ];
__device__ float g_sc_f1 [C_F1 ], g_sh_f1 [C_F1 ];
__device__ float g_sc_f2 [C_F2 ], g_sh_f2 [C_F2 ];

__device__ __forceinline__ float gelu_exact(float v) { return v * normcdff(v); }

// ---------------- tf32 mma.sync GEMM: C[b](M,N) = A(M,K) * B[b](K,N) ------
// 128x128 CTA tile, BK=32. A staged transposed As[k][m], B direct Bs[k][n],
// both padded to stride 136 (frag loads bank-conflict-free).
// 8 warps: warp_m = wid&1 (64 rows), warp_n = wid>>1 (32 cols).
// Fragments per PTX m16n8k8.row.col tf32 layout.

__device__ __forceinline__ void mma_tf32_16x8x8(float d[4],
                                                const uint32_t a[4],
                                                const uint32_t b[2])
{
    asm volatile(
        "mma.sync.aligned.m16n8k8.row.col.f32.tf32.tf32.f32 "
        "{%0,%1,%2,%3}, {%4,%5,%6,%7}, {%8,%9}, {%0,%1,%2,%3};"
        : "+f"(d[0]), "+f"(d[1]), "+f"(d[2]), "+f"(d[3])
        : "r"(a[0]), "r"(a[1]), "r"(a[2]), "r"(a[3]), "r"(b[0]), "r"(b[1]));
}

__global__ void __launch_bounds__(256) tf32_gemm(const float* __restrict__ A,
                                                 const float* __restrict__ Bg,
                                                 float* __restrict__ Cg,
                                                 int M, int N, int K)
{
    __shared__ float As[32][136];   // [k][m], padded
    __shared__ float Bs[32][136];   // [k][n], padded

    const int tid  = threadIdx.x;
    const int wid  = tid >> 5;
    const int lane = tid & 31;
    const int gid  = lane >> 2;     // group id 0..7
    const int tid4 = lane & 3;      // 0..3
    const int wm   = (wid & 1) * 64;
    const int wn   = (wid >> 1) * 32;

    const int mBase = blockIdx.x * 128, nBase = blockIdx.y * 128;
    const float* Bp = Bg + (size_t)blockIdx.z * K * N;
    float*       Cp = Cg + (size_t)blockIdx.z * M * N;

    float d[4][4][4];
#pragma unroll
    for (int mi = 0; mi < 4; ++mi)
#pragma unroll
        for (int ni = 0; ni < 4; ++ni)
#pragma unroll
            for (int r = 0; r < 4; ++r) d[mi][ni][r] = 0.f;

    for (int k0 = 0; k0 < K; k0 += 32) {
        // A tile: gmem [m][k] -> smem As[k][m] (transpose on store)
#pragma unroll
        for (int t = 0; t < 4; ++t) {
            int c  = tid + t * 256;          // 0..1023 float4 chunks
            int m  = c >> 3, k4 = c & 7;
            float4 v = *(const float4*)&A[(size_t)(mBase + m) * K + k0 + (k4 << 2)];
            As[k4 * 4 + 0][m] = v.x;
            As[k4 * 4 + 1][m] = v.y;
            As[k4 * 4 + 2][m] = v.z;
            As[k4 * 4 + 3][m] = v.w;
        }
        // B tile: gmem [k][n] -> smem Bs[k][n] (direct, float4)
#pragma unroll
        for (int t = 0; t < 4; ++t) {
            int c = tid + t * 256;
            int k = c >> 5, n4 = c & 31;
            float4 v = *(const float4*)&Bp[(size_t)(k0 + k) * N + nBase + (n4 << 2)];
            *(float4*)&Bs[k][n4 << 2] = v;
        }
        __syncthreads();

#pragma unroll
        for (int kk = 0; kk < 32; kk += 8) {
            uint32_t af[4][4], bf[4][2];
#pragma unroll
            for (int mi = 0; mi < 4; ++mi) {
                int mr = wm + mi * 16 + gid;
                af[mi][0] = __float_as_uint(As[kk + tid4][mr]);
                af[mi][1] = __float_as_uint(As[kk + tid4][mr + 8]);
                af[mi][2] = __float_as_uint(As[kk + tid4 + 4][mr]);
                af[mi][3] = __float_as_uint(As[kk + tid4 + 4][mr + 8]);
            }
#pragma unroll
            for (int ni = 0; ni < 4; ++ni) {
                int nc = wn + ni * 8 + gid;
                bf[ni][0] = __float_as_uint(Bs[kk + tid4][nc]);
                bf[ni][1] = __float_as_uint(Bs[kk + tid4 + 4][nc]);
            }
#pragma unroll
            for (int mi = 0; mi < 4; ++mi)
#pragma unroll
                for (int ni = 0; ni < 4; ++ni)
                    mma_tf32_16x8x8(d[mi][ni], af[mi], bf[ni]);
        }
        __syncthreads();
    }

    // epilogue: c0,c1 at (row, 2*tid4), c2,c3 at (row+8, 2*tid4)
#pragma unroll
    for (int mi = 0; mi < 4; ++mi) {
        int row = mBase + wm + mi * 16 + gid;
#pragma unroll
        for (int ni = 0; ni < 4; ++ni) {
            int col = nBase + wn + ni * 8 + 2 * tid4;
            *(float2*)&Cp[(size_t)row * N + col] =
                make_float2(d[mi][ni][0], d[mi][ni][1]);
            *(float2*)&Cp[(size_t)(row + 8) * N + col] =
                make_float2(d[mi][ni][2], d[mi][ni][3]);
        }
    }
}

// ---------------- BN stats -> fused scale/shift ----------------
__global__ void bn_stats(const float* __restrict__ y,
                         const float* __restrict__ gamma,
                         const float* __restrict__ beta,
                         float* __restrict__ scl, float* __restrict__ shf, int C)
{
    int c = blockIdx.x, tid = threadIdx.x;
    float s = 0.f, s2 = 0.f;
    for (int i = tid; i < NB * NPix; i += 256) {
        int b = i >> 10, n = i & 1023;
        float v = y[((size_t)b * C + c) * NPix + n];
        s += v; s2 += v * v;
    }
    __shared__ float rs[256], rs2[256];
    rs[tid] = s; rs2[tid] = s2;
    __syncthreads();
    for (int off = 128; off > 0; off >>= 1) {
        if (tid < off) { rs[tid] += rs[tid + off]; rs2[tid] += rs2[tid + off]; }
        __syncthreads();
    }
    if (tid == 0) {
        const float invN = 1.f / (NB * NPix);
        float mean = rs[0] * invN;
        float var  = rs2[0] * invN - mean * mean;
        float sc   = gamma[c] * rsqrtf(var + 1e-5f);
        scl[c] = sc;
        shf[c] = beta[c] - mean * sc;
    }
}

// ---------------- attention ----------------
__global__ void attn_scores(const float* __restrict__ yqkv,
                            const float* __restrict__ scl,
                            const float* __restrict__ shf,
                            float* __restrict__ att)
{
    int bh = blockIdx.z, b = bh >> 3, h = bh & 7;
    int mBase = blockIdx.x * 64, nBase = blockIdx.y * 64;
    __shared__ float qs[32][64];
    __shared__ float ks[32][64];
    int tid = threadIdx.x;
    const float* base = yqkv + (size_t)b * C_QKV * NPix;

    for (int i = tid; i < 2048; i += 256) {
        int d = i >> 6, c = i & 63;
        int chq = h * 192 + d, chk = chq + DK;
        qs[d][c] = base[(size_t)chq * NPix + nBase + c] * scl[chq] + shf[chq];
        ks[d][c] = base[(size_t)chk * NPix + mBase + c] * scl[chk] + shf[chk];
    }
    __syncthreads();

    int tx = tid & 15, ty = tid >> 4;
    float acc[4][4];
#pragma unroll
    for (int i = 0; i < 4; ++i)
#pragma unroll
        for (int j = 0; j < 4; ++j) acc[i][j] = 0.f;

#pragma unroll 8
    for (int d = 0; d < 32; ++d) {
        float4 q = *(float4*)&qs[d][ty * 4];
        float4 k = *(float4*)&ks[d][tx * 4];
        float rq[4] = {q.x,q.y,q.z,q.w}, rk[4] = {k.x,k.y,k.z,k.w};
#pragma unroll
        for (int i = 0; i < 4; ++i)
#pragma unroll
            for (int j = 0; j < 4; ++j)
                acc[i][j] = fmaf(rq[i], rk[j], acc[i][j]);
    }
    const float sc = 0.17677669529663687f;
    float* out = att + ((size_t)bh * 1024 + nBase) * 1024 + mBase;
#pragma unroll
    for (int i = 0; i < 4; ++i)
        *(float4*)&out[(size_t)(ty * 4 + i) * 1024 + tx * 4] =
            make_float4(acc[i][0]*sc, acc[i][1]*sc, acc[i][2]*sc, acc[i][3]*sc);
}

__global__ void softmax_rows(float* __restrict__ att)
{
    float* p = att + (size_t)blockIdx.x * 1024;
    int tid = threadIdx.x;
    float4 v = *(float4*)&p[tid * 4];
    __shared__ float red[256];
    float m = fmaxf(fmaxf(v.x, v.y), fmaxf(v.z, v.w));
    red[tid] = m; __syncthreads();
    for (int off = 128; off > 0; off >>= 1) {
        if (tid < off) red[tid] = fmaxf(red[tid], red[tid + off]);
        __syncthreads();
    }
    float M = red[0];
    __syncthreads();
    v.x = __expf(v.x - M); v.y = __expf(v.y - M);
    v.z = __expf(v.z - M); v.w = __expf(v.w - M);
    red[tid] = v.x + v.y + v.z + v.w; __syncthreads();
    for (int off = 128; off > 0; off >>= 1) {
        if (tid < off) red[tid] += red[tid + off];
        __syncthreads();
    }
    float inv = 1.f / red[0];
    v.x *= inv; v.y *= inv; v.z *= inv; v.w *= inv;
    *(float4*)&p[tid * 4] = v;
}

__global__ void attn_o(const float* __restrict__ yqkv,
                       const float* __restrict__ att,
                       const float* __restrict__ scl,
                       const float* __restrict__ shf,
                       float* __restrict__ obuf)
{
    int bh = blockIdx.z, b = bh >> 3, h = bh & 7;
    int nBase = blockIdx.x * 64, dBase = blockIdx.y * 64;
    __shared__ float vs[64][65];
    __shared__ float ps[64][65];
    int tid = threadIdx.x, tx = tid & 15, ty = tid >> 4;
    float acc[4][4];
#pragma unroll
    for (int i = 0; i < 4; ++i)
#pragma unroll
        for (int j = 0; j < 4; ++j) acc[i][j] = 0.f;

    const float* vbase = yqkv + ((size_t)b * C_QKV + h * 192 + 2 * DK + dBase) * NPix;
    const float* pbase = att + ((size_t)bh * 1024 + nBase) * 1024;

    for (int m0 = 0; m0 < 1024; m0 += 64) {
        for (int i = tid; i < 4096; i += 256) {
            int r = i >> 6, c = i & 63;
            int ch = h * 192 + 2 * DK + dBase + r;
            vs[r][c] = vbase[(size_t)r * NPix + m0 + c] * scl[ch] + shf[ch];
            ps[r][c] = pbase[(size_t)r * 1024 + m0 + c];
        }
        __syncthreads();
#pragma unroll 4
        for (int m = 0; m < 64; ++m) {
            float rv[4], rp[4];
#pragma unroll
            for (int i = 0; i < 4; ++i) rv[i] = vs[ty * 4 + i][m];
#pragma unroll
            for (int j = 0; j < 4; ++j) rp[j] = ps[tx * 4 + j][m];
#pragma unroll
            for (int i = 0; i < 4; ++i)
#pragma unroll
                for (int j = 0; j < 4; ++j)
                    acc[i][j] = fmaf(rv[i], rp[j], acc[i][j]);
        }
        __syncthreads();
    }
#pragma unroll
    for (int i = 0; i < 4; ++i) {
        int ch = h * DV + dBase + ty * 4 + i;
        float* ob = obuf + ((size_t)b * 1024 + ch) * NPix + nBase + tx * 4;
#pragma unroll
        for (int j = 0; j < 4; ++j) ob[j] = gelu_exact(acc[i][j]);
    }
}

// ---------------- elementwise ----------------
__global__ void resadd_bn(const float* __restrict__ x, const float* __restrict__ y,
                          const float* __restrict__ scl, const float* __restrict__ shf,
                          float* __restrict__ o, int C, int total)
{
    int i = blockIdx.x * 256 + threadIdx.x;
    if (i >= total) return;
    int ch = (i >> 10) % C;
    o[i] = x[i] + y[i] * scl[ch] + shf[ch];
}
__global__ void bn_gelu_inplace(float* __restrict__ y,
                                const float* __restrict__ scl,
                                const float* __restrict__ shf, int C, int total)
{
    int i = blockIdx.x * 256 + threadIdx.x;
    if (i >= total) return;
    int ch = (i >> 10) % C;
    y[i] = gelu_exact(y[i] * scl[ch] + shf[ch]);
}

// ---------------- host ----------------
extern "C" void kernel_launch(void* const* d_in, const int* in_sizes, int n_in,
                              void* d_out, int out_size)
{
    const float* x       = (const float*)d_in[0];
    const float* w_qkv   = (const float*)d_in[1];
    const float* gq      = (const float*)d_in[2];
    const float* bq      = (const float*)d_in[3];
    const float* w_merge = (const float*)d_in[4];
    const float* gm      = (const float*)d_in[5];
    const float* bm      = (const float*)d_in[6];
    const float* w_fc1   = (const float*)d_in[7];
    const float* g1      = (const float*)d_in[8];
    const float* b1      = (const float*)d_in[9];
    const float* w_fc2   = (const float*)d_in[10];
    const float* g2      = (const float*)d_in[11];
    const float* b2      = (const float*)d_in[12];
    float* out = (float*)d_out;

    float *yqkv, *att, *obuf, *y2, *xr, *h1, *y3;
    float *scq, *shq, *scm, *shm, *sc1, *sh1, *sc2, *sh2;
    cudaGetSymbolAddress((void**)&yqkv, g_yqkv);
    cudaGetSymbolAddress((void**)&att,  g_att);
    cudaGetSymbolAddress((void**)&obuf, g_obuf);
    cudaGetSymbolAddress((void**)&y2,   g_y2);
    cudaGetSymbolAddress((void**)&xr,   g_xr);
    cudaGetSymbolAddress((void**)&h1,   g_h1);
    cudaGetSymbolAddress((void**)&y3,   g_y3);
    cudaGetSymbolAddress((void**)&scq, g_sc_qkv);
    cudaGetSymbolAddress((void**)&shq, g_sh_qkv);
    cudaGetSymbolAddress((void**)&scm, g_sc_mg);
    cudaGetSymbolAddress((void**)&shm, g_sh_mg);
    cudaGetSymbolAddress((void**)&sc1, g_sc_f1);
    cudaGetSymbolAddress((void**)&sh1, g_sh_f1);
    cudaGetSymbolAddress((void**)&sc2, g_sc_f2);
    cudaGetSymbolAddress((void**)&sh2, g_sh_f2);

    tf32_gemm<<<dim3(C_QKV/128, NPix/128, NB), 256>>>(w_qkv, x, yqkv, C_QKV, NPix, C_IN);
    bn_stats<<<C_QKV, 256>>>(yqkv, gq, bq, scq, shq, C_QKV);
    attn_scores<<<dim3(16, 16, 64), 256>>>(yqkv, scq, shq, att);
    softmax_rows<<<64 * 1024, 256>>>(att);
    attn_o<<<dim3(16, 2, 64), 256>>>(yqkv, att, scq, shq, obuf);
    tf32_gemm<<<dim3(C_MG/128, NPix/128, NB), 256>>>(w_merge, obuf, y2, C_MG, NPix, 1024);
    bn_stats<<<C_MG, 256>>>(y2, gm, bm, scm, shm, C_MG);
    {
        int total = NB * C_IN * NPix;
        resadd_bn<<<(total + 255) / 256, 256>>>(x, y2, scm, shm, xr, C_MG, total);
    }
    tf32_gemm<<<dim3(C_F1/128, NPix/128, NB), 256>>>(w_fc1, xr, h1, C_F1, NPix, C_IN);
    bn_stats<<<C_F1, 256>>>(h1, g1, b1, sc1, sh1, C_F1);
    {
        int total = NB * C_F1 * NPix;
        bn_gelu_inplace<<<(total + 255) / 256, 256>>>(h1, sc1, sh1, C_F1, total);
    }
    tf32_gemm<<<dim3(C_F2/128, NPix/128, NB), 256>>>(w_fc2, h1, y3, C_F2, NPix, C_F1);
    bn_stats<<<C_F2, 256>>>(y3, g2, b2, sc2, sh2, C_F2);
    {
        int total = NB * C_F2 * NPix;
        resadd_bn<<<(total + 255) / 256, 256>>>(xr, y3, sc2, sh2, out, C_F2, total);
    }
}

// round 5
// speedup vs baseline: 1.9933x; 1.6449x over previous
#include <cuda_runtime.h>
#include <cstdint>
#include <math.h>

#define NB    8
#define NPix  1024
#define C_IN  384
#define C_QKV 1536
#define C_MG  384
#define C_F1  768
#define C_F2  384
#define DK    32
#define DV    128

__device__ float g_yqkv[NB * C_QKV * NPix];
__device__ float g_obuf[NB * 1024 * NPix];
__device__ float g_y2  [NB * C_MG * NPix];
__device__ float g_xr  [NB * C_IN * NPix];
__device__ float g_h1  [NB * C_F1 * NPix];
__device__ float g_y3  [NB * C_F2 * NPix];
__device__ float g_sc_qkv[C_QKV], g_sh_qkv[C_QKV];
__device__ float g_sc_mg [C_MG ], g_sh_mg [C_MG ];
__device__ float g_sc_f1 [C_F1 ], g_sh_f1 [C_F1 ];
__device__ float g_sc_f2 [C_F2 ], g_sh_f2 [C_F2 ];

__device__ __forceinline__ float gelu_exact(float v) { return v * normcdff(v); }

// round-to-nearest tf32 (kept in a float register; exactly representable)
__device__ __forceinline__ float f2tf(float f) {
    uint32_t r;
    asm("cvt.rna.tf32.f32 %0, %1;" : "=r"(r) : "f"(f));
    return __uint_as_float(r);
}

__device__ __forceinline__ void mma_tf32_16x8x8(float d[4],
                                                const uint32_t a[4],
                                                const uint32_t b[2])
{
    asm volatile(
        "mma.sync.aligned.m16n8k8.row.col.f32.tf32.tf32.f32 "
        "{%0,%1,%2,%3}, {%4,%5,%6,%7}, {%8,%9}, {%0,%1,%2,%3};"
        : "+f"(d[0]), "+f"(d[1]), "+f"(d[2]), "+f"(d[3])
        : "r"(a[0]), "r"(a[1]), "r"(a[2]), "r"(a[3]), "r"(b[0]), "r"(b[1]));
}

// ---------------- tf32 mma.sync GEMM: C[b](M,N) = A(M,K) * B[b](K,N) ------
__global__ void __launch_bounds__(256) tf32_gemm(const float* __restrict__ A,
                                                 const float* __restrict__ Bg,
                                                 float* __restrict__ Cg,
                                                 int M, int N, int K)
{
    __shared__ float As[32][136];   // [k][m]
    __shared__ float Bs[32][136];   // [k][n]

    const int tid  = threadIdx.x;
    const int wid  = tid >> 5;
    const int lane = tid & 31;
    const int gid  = lane >> 2;
    const int tid4 = lane & 3;
    const int wm   = (wid & 1) * 64;
    const int wn   = (wid >> 1) * 32;

    const int mBase = blockIdx.x * 128, nBase = blockIdx.y * 128;
    const float* Bp = Bg + (size_t)blockIdx.z * K * N;
    float*       Cp = Cg + (size_t)blockIdx.z * M * N;

    float d[4][4][4];
#pragma unroll
    for (int mi = 0; mi < 4; ++mi)
#pragma unroll
        for (int ni = 0; ni < 4; ++ni)
#pragma unroll
            for (int r = 0; r < 4; ++r) d[mi][ni][r] = 0.f;

    for (int k0 = 0; k0 < K; k0 += 32) {
#pragma unroll
        for (int t = 0; t < 4; ++t) {
            int c  = tid + t * 256;
            int m  = c >> 3, k4 = c & 7;
            float4 v = *(const float4*)&A[(size_t)(mBase + m) * K + k0 + (k4 << 2)];
            As[k4 * 4 + 0][m] = f2tf(v.x);
            As[k4 * 4 + 1][m] = f2tf(v.y);
            As[k4 * 4 + 2][m] = f2tf(v.z);
            As[k4 * 4 + 3][m] = f2tf(v.w);
        }
#pragma unroll
        for (int t = 0; t < 4; ++t) {
            int c = tid + t * 256;
            int k = c >> 5, n4 = c & 31;
            float4 v = *(const float4*)&Bp[(size_t)(k0 + k) * N + nBase + (n4 << 2)];
            Bs[k][(n4 << 2) + 0] = f2tf(v.x);
            Bs[k][(n4 << 2) + 1] = f2tf(v.y);
            Bs[k][(n4 << 2) + 2] = f2tf(v.z);
            Bs[k][(n4 << 2) + 3] = f2tf(v.w);
        }
        __syncthreads();

#pragma unroll
        for (int kk = 0; kk < 32; kk += 8) {
            uint32_t af[4][4], bf[4][2];
#pragma unroll
            for (int mi = 0; mi < 4; ++mi) {
                int mr = wm + mi * 16 + gid;
                af[mi][0] = __float_as_uint(As[kk + tid4][mr]);
                af[mi][1] = __float_as_uint(As[kk + tid4][mr + 8]);
                af[mi][2] = __float_as_uint(As[kk + tid4 + 4][mr]);
                af[mi][3] = __float_as_uint(As[kk + tid4 + 4][mr + 8]);
            }
#pragma unroll
            for (int ni = 0; ni < 4; ++ni) {
                int nc = wn + ni * 8 + gid;
                bf[ni][0] = __float_as_uint(Bs[kk + tid4][nc]);
                bf[ni][1] = __float_as_uint(Bs[kk + tid4 + 4][nc]);
            }
#pragma unroll
            for (int mi = 0; mi < 4; ++mi)
#pragma unroll
                for (int ni = 0; ni < 4; ++ni)
                    mma_tf32_16x8x8(d[mi][ni], af[mi], bf[ni]);
        }
        __syncthreads();
    }

#pragma unroll
    for (int mi = 0; mi < 4; ++mi) {
        int row = mBase + wm + mi * 16 + gid;
#pragma unroll
        for (int ni = 0; ni < 4; ++ni) {
            int col = nBase + wn + ni * 8 + 2 * tid4;
            *(float2*)&Cp[(size_t)row * N + col] =
                make_float2(d[mi][ni][0], d[mi][ni][1]);
            *(float2*)&Cp[(size_t)(row + 8) * N + col] =
                make_float2(d[mi][ni][2], d[mi][ni][3]);
        }
    }
}

// ---------------- BN stats ----------------
__global__ void bn_stats(const float* __restrict__ y,
                         const float* __restrict__ gamma,
                         const float* __restrict__ beta,
                         float* __restrict__ scl, float* __restrict__ shf, int C)
{
    int c = blockIdx.x, tid = threadIdx.x;
    float s = 0.f, s2 = 0.f;
    for (int i = tid; i < NB * NPix; i += 256) {
        int b = i >> 10, n = i & 1023;
        float v = y[((size_t)b * C + c) * NPix + n];
        s += v; s2 += v * v;
    }
    __shared__ float rs[256], rs2[256];
    rs[tid] = s; rs2[tid] = s2;
    __syncthreads();
    for (int off = 128; off > 0; off >>= 1) {
        if (tid < off) { rs[tid] += rs[tid + off]; rs2[tid] += rs2[tid + off]; }
        __syncthreads();
    }
    if (tid == 0) {
        const float invN = 1.f / (NB * NPix);
        float mean = rs[0] * invN;
        float var  = rs2[0] * invN - mean * mean;
        float sc   = gamma[c] * rsqrtf(var + 1e-5f);
        scl[c] = sc;
        shf[c] = beta[c] - mean * sc;
    }
}

// ---------------- fused flash attention (tf32 mma) + gelu ----------------
// grid(8 qtiles, 64 bh), 256 threads. Per CTA: 128 queries, loop 16 key-tiles of 64.
// smem (floats): Ks[32][72] @0 (2304), Vs[64][136] @2304 (8704), Ps[128][68] @11008 (8704)
// Qs aliases Ps (start), Os[128][132] aliases base (end). Total 19712 f = 78848 B.
#define FL_SMEM 78848

__global__ void __launch_bounds__(256) flash_attn(const float* __restrict__ yqkv,
                                                  const float* __restrict__ scl,
                                                  const float* __restrict__ shf,
                                                  float* __restrict__ obuf)
{
    extern __shared__ float sm[];
    float* Ks = sm;
    float* Vs = sm + 2304;
    float* Ps = sm + 11008;
    float* Qs = Ps;
    float* Os = sm;

    const int bh = blockIdx.y, b = bh >> 3, h = bh & 7;
    const int qBase = blockIdx.x * 128;
    const int tid = threadIdx.x, wid = tid >> 5, lane = tid & 31;
    const int gid = lane >> 2, tid4 = lane & 3;
    const float* base = yqkv + (size_t)b * C_QKV * NPix;

    // Q tile [32 d][128 q], BN + 1/sqrt(dk) folded, tf32-rounded
    for (int i = tid; i < 32 * 128; i += 256) {
        int d = i >> 7, q = i & 127;
        int ch = h * 192 + d;
        Qs[d * 136 + q] =
            f2tf((base[(size_t)ch * NPix + qBase + q] * scl[ch] + shf[ch]) * 0.17677669529663687f);
    }
    __syncthreads();

    // preload Q fragments (warp owns q rows [16*wid, 16*wid+16))
    uint32_t qf[4][4];
    const int mr = wid * 16 + gid;
#pragma unroll
    for (int ks = 0; ks < 4; ++ks) {
        qf[ks][0] = __float_as_uint(Qs[(ks * 8 + tid4) * 136 + mr]);
        qf[ks][1] = __float_as_uint(Qs[(ks * 8 + tid4) * 136 + mr + 8]);
        qf[ks][2] = __float_as_uint(Qs[(ks * 8 + tid4 + 4) * 136 + mr]);
        qf[ks][3] = __float_as_uint(Qs[(ks * 8 + tid4 + 4) * 136 + mr + 8]);
    }
    __syncthreads();

    float o[16][4];
#pragma unroll
    for (int nt = 0; nt < 16; ++nt)
#pragma unroll
        for (int r = 0; r < 4; ++r) o[nt][r] = 0.f;
    float m0 = -1e30f, m1 = -1e30f, l0 = 0.f, l1 = 0.f;

    for (int k0 = 0; k0 < NPix; k0 += 64) {
        // K tile [32 d][64 keys], V tile [64 keys][128 dv] (transposed), BN applied
        for (int i = tid; i < 32 * 64; i += 256) {
            int d = i >> 6, kx = i & 63;
            int ch = h * 192 + DK + d;
            Ks[d * 72 + kx] = f2tf(base[(size_t)ch * NPix + k0 + kx] * scl[ch] + shf[ch]);
        }
        for (int i = tid; i < 128 * 64; i += 256) {
            int dv = i >> 6, kx = i & 63;
            int ch = h * 192 + 2 * DK + dv;
            Vs[kx * 136 + dv] = f2tf(base[(size_t)ch * NPix + k0 + kx] * scl[ch] + shf[ch]);
        }
        __syncthreads();

        // S = Q^T K  (16 q rows x 64 keys per warp)
        float s[8][4];
#pragma unroll
        for (int ni = 0; ni < 8; ++ni)
#pragma unroll
            for (int r = 0; r < 4; ++r) s[ni][r] = 0.f;
#pragma unroll
        for (int ks = 0; ks < 4; ++ks) {
#pragma unroll
            for (int ni = 0; ni < 8; ++ni) {
                uint32_t bf[2];
                bf[0] = __float_as_uint(Ks[(ks * 8 + tid4) * 72 + ni * 8 + gid]);
                bf[1] = __float_as_uint(Ks[(ks * 8 + tid4 + 4) * 72 + ni * 8 + gid]);
                mma_tf32_16x8x8(s[ni], qf[ks], bf);
            }
        }

        // online softmax (row0 = q row gid, row1 = q row gid+8)
        float t0 = -1e30f, t1 = -1e30f;
#pragma unroll
        for (int ni = 0; ni < 8; ++ni) {
            t0 = fmaxf(t0, fmaxf(s[ni][0], s[ni][1]));
            t1 = fmaxf(t1, fmaxf(s[ni][2], s[ni][3]));
        }
        t0 = fmaxf(t0, __shfl_xor_sync(0xffffffffu, t0, 1));
        t0 = fmaxf(t0, __shfl_xor_sync(0xffffffffu, t0, 2));
        t1 = fmaxf(t1, __shfl_xor_sync(0xffffffffu, t1, 1));
        t1 = fmaxf(t1, __shfl_xor_sync(0xffffffffu, t1, 2));
        float mn0 = fmaxf(m0, t0), mn1 = fmaxf(m1, t1);
        float a0 = __expf(m0 - mn0), a1 = __expf(m1 - mn1);
        m0 = mn0; m1 = mn1;

        float ps0 = 0.f, ps1 = 0.f;
#pragma unroll
        for (int ni = 0; ni < 8; ++ni) {
            s[ni][0] = f2tf(__expf(s[ni][0] - mn0));
            s[ni][1] = f2tf(__expf(s[ni][1] - mn0));
            s[ni][2] = f2tf(__expf(s[ni][2] - mn1));
            s[ni][3] = f2tf(__expf(s[ni][3] - mn1));
            ps0 += s[ni][0] + s[ni][1];
            ps1 += s[ni][2] + s[ni][3];
        }
        ps0 += __shfl_xor_sync(0xffffffffu, ps0, 1);
        ps0 += __shfl_xor_sync(0xffffffffu, ps0, 2);
        ps1 += __shfl_xor_sync(0xffffffffu, ps1, 1);
        ps1 += __shfl_xor_sync(0xffffffffu, ps1, 2);
        l0 = l0 * a0 + ps0;
        l1 = l1 * a1 + ps1;

#pragma unroll
        for (int nt = 0; nt < 16; ++nt) {
            o[nt][0] *= a0; o[nt][1] *= a0;
            o[nt][2] *= a1; o[nt][3] *= a1;
        }

        // P -> warp-private smem rows
#pragma unroll
        for (int ni = 0; ni < 8; ++ni) {
            Ps[(wid * 16 + gid) * 68 + ni * 8 + 2 * tid4]     = s[ni][0];
            Ps[(wid * 16 + gid) * 68 + ni * 8 + 2 * tid4 + 1] = s[ni][1];
            Ps[(wid * 16 + gid + 8) * 68 + ni * 8 + 2 * tid4]     = s[ni][2];
            Ps[(wid * 16 + gid + 8) * 68 + ni * 8 + 2 * tid4 + 1] = s[ni][3];
        }
        __syncwarp();

        // O += P * V
#pragma unroll
        for (int kk = 0; kk < 8; ++kk) {
            uint32_t pf[4];
            pf[0] = __float_as_uint(Ps[(wid * 16 + gid) * 68 + kk * 8 + tid4]);
            pf[1] = __float_as_uint(Ps[(wid * 16 + gid + 8) * 68 + kk * 8 + tid4]);
            pf[2] = __float_as_uint(Ps[(wid * 16 + gid) * 68 + kk * 8 + tid4 + 4]);
            pf[3] = __float_as_uint(Ps[(wid * 16 + gid + 8) * 68 + kk * 8 + tid4 + 4]);
#pragma unroll
            for (int nt = 0; nt < 16; ++nt) {
                uint32_t vf[2];
                vf[0] = __float_as_uint(Vs[(kk * 8 + tid4) * 136 + nt * 8 + gid]);
                vf[1] = __float_as_uint(Vs[(kk * 8 + tid4 + 4) * 136 + nt * 8 + gid]);
                mma_tf32_16x8x8(o[nt], pf, vf);
            }
        }
        __syncthreads();
    }

    // normalize + transpose through smem, then coalesced gelu write
    float inv0 = 1.f / l0, inv1 = 1.f / l1;
    __syncthreads();
#pragma unroll
    for (int nt = 0; nt < 16; ++nt) {
        int dv = nt * 8 + 2 * tid4;
        int q  = wid * 16 + gid;
        Os[(size_t)dv * 132 + q]           = o[nt][0] * inv0;
        Os[(size_t)(dv + 1) * 132 + q]     = o[nt][1] * inv0;
        Os[(size_t)dv * 132 + q + 8]       = o[nt][2] * inv1;
        Os[(size_t)(dv + 1) * 132 + q + 8] = o[nt][3] * inv1;
    }
    __syncthreads();
    for (int i = tid; i < 128 * 128; i += 256) {
        int dv = i >> 7, q = i & 127;
        int ch = b * 1024 + h * 128 + dv;
        obuf[(size_t)ch * NPix + qBase + q] = gelu_exact(Os[dv * 132 + q]);
    }
}

// ---------------- elementwise ----------------
__global__ void resadd_bn(const float* __restrict__ x, const float* __restrict__ y,
                          const float* __restrict__ scl, const float* __restrict__ shf,
                          float* __restrict__ o, int C, int total)
{
    int i = blockIdx.x * 256 + threadIdx.x;
    if (i >= total) return;
    int ch = (i >> 10) % C;
    o[i] = x[i] + y[i] * scl[ch] + shf[ch];
}
__global__ void bn_gelu_inplace(float* __restrict__ y,
                                const float* __restrict__ scl,
                                const float* __restrict__ shf, int C, int total)
{
    int i = blockIdx.x * 256 + threadIdx.x;
    if (i >= total) return;
    int ch = (i >> 10) % C;
    y[i] = gelu_exact(y[i] * scl[ch] + shf[ch]);
}

// ---------------- host ----------------
extern "C" void kernel_launch(void* const* d_in, const int* in_sizes, int n_in,
                              void* d_out, int out_size)
{
    const float* x       = (const float*)d_in[0];
    const float* w_qkv   = (const float*)d_in[1];
    const float* gq      = (const float*)d_in[2];
    const float* bq      = (const float*)d_in[3];
    const float* w_merge = (const float*)d_in[4];
    const float* gm      = (const float*)d_in[5];
    const float* bm      = (const float*)d_in[6];
    const float* w_fc1   = (const float*)d_in[7];
    const float* g1      = (const float*)d_in[8];
    const float* b1      = (const float*)d_in[9];
    const float* w_fc2   = (const float*)d_in[10];
    const float* g2      = (const float*)d_in[11];
    const float* b2      = (const float*)d_in[12];
    float* out = (float*)d_out;

    float *yqkv, *obuf, *y2, *xr, *h1, *y3;
    float *scq, *shq, *scm, *shm, *sc1, *sh1, *sc2, *sh2;
    cudaGetSymbolAddress((void**)&yqkv, g_yqkv);
    cudaGetSymbolAddress((void**)&obuf, g_obuf);
    cudaGetSymbolAddress((void**)&y2,   g_y2);
    cudaGetSymbolAddress((void**)&xr,   g_xr);
    cudaGetSymbolAddress((void**)&h1,   g_h1);
    cudaGetSymbolAddress((void**)&y3,   g_y3);
    cudaGetSymbolAddress((void**)&scq, g_sc_qkv);
    cudaGetSymbolAddress((void**)&shq, g_sh_qkv);
    cudaGetSymbolAddress((void**)&scm, g_sc_mg);
    cudaGetSymbolAddress((void**)&shm, g_sh_mg);
    cudaGetSymbolAddress((void**)&sc1, g_sc_f1);
    cudaGetSymbolAddress((void**)&sh1, g_sh_f1);
    cudaGetSymbolAddress((void**)&sc2, g_sc_f2);
    cudaGetSymbolAddress((void**)&sh2, g_sh_f2);

    cudaFuncSetAttribute(flash_attn, cudaFuncAttributeMaxDynamicSharedMemorySize, FL_SMEM);

    tf32_gemm<<<dim3(C_QKV/128, NPix/128, NB), 256>>>(w_qkv, x, yqkv, C_QKV, NPix, C_IN);
    bn_stats<<<C_QKV, 256>>>(yqkv, gq, bq, scq, shq, C_QKV);
    flash_attn<<<dim3(8, 64), 256, FL_SMEM>>>(yqkv, scq, shq, obuf);
    tf32_gemm<<<dim3(C_MG/128, NPix/128, NB), 256>>>(w_merge, obuf, y2, C_MG, NPix, 1024);
    bn_stats<<<C_MG, 256>>>(y2, gm, bm, scm, shm, C_MG);
    {
        int total = NB * C_IN * NPix;
        resadd_bn<<<(total + 255) / 256, 256>>>(x, y2, scm, shm, xr, C_MG, total);
    }
    tf32_gemm<<<dim3(C_F1/128, NPix/128, NB), 256>>>(w_fc1, xr, h1, C_F1, NPix, C_IN);
    bn_stats<<<C_F1, 256>>>(h1, g1, b1, sc1, sh1, C_F1);
    {
        int total = NB * C_F1 * NPix;
        bn_gelu_inplace<<<(total + 255) / 256, 256>>>(h1, sc1, sh1, C_F1, total);
    }
    tf32_gemm<<<dim3(C_F2/128, NPix/128, NB), 256>>>(w_fc2, h1, y3, C_F2, NPix, C_F1);
    bn_stats<<<C_F2, 256>>>(y3, g2, b2, sc2, sh2, C_F2);
    {
        int total = NB * C_F2 * NPix;
        resadd_bn<<<(total + 255) / 256, 256>>>(xr, y3, sc2, sh2, out, C_F2, total);
    }
}

// round 6
// speedup vs baseline: 2.4690x; 1.2386x over previous
#include <cuda_runtime.h>
#include <cstdint>
#include <math.h>

#define NB    8
#define NPix  1024
#define C_IN  384
#define C_QKV 1536
#define C_MG  384
#define C_F1  768
#define C_F2  384
#define DK    32
#define DV    128

__device__ float g_yqkv[NB * C_QKV * NPix];
__device__ float g_obuf[NB * 1024 * NPix];
__device__ float g_y2  [NB * C_MG * NPix];
__device__ float g_xr  [NB * C_IN * NPix];
__device__ float g_h1  [NB * C_F1 * NPix];
__device__ float g_y3  [NB * C_F2 * NPix];
__device__ float g_sc_qkv[C_QKV], g_sh_qkv[C_QKV];
__device__ float g_sc_mg [C_MG ], g_sh_mg [C_MG ];
__device__ float g_sc_f1 [C_F1 ], g_sh_f1 [C_F1 ];
__device__ float g_sc_f2 [C_F2 ], g_sh_f2 [C_F2 ];

__device__ __forceinline__ float gelu_exact(float v) { return v * normcdff(v); }

__device__ __forceinline__ float f2tf(float f) {
    uint32_t r;
    asm("cvt.rna.tf32.f32 %0, %1;" : "=r"(r) : "f"(f));
    return __uint_as_float(r);
}
__device__ __forceinline__ uint32_t f2tfu(float f) {
    uint32_t r;
    asm("cvt.rna.tf32.f32 %0, %1;" : "=r"(r) : "f"(f));
    return r;
}

__device__ __forceinline__ void mma_tf32_16x8x8(float d[4],
                                                const uint32_t a[4],
                                                const uint32_t b[2])
{
    asm volatile(
        "mma.sync.aligned.m16n8k8.row.col.f32.tf32.tf32.f32 "
        "{%0,%1,%2,%3}, {%4,%5,%6,%7}, {%8,%9}, {%0,%1,%2,%3};"
        : "+f"(d[0]), "+f"(d[1]), "+f"(d[2]), "+f"(d[3])
        : "r"(a[0]), "r"(a[1]), "r"(a[2]), "r"(a[3]), "r"(b[0]), "r"(b[1]));
}

__device__ __forceinline__ void cp16(uint32_t saddr, const void* gptr) {
    asm volatile("cp.async.cg.shared.global [%0], [%1], 16;" :: "r"(saddr), "l"(gptr));
}
#define CP_COMMIT asm volatile("cp.async.commit_group;" ::: "memory")
#define CP_WAIT1  asm volatile("cp.async.wait_group 1;" ::: "memory")

// ---------------- tf32 mma.sync GEMM, 3-stage cp.async pipeline -----------
// C[b](M,N) = A(M,K) * B[b](K,N). 128x128 CTA tile, BK=32.
// As[m][36] untransposed (frag addr mod32 = 4*gid+tid4, conflict-free)
// Bs[k][136] direct      (frag addr mod32 = 8*tid4+gid, conflict-free)
#define STG_F 8960              // floats per stage (128*36 + 32*136)
#define STG_B 35840             // bytes per stage
#define GEMM_SMEM (3 * STG_B)

__global__ void __launch_bounds__(256) tf32_gemm(const float* __restrict__ A,
                                                 const float* __restrict__ Bg,
                                                 float* __restrict__ Cg,
                                                 int M, int N, int K)
{
    extern __shared__ float sm[];
    const uint32_t sbase = (uint32_t)__cvta_generic_to_shared(sm);

    const int tid  = threadIdx.x;
    const int wid  = tid >> 5;
    const int lane = tid & 31;
    const int gid  = lane >> 2;
    const int tid4 = lane & 3;
    const int wm   = (wid & 1) * 64;
    const int wn   = (wid >> 1) * 32;

    const int mBase = blockIdx.x * 128, nBase = blockIdx.y * 128;
    const float* Bp = Bg + (size_t)blockIdx.z * K * N;
    float*       Cp = Cg + (size_t)blockIdx.z * M * N;

    const int am = tid >> 3, aj = tid & 7;       // A: 4 chunk-iters, m=am+32*t... no:
    // A tile: 1024 chunks (128 rows x 8). chunk c = tid + t*256: m=c>>3, j=c&7
    // B tile: 1024 chunks (32 rows x 32).  chunk c = tid + t*256: k=c>>5, j=c&31

    const int nst = K >> 5;

    // ---- copy issue helper (as a lambda-style macro) ----
#define ISSUE_STAGE(s_) do {                                                   \
        int _s = (s_);                                                         \
        uint32_t sa = sbase + (_s % 3) * STG_B;                                \
        uint32_t sb2 = sa + 18432;                                             \
        int _k0 = _s << 5;                                                     \
        _Pragma("unroll")                                                      \
        for (int t = 0; t < 4; ++t) {                                          \
            int c = tid + t * 256;                                             \
            int m = c >> 3, j = c & 7;                                         \
            cp16(sa + m * 144 + j * 16,                                        \
                 &A[(size_t)(mBase + m) * K + _k0 + (j << 2)]);                \
        }                                                                      \
        _Pragma("unroll")                                                      \
        for (int t = 0; t < 4; ++t) {                                          \
            int c = tid + t * 256;                                             \
            int k = c >> 5, j = c & 31;                                        \
            cp16(sb2 + k * 544 + j * 16,                                       \
                 &Bp[(size_t)(_k0 + k) * N + nBase + (j << 2)]);               \
        }                                                                      \
    } while (0)

    float d[4][4][4];
#pragma unroll
    for (int mi = 0; mi < 4; ++mi)
#pragma unroll
        for (int ni = 0; ni < 4; ++ni)
#pragma unroll
            for (int r = 0; r < 4; ++r) d[mi][ni][r] = 0.f;

    // prologue: stages 0 and 1
    ISSUE_STAGE(0); CP_COMMIT;
    ISSUE_STAGE(1); CP_COMMIT;

    for (int s = 0; s < nst; ++s) {
        CP_WAIT1;                 // stage s data resident
        __syncthreads();          // all warps done with stage s-1 compute
        if (s + 2 < nst) ISSUE_STAGE(s + 2);
        CP_COMMIT;

        const float* As = sm + (s % 3) * STG_F;          // [m][36]
        const float* Bs = As + 4608;                     // [k][136]

#pragma unroll
        for (int kk = 0; kk < 32; kk += 8) {
            uint32_t af[4][4], bf[4][2];
#pragma unroll
            for (int mi = 0; mi < 4; ++mi) {
                int mr = wm + mi * 16 + gid;
                af[mi][0] = f2tfu(As[mr * 36 + kk + tid4]);
                af[mi][1] = f2tfu(As[(mr + 8) * 36 + kk + tid4]);
                af[mi][2] = f2tfu(As[mr * 36 + kk + tid4 + 4]);
                af[mi][3] = f2tfu(As[(mr + 8) * 36 + kk + tid4 + 4]);
            }
#pragma unroll
            for (int ni = 0; ni < 4; ++ni) {
                int nc = wn + ni * 8 + gid;
                bf[ni][0] = f2tfu(Bs[(kk + tid4) * 136 + nc]);
                bf[ni][1] = f2tfu(Bs[(kk + tid4 + 4) * 136 + nc]);
            }
#pragma unroll
            for (int mi = 0; mi < 4; ++mi)
#pragma unroll
                for (int ni = 0; ni < 4; ++ni)
                    mma_tf32_16x8x8(d[mi][ni], af[mi], bf[ni]);
        }
    }
#undef ISSUE_STAGE

#pragma unroll
    for (int mi = 0; mi < 4; ++mi) {
        int row = mBase + wm + mi * 16 + gid;
#pragma unroll
        for (int ni = 0; ni < 4; ++ni) {
            int col = nBase + wn + ni * 8 + 2 * tid4;
            *(float2*)&Cp[(size_t)row * N + col] =
                make_float2(d[mi][ni][0], d[mi][ni][1]);
            *(float2*)&Cp[(size_t)(row + 8) * N + col] =
                make_float2(d[mi][ni][2], d[mi][ni][3]);
        }
    }
}

// ---------------- BN stats ----------------
__global__ void bn_stats(const float* __restrict__ y,
                         const float* __restrict__ gamma,
                         const float* __restrict__ beta,
                         float* __restrict__ scl, float* __restrict__ shf, int C)
{
    int c = blockIdx.x, tid = threadIdx.x;
    float s = 0.f, s2 = 0.f;
    for (int i = tid; i < NB * NPix; i += 256) {
        int b = i >> 10, n = i & 1023;
        float v = y[((size_t)b * C + c) * NPix + n];
        s += v; s2 += v * v;
    }
    __shared__ float rs[256], rs2[256];
    rs[tid] = s; rs2[tid] = s2;
    __syncthreads();
    for (int off = 128; off > 0; off >>= 1) {
        if (tid < off) { rs[tid] += rs[tid + off]; rs2[tid] += rs2[tid + off]; }
        __syncthreads();
    }
    if (tid == 0) {
        const float invN = 1.f / (NB * NPix);
        float mean = rs[0] * invN;
        float var  = rs2[0] * invN - mean * mean;
        float sc   = gamma[c] * rsqrtf(var + 1e-5f);
        scl[c] = sc;
        shf[c] = beta[c] - mean * sc;
    }
}

// ---------------- fused flash attention (tf32 mma) + gelu ----------------
#define FL_SMEM 78848

__global__ void __launch_bounds__(256) flash_attn(const float* __restrict__ yqkv,
                                                  const float* __restrict__ scl,
                                                  const float* __restrict__ shf,
                                                  float* __restrict__ obuf)
{
    extern __shared__ float fsm[];
    float* Ks = fsm;
    float* Vs = fsm + 2304;
    float* Ps = fsm + 11008;
    float* Qs = Ps;
    float* Os = fsm;

    const int bh = blockIdx.y, b = bh >> 3, h = bh & 7;
    const int qBase = blockIdx.x * 128;
    const int tid = threadIdx.x, wid = tid >> 5, lane = tid & 31;
    const int gid = lane >> 2, tid4 = lane & 3;
    const float* base = yqkv + (size_t)b * C_QKV * NPix;

    for (int i = tid; i < 32 * 128; i += 256) {
        int d = i >> 7, q = i & 127;
        int ch = h * 192 + d;
        Qs[d * 136 + q] =
            f2tf((base[(size_t)ch * NPix + qBase + q] * scl[ch] + shf[ch]) * 0.17677669529663687f);
    }
    __syncthreads();

    uint32_t qf[4][4];
    const int mr = wid * 16 + gid;
#pragma unroll
    for (int ks = 0; ks < 4; ++ks) {
        qf[ks][0] = __float_as_uint(Qs[(ks * 8 + tid4) * 136 + mr]);
        qf[ks][1] = __float_as_uint(Qs[(ks * 8 + tid4) * 136 + mr + 8]);
        qf[ks][2] = __float_as_uint(Qs[(ks * 8 + tid4 + 4) * 136 + mr]);
        qf[ks][3] = __float_as_uint(Qs[(ks * 8 + tid4 + 4) * 136 + mr + 8]);
    }
    __syncthreads();

    float o[16][4];
#pragma unroll
    for (int nt = 0; nt < 16; ++nt)
#pragma unroll
        for (int r = 0; r < 4; ++r) o[nt][r] = 0.f;
    float m0 = -1e30f, m1 = -1e30f, l0 = 0.f, l1 = 0.f;

    for (int k0 = 0; k0 < NPix; k0 += 64) {
        for (int i = tid; i < 32 * 64; i += 256) {
            int d = i >> 6, kx = i & 63;
            int ch = h * 192 + DK + d;
            Ks[d * 72 + kx] = f2tf(base[(size_t)ch * NPix + k0 + kx] * scl[ch] + shf[ch]);
        }
        for (int i = tid; i < 128 * 64; i += 256) {
            int dv = i >> 6, kx = i & 63;
            int ch = h * 192 + 2 * DK + dv;
            Vs[kx * 136 + dv] = f2tf(base[(size_t)ch * NPix + k0 + kx] * scl[ch] + shf[ch]);
        }
        __syncthreads();

        float s[8][4];
#pragma unroll
        for (int ni = 0; ni < 8; ++ni)
#pragma unroll
            for (int r = 0; r < 4; ++r) s[ni][r] = 0.f;
#pragma unroll
        for (int ks = 0; ks < 4; ++ks) {
#pragma unroll
            for (int ni = 0; ni < 8; ++ni) {
                uint32_t bf[2];
                bf[0] = __float_as_uint(Ks[(ks * 8 + tid4) * 72 + ni * 8 + gid]);
                bf[1] = __float_as_uint(Ks[(ks * 8 + tid4 + 4) * 72 + ni * 8 + gid]);
                mma_tf32_16x8x8(s[ni], qf[ks], bf);
            }
        }

        float t0 = -1e30f, t1 = -1e30f;
#pragma unroll
        for (int ni = 0; ni < 8; ++ni) {
            t0 = fmaxf(t0, fmaxf(s[ni][0], s[ni][1]));
            t1 = fmaxf(t1, fmaxf(s[ni][2], s[ni][3]));
        }
        t0 = fmaxf(t0, __shfl_xor_sync(0xffffffffu, t0, 1));
        t0 = fmaxf(t0, __shfl_xor_sync(0xffffffffu, t0, 2));
        t1 = fmaxf(t1, __shfl_xor_sync(0xffffffffu, t1, 1));
        t1 = fmaxf(t1, __shfl_xor_sync(0xffffffffu, t1, 2));
        float mn0 = fmaxf(m0, t0), mn1 = fmaxf(m1, t1);
        float a0 = __expf(m0 - mn0), a1 = __expf(m1 - mn1);
        m0 = mn0; m1 = mn1;

        float ps0 = 0.f, ps1 = 0.f;
#pragma unroll
        for (int ni = 0; ni < 8; ++ni) {
            s[ni][0] = f2tf(__expf(s[ni][0] - mn0));
            s[ni][1] = f2tf(__expf(s[ni][1] - mn0));
            s[ni][2] = f2tf(__expf(s[ni][2] - mn1));
            s[ni][3] = f2tf(__expf(s[ni][3] - mn1));
            ps0 += s[ni][0] + s[ni][1];
            ps1 += s[ni][2] + s[ni][3];
        }
        ps0 += __shfl_xor_sync(0xffffffffu, ps0, 1);
        ps0 += __shfl_xor_sync(0xffffffffu, ps0, 2);
        ps1 += __shfl_xor_sync(0xffffffffu, ps1, 1);
        ps1 += __shfl_xor_sync(0xffffffffu, ps1, 2);
        l0 = l0 * a0 + ps0;
        l1 = l1 * a1 + ps1;

#pragma unroll
        for (int nt = 0; nt < 16; ++nt) {
            o[nt][0] *= a0; o[nt][1] *= a0;
            o[nt][2] *= a1; o[nt][3] *= a1;
        }

#pragma unroll
        for (int ni = 0; ni < 8; ++ni) {
            Ps[(wid * 16 + gid) * 68 + ni * 8 + 2 * tid4]     = s[ni][0];
            Ps[(wid * 16 + gid) * 68 + ni * 8 + 2 * tid4 + 1] = s[ni][1];
            Ps[(wid * 16 + gid + 8) * 68 + ni * 8 + 2 * tid4]     = s[ni][2];
            Ps[(wid * 16 + gid + 8) * 68 + ni * 8 + 2 * tid4 + 1] = s[ni][3];
        }
        __syncwarp();

#pragma unroll
        for (int kk = 0; kk < 8; ++kk) {
            uint32_t pf[4];
            pf[0] = __float_as_uint(Ps[(wid * 16 + gid) * 68 + kk * 8 + tid4]);
            pf[1] = __float_as_uint(Ps[(wid * 16 + gid + 8) * 68 + kk * 8 + tid4]);
            pf[2] = __float_as_uint(Ps[(wid * 16 + gid) * 68 + kk * 8 + tid4 + 4]);
            pf[3] = __float_as_uint(Ps[(wid * 16 + gid + 8) * 68 + kk * 8 + tid4 + 4]);
#pragma unroll
            for (int nt = 0; nt < 16; ++nt) {
                uint32_t vf[2];
                vf[0] = __float_as_uint(Vs[(kk * 8 + tid4) * 136 + nt * 8 + gid]);
                vf[1] = __float_as_uint(Vs[(kk * 8 + tid4 + 4) * 136 + nt * 8 + gid]);
                mma_tf32_16x8x8(o[nt], pf, vf);
            }
        }
        __syncthreads();
    }

    float inv0 = 1.f / l0, inv1 = 1.f / l1;
    __syncthreads();
#pragma unroll
    for (int nt = 0; nt < 16; ++nt) {
        int dv = nt * 8 + 2 * tid4;
        int q  = wid * 16 + gid;
        Os[(size_t)dv * 132 + q]           = o[nt][0] * inv0;
        Os[(size_t)(dv + 1) * 132 + q]     = o[nt][1] * inv0;
        Os[(size_t)dv * 132 + q + 8]       = o[nt][2] * inv1;
        Os[(size_t)(dv + 1) * 132 + q + 8] = o[nt][3] * inv1;
    }
    __syncthreads();
    for (int i = tid; i < 128 * 128; i += 256) {
        int dv = i >> 7, q = i & 127;
        int ch = b * 1024 + h * 128 + dv;
        obuf[(size_t)ch * NPix + qBase + q] = gelu_exact(Os[dv * 132 + q]);
    }
}

// ---------------- elementwise ----------------
__global__ void resadd_bn(const float* __restrict__ x, const float* __restrict__ y,
                          const float* __restrict__ scl, const float* __restrict__ shf,
                          float* __restrict__ o, int C, int total)
{
    int i = blockIdx.x * 256 + threadIdx.x;
    if (i >= total) return;
    int ch = (i >> 10) % C;
    o[i] = x[i] + y[i] * scl[ch] + shf[ch];
}
__global__ void bn_gelu_inplace(float* __restrict__ y,
                                const float* __restrict__ scl,
                                const float* __restrict__ shf, int C, int total)
{
    int i = blockIdx.x * 256 + threadIdx.x;
    if (i >= total) return;
    int ch = (i >> 10) % C;
    y[i] = gelu_exact(y[i] * scl[ch] + shf[ch]);
}

// ---------------- host ----------------
extern "C" void kernel_launch(void* const* d_in, const int* in_sizes, int n_in,
                              void* d_out, int out_size)
{
    const float* x       = (const float*)d_in[0];
    const float* w_qkv   = (const float*)d_in[1];
    const float* gq      = (const float*)d_in[2];
    const float* bq      = (const float*)d_in[3];
    const float* w_merge = (const float*)d_in[4];
    const float* gm      = (const float*)d_in[5];
    const float* bm      = (const float*)d_in[6];
    const float* w_fc1   = (const float*)d_in[7];
    const float* g1      = (const float*)d_in[8];
    const float* b1      = (const float*)d_in[9];
    const float* w_fc2   = (const float*)d_in[10];
    const float* g2      = (const float*)d_in[11];
    const float* b2      = (const float*)d_in[12];
    float* out = (float*)d_out;

    float *yqkv, *obuf, *y2, *xr, *h1, *y3;
    float *scq, *shq, *scm, *shm, *sc1, *sh1, *sc2, *sh2;
    cudaGetSymbolAddress((void**)&yqkv, g_yqkv);
    cudaGetSymbolAddress((void**)&obuf, g_obuf);
    cudaGetSymbolAddress((void**)&y2,   g_y2);
    cudaGetSymbolAddress((void**)&xr,   g_xr);
    cudaGetSymbolAddress((void**)&h1,   g_h1);
    cudaGetSymbolAddress((void**)&y3,   g_y3);
    cudaGetSymbolAddress((void**)&scq, g_sc_qkv);
    cudaGetSymbolAddress((void**)&shq, g_sh_qkv);
    cudaGetSymbolAddress((void**)&scm, g_sc_mg);
    cudaGetSymbolAddress((void**)&shm, g_sh_mg);
    cudaGetSymbolAddress((void**)&sc1, g_sc_f1);
    cudaGetSymbolAddress((void**)&sh1, g_sh_f1);
    cudaGetSymbolAddress((void**)&sc2, g_sc_f2);
    cudaGetSymbolAddress((void**)&sh2, g_sh_f2);

    cudaFuncSetAttribute(tf32_gemm, cudaFuncAttributeMaxDynamicSharedMemorySize, GEMM_SMEM);
    cudaFuncSetAttribute(flash_attn, cudaFuncAttributeMaxDynamicSharedMemorySize, FL_SMEM);

    tf32_gemm<<<dim3(C_QKV/128, NPix/128, NB), 256, GEMM_SMEM>>>(w_qkv, x, yqkv, C_QKV, NPix, C_IN);
    bn_stats<<<C_QKV, 256>>>(yqkv, gq, bq, scq, shq, C_QKV);
    flash_attn<<<dim3(8, 64), 256, FL_SMEM>>>(yqkv, scq, shq, obuf);
    tf32_gemm<<<dim3(C_MG/128, NPix/128, NB), 256, GEMM_SMEM>>>(w_merge, obuf, y2, C_MG, NPix, 1024);
    bn_stats<<<C_MG, 256>>>(y2, gm, bm, scm, shm, C_MG);
    {
        int total = NB * C_IN * NPix;
        resadd_bn<<<(total + 255) / 256, 256>>>(x, y2, scm, shm, xr, C_MG, total);
    }
    tf32_gemm<<<dim3(C_F1/128, NPix/128, NB), 256, GEMM_SMEM>>>(w_fc1, xr, h1, C_F1, NPix, C_IN);
    bn_stats<<<C_F1, 256>>>(h1, g1, b1, sc1, sh1, C_F1);
    {
        int total = NB * C_F1 * NPix;
        bn_gelu_inplace<<<(total + 255) / 256, 256>>>(h1, sc1, sh1, C_F1, total);
    }
    tf32_gemm<<<dim3(C_F2/128, NPix/128, NB), 256, GEMM_SMEM>>>(w_fc2, h1, y3, C_F2, NPix, C_F1);
    bn_stats<<<C_F2, 256>>>(y3, g2, b2, sc2, sh2, C_F2);
    {
        int total = NB * C_F2 * NPix;
        resadd_bn<<<(total + 255) / 256, 256>>>(xr, y3, sc2, sh2, out, C_F2, total);
    }
}

// round 7
// speedup vs baseline: 2.5952x; 1.0511x over previous
#include <cuda_runtime.h>
#include <cstdint>
#include <math.h>

#define NB    8
#define NPix  1024
#define C_IN  384
#define C_QKV 1536
#define C_MG  384
#define C_F1  768
#define C_F2  384
#define DK    32
#define DV    128

__device__ float g_yqkv[NB * C_QKV * NPix];
__device__ float g_obuf[NB * 1024 * NPix];
__device__ float g_y2  [NB * C_MG * NPix];
__device__ float g_xr  [NB * C_IN * NPix];
__device__ float g_h1  [NB * C_F1 * NPix];
__device__ float g_y3  [NB * C_F2 * NPix];
__device__ float g_sc_qkv[C_QKV], g_sh_qkv[C_QKV];
__device__ float g_sc_mg [C_MG ], g_sh_mg [C_MG ];
__device__ float g_sc_f1 [C_F1 ], g_sh_f1 [C_F1 ];
__device__ float g_sc_f2 [C_F2 ], g_sh_f2 [C_F2 ];
// tf32-rounded weight scratch
__device__ float g_wq[C_QKV * C_IN];
__device__ float g_wm[C_MG * 1024];
__device__ float g_w1[C_F1 * C_IN];
__device__ float g_w2[C_F2 * C_F1];

__device__ __forceinline__ float gelu_exact(float v) { return v * normcdff(v); }

__device__ __forceinline__ float f2tf(float f) {
    uint32_t r;
    asm("cvt.rna.tf32.f32 %0, %1;" : "=r"(r) : "f"(f));
    return __uint_as_float(r);
}

__device__ __forceinline__ void mma_tf32_16x8x8(float d[4],
                                                const uint32_t a[4],
                                                const uint32_t b[2])
{
    asm volatile(
        "mma.sync.aligned.m16n8k8.row.col.f32.tf32.tf32.f32 "
        "{%0,%1,%2,%3}, {%4,%5,%6,%7}, {%8,%9}, {%0,%1,%2,%3};"
        : "+f"(d[0]), "+f"(d[1]), "+f"(d[2]), "+f"(d[3])
        : "r"(a[0]), "r"(a[1]), "r"(a[2]), "r"(a[3]), "r"(b[0]), "r"(b[1]));
}

__device__ __forceinline__ void cp16(uint32_t saddr, const void* gptr) {
    asm volatile("cp.async.cg.shared.global [%0], [%1], 16;" :: "r"(saddr), "l"(gptr));
}
#define CP_COMMIT asm volatile("cp.async.commit_group;" ::: "memory")
#define CP_WAIT1  asm volatile("cp.async.wait_group 1;" ::: "memory")

// ---------------- weight pre-rounding ----------------
__global__ void round_w(const float* __restrict__ w, float* __restrict__ o, int n4)
{
    int i = blockIdx.x * 256 + threadIdx.x;
    if (i >= n4) return;
    float4 v = ((const float4*)w)[i];
    v.x = f2tf(v.x); v.y = f2tf(v.y); v.z = f2tf(v.z); v.w = f2tf(v.w);
    ((float4*)o)[i] = v;
}

// ---------------- tf32 mma.sync GEMM, 3-stage cp.async pipeline -----------
// A pre-rounded tf32; B truncated in-MMA. No cvts in the hot loop.
#define STG_F 8960
#define STG_B 35840
#define GEMM_SMEM (3 * STG_B)

__global__ void __launch_bounds__(256) tf32_gemm(const float* __restrict__ A,
                                                 const float* __restrict__ Bg,
                                                 float* __restrict__ Cg,
                                                 int M, int N, int K)
{
    extern __shared__ float sm[];
    const uint32_t sbase = (uint32_t)__cvta_generic_to_shared(sm);

    const int tid  = threadIdx.x;
    const int wid  = tid >> 5;
    const int lane = tid & 31;
    const int gid  = lane >> 2;
    const int tid4 = lane & 3;
    const int wm   = (wid & 1) * 64;
    const int wn   = (wid >> 1) * 32;

    const int mBase = blockIdx.x * 128, nBase = blockIdx.y * 128;
    const float* Bp = Bg + (size_t)blockIdx.z * K * N;
    float*       Cp = Cg + (size_t)blockIdx.z * M * N;

    const int nst = K >> 5;

#define ISSUE_STAGE(s_) do {                                                   \
        int _s = (s_);                                                         \
        uint32_t sa = sbase + (_s % 3) * STG_B;                                \
        uint32_t sb2 = sa + 18432;                                             \
        int _k0 = _s << 5;                                                     \
        _Pragma("unroll")                                                      \
        for (int t = 0; t < 4; ++t) {                                          \
            int c = tid + t * 256;                                             \
            int m = c >> 3, j = c & 7;                                         \
            cp16(sa + m * 144 + j * 16,                                        \
                 &A[(size_t)(mBase + m) * K + _k0 + (j << 2)]);                \
        }                                                                      \
        _Pragma("unroll")                                                      \
        for (int t = 0; t < 4; ++t) {                                          \
            int c = tid + t * 256;                                             \
            int k = c >> 5, j = c & 31;                                        \
            cp16(sb2 + k * 544 + j * 16,                                       \
                 &Bp[(size_t)(_k0 + k) * N + nBase + (j << 2)]);               \
        }                                                                      \
    } while (0)

    float d[4][4][4];
#pragma unroll
    for (int mi = 0; mi < 4; ++mi)
#pragma unroll
        for (int ni = 0; ni < 4; ++ni)
#pragma unroll
            for (int r = 0; r < 4; ++r) d[mi][ni][r] = 0.f;

    ISSUE_STAGE(0); CP_COMMIT;
    ISSUE_STAGE(1); CP_COMMIT;

    for (int s = 0; s < nst; ++s) {
        CP_WAIT1;
        __syncthreads();
        if (s + 2 < nst) ISSUE_STAGE(s + 2);
        CP_COMMIT;

        const float* As = sm + (s % 3) * STG_F;          // [m][36]
        const float* Bs = As + 4608;                     // [k][136]

#pragma unroll
        for (int kk = 0; kk < 32; kk += 8) {
            uint32_t af[4][4], bf[4][2];
#pragma unroll
            for (int mi = 0; mi < 4; ++mi) {
                int mr = wm + mi * 16 + gid;
                af[mi][0] = __float_as_uint(As[mr * 36 + kk + tid4]);
                af[mi][1] = __float_as_uint(As[(mr + 8) * 36 + kk + tid4]);
                af[mi][2] = __float_as_uint(As[mr * 36 + kk + tid4 + 4]);
                af[mi][3] = __float_as_uint(As[(mr + 8) * 36 + kk + tid4 + 4]);
            }
#pragma unroll
            for (int ni = 0; ni < 4; ++ni) {
                int nc = wn + ni * 8 + gid;
                bf[ni][0] = __float_as_uint(Bs[(kk + tid4) * 136 + nc]);
                bf[ni][1] = __float_as_uint(Bs[(kk + tid4 + 4) * 136 + nc]);
            }
#pragma unroll
            for (int mi = 0; mi < 4; ++mi)
#pragma unroll
                for (int ni = 0; ni < 4; ++ni)
                    mma_tf32_16x8x8(d[mi][ni], af[mi], bf[ni]);
        }
    }
#undef ISSUE_STAGE

#pragma unroll
    for (int mi = 0; mi < 4; ++mi) {
        int row = mBase + wm + mi * 16 + gid;
#pragma unroll
        for (int ni = 0; ni < 4; ++ni) {
            int col = nBase + wn + ni * 8 + 2 * tid4;
            *(float2*)&Cp[(size_t)row * N + col] =
                make_float2(d[mi][ni][0], d[mi][ni][1]);
            *(float2*)&Cp[(size_t)(row + 8) * N + col] =
                make_float2(d[mi][ni][2], d[mi][ni][3]);
        }
    }
}

// ---------------- BN stats ----------------
__global__ void bn_stats(const float* __restrict__ y,
                         const float* __restrict__ gamma,
                         const float* __restrict__ beta,
                         float* __restrict__ scl, float* __restrict__ shf, int C)
{
    int c = blockIdx.x, tid = threadIdx.x;
    float s = 0.f, s2 = 0.f;
    for (int i = tid; i < NB * NPix; i += 256) {
        int b = i >> 10, n = i & 1023;
        float v = y[((size_t)b * C + c) * NPix + n];
        s += v; s2 += v * v;
    }
    __shared__ float rs[256], rs2[256];
    rs[tid] = s; rs2[tid] = s2;
    __syncthreads();
    for (int off = 128; off > 0; off >>= 1) {
        if (tid < off) { rs[tid] += rs[tid + off]; rs2[tid] += rs2[tid + off]; }
        __syncthreads();
    }
    if (tid == 0) {
        const float invN = 1.f / (NB * NPix);
        float mean = rs[0] * invN;
        float var  = rs2[0] * invN - mean * mean;
        float sc   = gamma[c] * rsqrtf(var + 1e-5f);
        scl[c] = sc;
        shf[c] = beta[c] - mean * sc;
    }
}

// ---------------- BN application to qkv (in place, q pre-scaled, tf32) ----
__global__ void bn_apply_qkv(float* __restrict__ y,
                             const float* __restrict__ scl,
                             const float* __restrict__ shf)
{
    int i = blockIdx.x * 256 + threadIdx.x;            // float4 index
    int ch = (i >> 8) % C_QKV;
    float fac = ((ch % 192) < DK) ? 0.17677669529663687f : 1.f;
    float sc = scl[ch] * fac, sh = shf[ch] * fac;
    float4 v = ((float4*)y)[i];
    v.x = f2tf(v.x * sc + sh);
    v.y = f2tf(v.y * sc + sh);
    v.z = f2tf(v.z * sc + sh);
    v.w = f2tf(v.w * sc + sh);
    ((float4*)y)[i] = v;
}

// ---------------- fused flash attention (tf32 mma) + gelu ----------------
#define FL_SMEM 78848

__global__ void __launch_bounds__(256) flash_attn(const float* __restrict__ yqkv,
                                                  float* __restrict__ obuf)
{
    extern __shared__ float fsm[];
    float* Ks = fsm;
    float* Vs = fsm + 2304;
    float* Ps = fsm + 11008;
    float* Qs = Ps;
    float* Os = fsm;

    const int bh = blockIdx.y, b = bh >> 3, h = bh & 7;
    const int qBase = blockIdx.x * 128;
    const int tid = threadIdx.x, wid = tid >> 5, lane = tid & 31;
    const int gid = lane >> 2, tid4 = lane & 3;
    const float* base = yqkv + (size_t)b * C_QKV * NPix;

    // Q tile [32 d][128 q] — already BN'd, scaled, rounded
    for (int i = tid; i < 32 * 32; i += 256) {
        int d = i >> 5, q4 = (i & 31) << 2;
        int ch = h * 192 + d;
        *(float4*)&Qs[d * 136 + q4] =
            *(const float4*)&base[(size_t)ch * NPix + qBase + q4];
    }
    __syncthreads();

    uint32_t qf[4][4];
    const int mr = wid * 16 + gid;
#pragma unroll
    for (int ks = 0; ks < 4; ++ks) {
        qf[ks][0] = __float_as_uint(Qs[(ks * 8 + tid4) * 136 + mr]);
        qf[ks][1] = __float_as_uint(Qs[(ks * 8 + tid4) * 136 + mr + 8]);
        qf[ks][2] = __float_as_uint(Qs[(ks * 8 + tid4 + 4) * 136 + mr]);
        qf[ks][3] = __float_as_uint(Qs[(ks * 8 + tid4 + 4) * 136 + mr + 8]);
    }
    __syncthreads();

    float o[16][4];
#pragma unroll
    for (int nt = 0; nt < 16; ++nt)
#pragma unroll
        for (int r = 0; r < 4; ++r) o[nt][r] = 0.f;
    float m0 = -1e30f, m1 = -1e30f, l0 = 0.f, l1 = 0.f;

    for (int k0 = 0; k0 < NPix; k0 += 64) {
        // K tile [32 d][64 k] (float4 both sides)
        for (int i = tid; i < 32 * 16; i += 256) {
            int d = i >> 4, k4 = (i & 15) << 2;
            int ch = h * 192 + DK + d;
            *(float4*)&Ks[d * 72 + k4] =
                *(const float4*)&base[(size_t)ch * NPix + k0 + k4];
        }
        // V tile -> transposed Vs[k][dv] (float4 gmem read, scalar STS)
        for (int i = tid; i < 128 * 16; i += 256) {
            int dv = i >> 4, k4 = (i & 15) << 2;
            int ch = h * 192 + 2 * DK + dv;
            float4 v = *(const float4*)&base[(size_t)ch * NPix + k0 + k4];
            Vs[(k4 + 0) * 136 + dv] = v.x;
            Vs[(k4 + 1) * 136 + dv] = v.y;
            Vs[(k4 + 2) * 136 + dv] = v.z;
            Vs[(k4 + 3) * 136 + dv] = v.w;
        }
        __syncthreads();

        float s[8][4];
#pragma unroll
        for (int ni = 0; ni < 8; ++ni)
#pragma unroll
            for (int r = 0; r < 4; ++r) s[ni][r] = 0.f;
#pragma unroll
        for (int ks = 0; ks < 4; ++ks) {
#pragma unroll
            for (int ni = 0; ni < 8; ++ni) {
                uint32_t bf[2];
                bf[0] = __float_as_uint(Ks[(ks * 8 + tid4) * 72 + ni * 8 + gid]);
                bf[1] = __float_as_uint(Ks[(ks * 8 + tid4 + 4) * 72 + ni * 8 + gid]);
                mma_tf32_16x8x8(s[ni], qf[ks], bf);
            }
        }

        float t0 = -1e30f, t1 = -1e30f;
#pragma unroll
        for (int ni = 0; ni < 8; ++ni) {
            t0 = fmaxf(t0, fmaxf(s[ni][0], s[ni][1]));
            t1 = fmaxf(t1, fmaxf(s[ni][2], s[ni][3]));
        }
        t0 = fmaxf(t0, __shfl_xor_sync(0xffffffffu, t0, 1));
        t0 = fmaxf(t0, __shfl_xor_sync(0xffffffffu, t0, 2));
        t1 = fmaxf(t1, __shfl_xor_sync(0xffffffffu, t1, 1));
        t1 = fmaxf(t1, __shfl_xor_sync(0xffffffffu, t1, 2));
        float mn0 = fmaxf(m0, t0), mn1 = fmaxf(m1, t1);
        float a0 = __expf(m0 - mn0), a1 = __expf(m1 - mn1);
        m0 = mn0; m1 = mn1;

        float ps0 = 0.f, ps1 = 0.f;
#pragma unroll
        for (int ni = 0; ni < 8; ++ni) {
            s[ni][0] = f2tf(__expf(s[ni][0] - mn0));
            s[ni][1] = f2tf(__expf(s[ni][1] - mn0));
            s[ni][2] = f2tf(__expf(s[ni][2] - mn1));
            s[ni][3] = f2tf(__expf(s[ni][3] - mn1));
            ps0 += s[ni][0] + s[ni][1];
            ps1 += s[ni][2] + s[ni][3];
        }
        ps0 += __shfl_xor_sync(0xffffffffu, ps0, 1);
        ps0 += __shfl_xor_sync(0xffffffffu, ps0, 2);
        ps1 += __shfl_xor_sync(0xffffffffu, ps1, 1);
        ps1 += __shfl_xor_sync(0xffffffffu, ps1, 2);
        l0 = l0 * a0 + ps0;
        l1 = l1 * a1 + ps1;

#pragma unroll
        for (int nt = 0; nt < 16; ++nt) {
            o[nt][0] *= a0; o[nt][1] *= a0;
            o[nt][2] *= a1; o[nt][3] *= a1;
        }

#pragma unroll
        for (int ni = 0; ni < 8; ++ni) {
            Ps[(wid * 16 + gid) * 68 + ni * 8 + 2 * tid4]     = s[ni][0];
            Ps[(wid * 16 + gid) * 68 + ni * 8 + 2 * tid4 + 1] = s[ni][1];
            Ps[(wid * 16 + gid + 8) * 68 + ni * 8 + 2 * tid4]     = s[ni][2];
            Ps[(wid * 16 + gid + 8) * 68 + ni * 8 + 2 * tid4 + 1] = s[ni][3];
        }
        __syncwarp();

#pragma unroll
        for (int kk = 0; kk < 8; ++kk) {
            uint32_t pf[4];
            pf[0] = __float_as_uint(Ps[(wid * 16 + gid) * 68 + kk * 8 + tid4]);
            pf[1] = __float_as_uint(Ps[(wid * 16 + gid + 8) * 68 + kk * 8 + tid4]);
            pf[2] = __float_as_uint(Ps[(wid * 16 + gid) * 68 + kk * 8 + tid4 + 4]);
            pf[3] = __float_as_uint(Ps[(wid * 16 + gid + 8) * 68 + kk * 8 + tid4 + 4]);
#pragma unroll
            for (int nt = 0; nt < 16; ++nt) {
                uint32_t vf[2];
                vf[0] = __float_as_uint(Vs[(kk * 8 + tid4) * 136 + nt * 8 + gid]);
                vf[1] = __float_as_uint(Vs[(kk * 8 + tid4 + 4) * 136 + nt * 8 + gid]);
                mma_tf32_16x8x8(o[nt], pf, vf);
            }
        }
        __syncthreads();
    }

    float inv0 = 1.f / l0, inv1 = 1.f / l1;
    __syncthreads();
#pragma unroll
    for (int nt = 0; nt < 16; ++nt) {
        int dv = nt * 8 + 2 * tid4;
        int q  = wid * 16 + gid;
        Os[(size_t)dv * 132 + q]           = o[nt][0] * inv0;
        Os[(size_t)(dv + 1) * 132 + q]     = o[nt][1] * inv0;
        Os[(size_t)dv * 132 + q + 8]       = o[nt][2] * inv1;
        Os[(size_t)(dv + 1) * 132 + q + 8] = o[nt][3] * inv1;
    }
    __syncthreads();
    for (int i = tid; i < 128 * 32; i += 256) {
        int dv = i >> 5, q4 = (i & 31) << 2;
        int ch = b * 1024 + h * 128 + dv;
        float4 v = *(float4*)&Os[dv * 132 + q4];
        v.x = gelu_exact(v.x); v.y = gelu_exact(v.y);
        v.z = gelu_exact(v.z); v.w = gelu_exact(v.w);
        *(float4*)&obuf[(size_t)ch * NPix + qBase + q4] = v;
    }
}

// ---------------- elementwise ----------------
__global__ void resadd_bn(const float* __restrict__ x, const float* __restrict__ y,
                          const float* __restrict__ scl, const float* __restrict__ shf,
                          float* __restrict__ o, int C, int total)
{
    int i = blockIdx.x * 256 + threadIdx.x;
    if (i >= total) return;
    int ch = (i >> 10) % C;
    o[i] = x[i] + y[i] * scl[ch] + shf[ch];
}
__global__ void bn_gelu_inplace(float* __restrict__ y,
                                const float* __restrict__ scl,
                                const float* __restrict__ shf, int C, int total)
{
    int i = blockIdx.x * 256 + threadIdx.x;
    if (i >= total) return;
    int ch = (i >> 10) % C;
    y[i] = gelu_exact(y[i] * scl[ch] + shf[ch]);
}

// ---------------- host ----------------
extern "C" void kernel_launch(void* const* d_in, const int* in_sizes, int n_in,
                              void* d_out, int out_size)
{
    const float* x       = (const float*)d_in[0];
    const float* w_qkv   = (const float*)d_in[1];
    const float* gq      = (const float*)d_in[2];
    const float* bq      = (const float*)d_in[3];
    const float* w_merge = (const float*)d_in[4];
    const float* gm      = (const float*)d_in[5];
    const float* bm      = (const float*)d_in[6];
    const float* w_fc1   = (const float*)d_in[7];
    const float* g1      = (const float*)d_in[8];
    const float* b1      = (const float*)d_in[9];
    const float* w_fc2   = (const float*)d_in[10];
    const float* g2      = (const float*)d_in[11];
    const float* b2      = (const float*)d_in[12];
    float* out = (float*)d_out;

    float *yqkv, *obuf, *y2, *xr, *h1, *y3;
    float *scq, *shq, *scm, *shm, *sc1, *sh1, *sc2, *sh2;
    float *wq, *wm, *w1, *w2;
    cudaGetSymbolAddress((void**)&yqkv, g_yqkv);
    cudaGetSymbolAddress((void**)&obuf, g_obuf);
    cudaGetSymbolAddress((void**)&y2,   g_y2);
    cudaGetSymbolAddress((void**)&xr,   g_xr);
    cudaGetSymbolAddress((void**)&h1,   g_h1);
    cudaGetSymbolAddress((void**)&y3,   g_y3);
    cudaGetSymbolAddress((void**)&scq, g_sc_qkv);
    cudaGetSymbolAddress((void**)&shq, g_sh_qkv);
    cudaGetSymbolAddress((void**)&scm, g_sc_mg);
    cudaGetSymbolAddress((void**)&shm, g_sh_mg);
    cudaGetSymbolAddress((void**)&sc1, g_sc_f1);
    cudaGetSymbolAddress((void**)&sh1, g_sh_f1);
    cudaGetSymbolAddress((void**)&sc2, g_sc_f2);
    cudaGetSymbolAddress((void**)&sh2, g_sh_f2);
    cudaGetSymbolAddress((void**)&wq, g_wq);
    cudaGetSymbolAddress((void**)&wm, g_wm);
    cudaGetSymbolAddress((void**)&w1, g_w1);
    cudaGetSymbolAddress((void**)&w2, g_w2);

    cudaFuncSetAttribute(tf32_gemm, cudaFuncAttributeMaxDynamicSharedMemorySize, GEMM_SMEM);
    cudaFuncSetAttribute(flash_attn, cudaFuncAttributeMaxDynamicSharedMemorySize, FL_SMEM);

    // pre-round weights to tf32
    round_w<<<(C_QKV * C_IN / 4 + 255) / 256, 256>>>(w_qkv, wq, C_QKV * C_IN / 4);
    round_w<<<(C_MG * 1024 / 4 + 255) / 256, 256>>>(w_merge, wm, C_MG * 1024 / 4);
    round_w<<<(C_F1 * C_IN / 4 + 255) / 256, 256>>>(w_fc1, w1, C_F1 * C_IN / 4);
    round_w<<<(C_F2 * C_F1 / 4 + 255) / 256, 256>>>(w_fc2, w2, C_F2 * C_F1 / 4);

    tf32_gemm<<<dim3(C_QKV/128, NPix/128, NB), 256, GEMM_SMEM>>>(wq, x, yqkv, C_QKV, NPix, C_IN);
    bn_stats<<<C_QKV, 256>>>(yqkv, gq, bq, scq, shq, C_QKV);
    bn_apply_qkv<<<NB * C_QKV * NPix / 4 / 256, 256>>>(yqkv, scq, shq);
    flash_attn<<<dim3(8, 64), 256, FL_SMEM>>>(yqkv, obuf);
    tf32_gemm<<<dim3(C_MG/128, NPix/128, NB), 256, GEMM_SMEM>>>(wm, obuf, y2, C_MG, NPix, 1024);
    bn_stats<<<C_MG, 256>>>(y2, gm, bm, scm, shm, C_MG);
    {
        int total = NB * C_IN * NPix;
        resadd_bn<<<(total + 255) / 256, 256>>>(x, y2, scm, shm, xr, C_MG, total);
    }
    tf32_gemm<<<dim3(C_F1/128, NPix/128, NB), 256, GEMM_SMEM>>>(w1, xr, h1, C_F1, NPix, C_IN);
    bn_stats<<<C_F1, 256>>>(h1, g1, b1, sc1, sh1, C_F1);
    {
        int total = NB * C_F1 * NPix;
        bn_gelu_inplace<<<(total + 255) / 256, 256>>>(h1, sc1, sh1, C_F1, total);
    }
    tf32_gemm<<<dim3(C_F2/128, NPix/128, NB), 256, GEMM_SMEM>>>(w2, h1, y3, C_F2, NPix, C_F1);
    bn_stats<<<C_F2, 256>>>(y3, g2, b2, sc2, sh2, C_F2);
    {
        int total = NB * C_F2 * NPix;
        resadd_bn<<<(total + 255) / 256, 256>>>(xr, y3, sc2, sh2, out, C_F2, total);
    }
}

// round 8
// speedup vs baseline: 2.6208x; 1.0099x over previous
#include <cuda_runtime.h>
#include <cstdint>
#include <math.h>

#define NB    8
#define NPix  1024
#define C_IN  384
#define C_QKV 1536
#define C_MG  384
#define C_F1  768
#define C_F2  384
#define DK    32
#define DV    128
#define NPARTS 64          // gridDim.y * gridDim.z for every GEMM (8*8)

__device__ float g_yqkv[NB * C_QKV * NPix];
__device__ float g_obuf[NB * 1024 * NPix];
__device__ float g_y2  [NB * C_MG * NPix];
__device__ float g_xr  [NB * C_IN * NPix];
__device__ float g_h1  [NB * C_F1 * NPix];
__device__ float g_y3  [NB * C_F2 * NPix];
__device__ float g_part[NPARTS * C_QKV * 2];
__device__ float g_sc_qkv[C_QKV], g_sh_qkv[C_QKV];
__device__ float g_sc_mg [C_MG ], g_sh_mg [C_MG ];
__device__ float g_sc_f1 [C_F1 ], g_sh_f1 [C_F1 ];
__device__ float g_sc_f2 [C_F2 ], g_sh_f2 [C_F2 ];
__device__ float g_wq[C_QKV * C_IN];
__device__ float g_wm[C_MG * 1024];
__device__ float g_w1[C_F1 * C_IN];
__device__ float g_w2[C_F2 * C_F1];

__device__ __forceinline__ float gelu_exact(float v) { return v * normcdff(v); }

__device__ __forceinline__ float f2tf(float f) {
    uint32_t r;
    asm("cvt.rna.tf32.f32 %0, %1;" : "=r"(r) : "f"(f));
    return __uint_as_float(r);
}

__device__ __forceinline__ void mma_tf32_16x8x8(float d[4],
                                                const uint32_t a[4],
                                                const uint32_t b[2])
{
    asm volatile(
        "mma.sync.aligned.m16n8k8.row.col.f32.tf32.tf32.f32 "
        "{%0,%1,%2,%3}, {%4,%5,%6,%7}, {%8,%9}, {%0,%1,%2,%3};"
        : "+f"(d[0]), "+f"(d[1]), "+f"(d[2]), "+f"(d[3])
        : "r"(a[0]), "r"(a[1]), "r"(a[2]), "r"(a[3]), "r"(b[0]), "r"(b[1]));
}

__device__ __forceinline__ void cp16(uint32_t saddr, const void* gptr) {
    asm volatile("cp.async.cg.shared.global [%0], [%1], 16;" :: "r"(saddr), "l"(gptr));
}
#define CP_COMMIT asm volatile("cp.async.commit_group;" ::: "memory")
#define CP_WAIT1  asm volatile("cp.async.wait_group 1;" ::: "memory")

// ---------------- weight pre-rounding ----------------
__global__ void round_w(const float* __restrict__ w, float* __restrict__ o, int n4)
{
    int i = blockIdx.x * 256 + threadIdx.x;
    if (i >= n4) return;
    float4 v = ((const float4*)w)[i];
    v.x = f2tf(v.x); v.y = f2tf(v.y); v.z = f2tf(v.z); v.w = f2tf(v.w);
    ((float4*)o)[i] = v;
}

// ---------------- tf32 GEMM + fused BN partial stats ----------------------
#define STG_F 8960
#define STG_B 35840
#define GEMM_SMEM (3 * STG_B)

__global__ void __launch_bounds__(256, 2) tf32_gemm(const float* __restrict__ A,
                                                    const float* __restrict__ Bg,
                                                    float* __restrict__ Cg,
                                                    float* __restrict__ part,
                                                    int M, int N, int K)
{
    extern __shared__ float sm[];
    const uint32_t sbase = (uint32_t)__cvta_generic_to_shared(sm);

    const int tid  = threadIdx.x;
    const int wid  = tid >> 5;
    const int lane = tid & 31;
    const int gid  = lane >> 2;
    const int tid4 = lane & 3;
    const int wm   = (wid & 1) * 64;
    const int wn   = (wid >> 1) * 32;

    const int mBase = blockIdx.x * 128, nBase = blockIdx.y * 128;
    const float* Bp = Bg + (size_t)blockIdx.z * K * N;
    float*       Cp = Cg + (size_t)blockIdx.z * M * N;

    const int nst = K >> 5;

#define ISSUE_STAGE(s_) do {                                                   \
        int _s = (s_);                                                         \
        uint32_t sa = sbase + (_s % 3) * STG_B;                                \
        uint32_t sb2 = sa + 18432;                                             \
        int _k0 = _s << 5;                                                     \
        _Pragma("unroll")                                                      \
        for (int t = 0; t < 4; ++t) {                                          \
            int c = tid + t * 256;                                             \
            int m = c >> 3, j = c & 7;                                         \
            cp16(sa + m * 144 + j * 16,                                        \
                 &A[(size_t)(mBase + m) * K + _k0 + (j << 2)]);                \
        }                                                                      \
        _Pragma("unroll")                                                      \
        for (int t = 0; t < 4; ++t) {                                          \
            int c = tid + t * 256;                                             \
            int k = c >> 5, j = c & 31;                                        \
            cp16(sb2 + k * 544 + j * 16,                                       \
                 &Bp[(size_t)(_k0 + k) * N + nBase + (j << 2)]);               \
        }                                                                      \
    } while (0)

    float d[4][4][4];
#pragma unroll
    for (int mi = 0; mi < 4; ++mi)
#pragma unroll
        for (int ni = 0; ni < 4; ++ni)
#pragma unroll
            for (int r = 0; r < 4; ++r) d[mi][ni][r] = 0.f;

    ISSUE_STAGE(0); CP_COMMIT;
    ISSUE_STAGE(1); CP_COMMIT;

    for (int s = 0; s < nst; ++s) {
        CP_WAIT1;
        __syncthreads();
        if (s + 2 < nst) ISSUE_STAGE(s + 2);
        CP_COMMIT;

        const float* As = sm + (s % 3) * STG_F;          // [m][36]
        const float* Bs = As + 4608;                     // [k][136]

#pragma unroll
        for (int kk = 0; kk < 32; kk += 8) {
            uint32_t af[4][4], bf[4][2];
#pragma unroll
            for (int mi = 0; mi < 4; ++mi) {
                int mr = wm + mi * 16 + gid;
                af[mi][0] = __float_as_uint(As[mr * 36 + kk + tid4]);
                af[mi][1] = __float_as_uint(As[(mr + 8) * 36 + kk + tid4]);
                af[mi][2] = __float_as_uint(As[mr * 36 + kk + tid4 + 4]);
                af[mi][3] = __float_as_uint(As[(mr + 8) * 36 + kk + tid4 + 4]);
            }
#pragma unroll
            for (int ni = 0; ni < 4; ++ni) {
                int nc = wn + ni * 8 + gid;
                bf[ni][0] = __float_as_uint(Bs[(kk + tid4) * 136 + nc]);
                bf[ni][1] = __float_as_uint(Bs[(kk + tid4 + 4) * 136 + nc]);
            }
#pragma unroll
            for (int mi = 0; mi < 4; ++mi)
#pragma unroll
                for (int ni = 0; ni < 4; ++ni)
                    mma_tf32_16x8x8(d[mi][ni], af[mi], bf[ni]);
        }
    }
#undef ISSUE_STAGE

    // ---- store C + per-row BN partial sums ----
    float sl[4], ql[4], sh_[4], qh[4];
#pragma unroll
    for (int mi = 0; mi < 4; ++mi) {
        sl[mi] = ql[mi] = sh_[mi] = qh[mi] = 0.f;
        int row = mBase + wm + mi * 16 + gid;
#pragma unroll
        for (int ni = 0; ni < 4; ++ni) {
            int col = nBase + wn + ni * 8 + 2 * tid4;
            sl[mi] += d[mi][ni][0] + d[mi][ni][1];
            ql[mi] += d[mi][ni][0] * d[mi][ni][0] + d[mi][ni][1] * d[mi][ni][1];
            sh_[mi] += d[mi][ni][2] + d[mi][ni][3];
            qh[mi] += d[mi][ni][2] * d[mi][ni][2] + d[mi][ni][3] * d[mi][ni][3];
            *(float2*)&Cp[(size_t)row * N + col] =
                make_float2(d[mi][ni][0], d[mi][ni][1]);
            *(float2*)&Cp[(size_t)(row + 8) * N + col] =
                make_float2(d[mi][ni][2], d[mi][ni][3]);
        }
#pragma unroll
        for (int off = 1; off <= 2; off <<= 1) {
            sl[mi]  += __shfl_xor_sync(0xffffffffu, sl[mi],  off);
            ql[mi]  += __shfl_xor_sync(0xffffffffu, ql[mi],  off);
            sh_[mi] += __shfl_xor_sync(0xffffffffu, sh_[mi], off);
            qh[mi]  += __shfl_xor_sync(0xffffffffu, qh[mi],  off);
        }
    }
    __syncthreads();                 // mainloop smem traffic done
    float* pb = sm;                  // [4 groups][128 rows][2]
    if (tid4 == 0) {
        int g = wid >> 1;
#pragma unroll
        for (int mi = 0; mi < 4; ++mi) {
            int lr = wm + mi * 16 + gid;
            pb[(g * 128 + lr) * 2 + 0]     = sl[mi];
            pb[(g * 128 + lr) * 2 + 1]     = ql[mi];
            pb[(g * 128 + lr + 8) * 2 + 0] = sh_[mi];
            pb[(g * 128 + lr + 8) * 2 + 1] = qh[mi];
        }
    }
    __syncthreads();
    if (tid < 128) {
        float s = 0.f, q = 0.f;
#pragma unroll
        for (int g = 0; g < 4; ++g) {
            s += pb[(g * 128 + tid) * 2 + 0];
            q += pb[(g * 128 + tid) * 2 + 1];
        }
        int pidx = blockIdx.y * gridDim.z + blockIdx.z;
        part[((size_t)pidx * M + mBase + tid) * 2 + 0] = s;
        part[((size_t)pidx * M + mBase + tid) * 2 + 1] = q;
    }
}

// ---------------- BN finalize: partials -> scale/shift ----------------
__global__ void bn_finalize(const float* __restrict__ part,
                            const float* __restrict__ gamma,
                            const float* __restrict__ beta,
                            float* __restrict__ scl, float* __restrict__ shf, int C)
{
    int c = blockIdx.x * 128 + threadIdx.x;
    if (c >= C) return;
    float s = 0.f, q = 0.f;
    for (int p = 0; p < NPARTS; ++p) {
        s += part[((size_t)p * C + c) * 2 + 0];
        q += part[((size_t)p * C + c) * 2 + 1];
    }
    const float invN = 1.f / (NB * NPix);
    float mean = s * invN;
    float var  = q * invN - mean * mean;
    float sc   = gamma[c] * rsqrtf(var + 1e-5f);
    scl[c] = sc;
    shf[c] = beta[c] - mean * sc;
}

// ---------------- fused flash attention (BN on load) + gelu ----------------
#define FL_SMEM 78848

__global__ void __launch_bounds__(256) flash_attn(const float* __restrict__ yqkv,
                                                  const float* __restrict__ scl,
                                                  const float* __restrict__ shf,
                                                  float* __restrict__ obuf)
{
    extern __shared__ float fsm[];
    float* Ks = fsm;
    float* Vs = fsm + 2304;
    float* Ps = fsm + 11008;
    float* Qs = Ps;
    float* Os = fsm;

    const int bh = blockIdx.y, b = bh >> 3, h = bh & 7;
    const int qBase = blockIdx.x * 128;
    const int tid = threadIdx.x, wid = tid >> 5, lane = tid & 31;
    const int gid = lane >> 2, tid4 = lane & 3;
    const float* base = yqkv + (size_t)b * C_QKV * NPix;

    // Q tile [32 d][128 q]: BN + 1/sqrt(dk), RNA-rounded
    for (int i = tid; i < 32 * 32; i += 256) {
        int d = i >> 5, q4 = (i & 31) << 2;
        int ch = h * 192 + d;
        float sc = scl[ch] * 0.17677669529663687f;
        float sh = shf[ch] * 0.17677669529663687f;
        float4 v = *(const float4*)&base[(size_t)ch * NPix + qBase + q4];
        v.x = f2tf(v.x * sc + sh); v.y = f2tf(v.y * sc + sh);
        v.z = f2tf(v.z * sc + sh); v.w = f2tf(v.w * sc + sh);
        *(float4*)&Qs[d * 136 + q4] = v;
    }
    __syncthreads();

    uint32_t qf[4][4];
    const int mr = wid * 16 + gid;
#pragma unroll
    for (int ks = 0; ks < 4; ++ks) {
        qf[ks][0] = __float_as_uint(Qs[(ks * 8 + tid4) * 136 + mr]);
        qf[ks][1] = __float_as_uint(Qs[(ks * 8 + tid4) * 136 + mr + 8]);
        qf[ks][2] = __float_as_uint(Qs[(ks * 8 + tid4 + 4) * 136 + mr]);
        qf[ks][3] = __float_as_uint(Qs[(ks * 8 + tid4 + 4) * 136 + mr + 8]);
    }
    __syncthreads();

    float o[16][4];
#pragma unroll
    for (int nt = 0; nt < 16; ++nt)
#pragma unroll
        for (int r = 0; r < 4; ++r) o[nt][r] = 0.f;
    float m0 = -1e30f, m1 = -1e30f, l0 = 0.f, l1 = 0.f;

    for (int k0 = 0; k0 < NPix; k0 += 64) {
        // K tile [32 d][64 k], BN + RNA
        for (int i = tid; i < 32 * 16; i += 256) {
            int d = i >> 4, k4 = (i & 15) << 2;
            int ch = h * 192 + DK + d;
            float sc = scl[ch], sh = shf[ch];
            float4 v = *(const float4*)&base[(size_t)ch * NPix + k0 + k4];
            v.x = f2tf(v.x * sc + sh); v.y = f2tf(v.y * sc + sh);
            v.z = f2tf(v.z * sc + sh); v.w = f2tf(v.w * sc + sh);
            *(float4*)&Ks[d * 72 + k4] = v;
        }
        // V tile -> transposed Vs[k][dv], BN + RNA
        for (int i = tid; i < 128 * 16; i += 256) {
            int dv = i >> 4, k4 = (i & 15) << 2;
            int ch = h * 192 + 2 * DK + dv;
            float sc = scl[ch], sh = shf[ch];
            float4 v = *(const float4*)&base[(size_t)ch * NPix + k0 + k4];
            Vs[(k4 + 0) * 136 + dv] = f2tf(v.x * sc + sh);
            Vs[(k4 + 1) * 136 + dv] = f2tf(v.y * sc + sh);
            Vs[(k4 + 2) * 136 + dv] = f2tf(v.z * sc + sh);
            Vs[(k4 + 3) * 136 + dv] = f2tf(v.w * sc + sh);
        }
        __syncthreads();

        float s[8][4];
#pragma unroll
        for (int ni = 0; ni < 8; ++ni)
#pragma unroll
            for (int r = 0; r < 4; ++r) s[ni][r] = 0.f;
#pragma unroll
        for (int ks = 0; ks < 4; ++ks) {
#pragma unroll
            for (int ni = 0; ni < 8; ++ni) {
                uint32_t bf[2];
                bf[0] = __float_as_uint(Ks[(ks * 8 + tid4) * 72 + ni * 8 + gid]);
                bf[1] = __float_as_uint(Ks[(ks * 8 + tid4 + 4) * 72 + ni * 8 + gid]);
                mma_tf32_16x8x8(s[ni], qf[ks], bf);
            }
        }

        float t0 = -1e30f, t1 = -1e30f;
#pragma unroll
        for (int ni = 0; ni < 8; ++ni) {
            t0 = fmaxf(t0, fmaxf(s[ni][0], s[ni][1]));
            t1 = fmaxf(t1, fmaxf(s[ni][2], s[ni][3]));
        }
        t0 = fmaxf(t0, __shfl_xor_sync(0xffffffffu, t0, 1));
        t0 = fmaxf(t0, __shfl_xor_sync(0xffffffffu, t0, 2));
        t1 = fmaxf(t1, __shfl_xor_sync(0xffffffffu, t1, 1));
        t1 = fmaxf(t1, __shfl_xor_sync(0xffffffffu, t1, 2));
        float mn0 = fmaxf(m0, t0), mn1 = fmaxf(m1, t1);
        float a0 = __expf(m0 - mn0), a1 = __expf(m1 - mn1);
        m0 = mn0; m1 = mn1;

        float ps0 = 0.f, ps1 = 0.f;
#pragma unroll
        for (int ni = 0; ni < 8; ++ni) {
            s[ni][0] = __expf(s[ni][0] - mn0);
            s[ni][1] = __expf(s[ni][1] - mn0);
            s[ni][2] = __expf(s[ni][2] - mn1);
            s[ni][3] = __expf(s[ni][3] - mn1);
            ps0 += s[ni][0] + s[ni][1];
            ps1 += s[ni][2] + s[ni][3];
        }
        ps0 += __shfl_xor_sync(0xffffffffu, ps0, 1);
        ps0 += __shfl_xor_sync(0xffffffffu, ps0, 2);
        ps1 += __shfl_xor_sync(0xffffffffu, ps1, 1);
        ps1 += __shfl_xor_sync(0xffffffffu, ps1, 2);
        l0 = l0 * a0 + ps0;
        l1 = l1 * a1 + ps1;

#pragma unroll
        for (int nt = 0; nt < 16; ++nt) {
            o[nt][0] *= a0; o[nt][1] *= a0;
            o[nt][2] *= a1; o[nt][3] *= a1;
        }

#pragma unroll
        for (int ni = 0; ni < 8; ++ni) {
            Ps[(wid * 16 + gid) * 68 + ni * 8 + 2 * tid4]     = s[ni][0];
            Ps[(wid * 16 + gid) * 68 + ni * 8 + 2 * tid4 + 1] = s[ni][1];
            Ps[(wid * 16 + gid + 8) * 68 + ni * 8 + 2 * tid4]     = s[ni][2];
            Ps[(wid * 16 + gid + 8) * 68 + ni * 8 + 2 * tid4 + 1] = s[ni][3];
        }
        __syncwarp();

#pragma unroll
        for (int kk = 0; kk < 8; ++kk) {
            uint32_t pf[4];
            pf[0] = __float_as_uint(Ps[(wid * 16 + gid) * 68 + kk * 8 + tid4]);
            pf[1] = __float_as_uint(Ps[(wid * 16 + gid + 8) * 68 + kk * 8 + tid4]);
            pf[2] = __float_as_uint(Ps[(wid * 16 + gid) * 68 + kk * 8 + tid4 + 4]);
            pf[3] = __float_as_uint(Ps[(wid * 16 + gid + 8) * 68 + kk * 8 + tid4 + 4]);
#pragma unroll
            for (int nt = 0; nt < 16; ++nt) {
                uint32_t vf[2];
                vf[0] = __float_as_uint(Vs[(kk * 8 + tid4) * 136 + nt * 8 + gid]);
                vf[1] = __float_as_uint(Vs[(kk * 8 + tid4 + 4) * 136 + nt * 8 + gid]);
                mma_tf32_16x8x8(o[nt], pf, vf);
            }
        }
        __syncthreads();
    }

    float inv0 = 1.f / l0, inv1 = 1.f / l1;
    __syncthreads();
#pragma unroll
    for (int nt = 0; nt < 16; ++nt) {
        int dv = nt * 8 + 2 * tid4;
        int q  = wid * 16 + gid;
        Os[(size_t)dv * 132 + q]           = o[nt][0] * inv0;
        Os[(size_t)(dv + 1) * 132 + q]     = o[nt][1] * inv0;
        Os[(size_t)dv * 132 + q + 8]       = o[nt][2] * inv1;
        Os[(size_t)(dv + 1) * 132 + q + 8] = o[nt][3] * inv1;
    }
    __syncthreads();
    for (int i = tid; i < 128 * 32; i += 256) {
        int dv = i >> 5, q4 = (i & 31) << 2;
        int ch = b * 1024 + h * 128 + dv;
        float4 v = *(float4*)&Os[dv * 132 + q4];
        v.x = gelu_exact(v.x); v.y = gelu_exact(v.y);
        v.z = gelu_exact(v.z); v.w = gelu_exact(v.w);
        *(float4*)&obuf[(size_t)ch * NPix + qBase + q4] = v;
    }
}

// ---------------- elementwise ----------------
__global__ void resadd_bn(const float* __restrict__ x, const float* __restrict__ y,
                          const float* __restrict__ scl, const float* __restrict__ shf,
                          float* __restrict__ o, int C, int total)
{
    int i = blockIdx.x * 256 + threadIdx.x;
    if (i >= total) return;
    int ch = (i >> 10) % C;
    o[i] = x[i] + y[i] * scl[ch] + shf[ch];
}
__global__ void bn_gelu_inplace(float* __restrict__ y,
                                const float* __restrict__ scl,
                                const float* __restrict__ shf, int C, int total)
{
    int i = blockIdx.x * 256 + threadIdx.x;
    if (i >= total) return;
    int ch = (i >> 10) % C;
    y[i] = gelu_exact(y[i] * scl[ch] + shf[ch]);
}

// ---------------- host ----------------
extern "C" void kernel_launch(void* const* d_in, const int* in_sizes, int n_in,
                              void* d_out, int out_size)
{
    const float* x       = (const float*)d_in[0];
    const float* w_qkv   = (const float*)d_in[1];
    const float* gq      = (const float*)d_in[2];
    const float* bq      = (const float*)d_in[3];
    const float* w_merge = (const float*)d_in[4];
    const float* gm      = (const float*)d_in[5];
    const float* bm      = (const float*)d_in[6];
    const float* w_fc1   = (const float*)d_in[7];
    const float* g1      = (const float*)d_in[8];
    const float* b1      = (const float*)d_in[9];
    const float* w_fc2   = (const float*)d_in[10];
    const float* g2      = (const float*)d_in[11];
    const float* b2      = (const float*)d_in[12];
    float* out = (float*)d_out;

    float *yqkv, *obuf, *y2, *xr, *h1, *y3, *part;
    float *scq, *shq, *scm, *shm, *sc1, *sh1, *sc2, *sh2;
    float *wq, *wm, *w1, *w2;
    cudaGetSymbolAddress((void**)&yqkv, g_yqkv);
    cudaGetSymbolAddress((void**)&obuf, g_obuf);
    cudaGetSymbolAddress((void**)&y2,   g_y2);
    cudaGetSymbolAddress((void**)&xr,   g_xr);
    cudaGetSymbolAddress((void**)&h1,   g_h1);
    cudaGetSymbolAddress((void**)&y3,   g_y3);
    cudaGetSymbolAddress((void**)&part, g_part);
    cudaGetSymbolAddress((void**)&scq, g_sc_qkv);
    cudaGetSymbolAddress((void**)&shq, g_sh_qkv);
    cudaGetSymbolAddress((void**)&scm, g_sc_mg);
    cudaGetSymbolAddress((void**)&shm, g_sh_mg);
    cudaGetSymbolAddress((void**)&sc1, g_sc_f1);
    cudaGetSymbolAddress((void**)&sh1, g_sh_f1);
    cudaGetSymbolAddress((void**)&sc2, g_sc_f2);
    cudaGetSymbolAddress((void**)&sh2, g_sh_f2);
    cudaGetSymbolAddress((void**)&wq, g_wq);
    cudaGetSymbolAddress((void**)&wm, g_wm);
    cudaGetSymbolAddress((void**)&w1, g_w1);
    cudaGetSymbolAddress((void**)&w2, g_w2);

    cudaFuncSetAttribute(tf32_gemm, cudaFuncAttributeMaxDynamicSharedMemorySize, GEMM_SMEM);
    cudaFuncSetAttribute(flash_attn, cudaFuncAttributeMaxDynamicSharedMemorySize, FL_SMEM);

    round_w<<<(C_QKV * C_IN / 4 + 255) / 256, 256>>>(w_qkv, wq, C_QKV * C_IN / 4);
    round_w<<<(C_MG * 1024 / 4 + 255) / 256, 256>>>(w_merge, wm, C_MG * 1024 / 4);
    round_w<<<(C_F1 * C_IN / 4 + 255) / 256, 256>>>(w_fc1, w1, C_F1 * C_IN / 4);
    round_w<<<(C_F2 * C_F1 / 4 + 255) / 256, 256>>>(w_fc2, w2, C_F2 * C_F1 / 4);

    tf32_gemm<<<dim3(C_QKV/128, NPix/128, NB), 256, GEMM_SMEM>>>(wq, x, yqkv, part, C_QKV, NPix, C_IN);
    bn_finalize<<<(C_QKV + 127) / 128, 128>>>(part, gq, bq, scq, shq, C_QKV);
    flash_attn<<<dim3(8, 64), 256, FL_SMEM>>>(yqkv, scq, shq, obuf);
    tf32_gemm<<<dim3(C_MG/128, NPix/128, NB), 256, GEMM_SMEM>>>(wm, obuf, y2, part, C_MG, NPix, 1024);
    bn_finalize<<<(C_MG + 127) / 128, 128>>>(part, gm, bm, scm, shm, C_MG);
    {
        int total = NB * C_IN * NPix;
        resadd_bn<<<(total + 255) / 256, 256>>>(x, y2, scm, shm, xr, C_MG, total);
    }
    tf32_gemm<<<dim3(C_F1/128, NPix/128, NB), 256, GEMM_SMEM>>>(w1, xr, h1, part, C_F1, NPix, C_IN);
    bn_finalize<<<(C_F1 + 127) / 128, 128>>>(part, g1, b1, sc1, sh1, C_F1);
    {
        int total = NB * C_F1 * NPix;
        bn_gelu_inplace<<<(total + 255) / 256, 256>>>(h1, sc1, sh1, C_F1, total);
    }
    tf32_gemm<<<dim3(C_F2/128, NPix/128, NB), 256, GEMM_SMEM>>>(w2, h1, y3, part, C_F2, NPix, C_F1);
    bn_finalize<<<(C_F2 + 127) / 128, 128>>>(part, g2, b2, sc2, sh2, C_F2);
    {
        int total = NB * C_F2 * NPix;
        resadd_bn<<<(total + 255) / 256, 256>>>(xr, y3, sc2, sh2, out, C_F2, total);
    }
}

// round 9
// speedup vs baseline: 2.6691x; 1.0184x over previous
#include <cuda_runtime.h>
#include <cstdint>
#include <math.h>

#define NB    8
#define NPix  1024
#define C_IN  384
#define C_QKV 1536
#define C_MG  384
#define C_F1  768
#define C_F2  384
#define DK    32
#define DV    128
#define NPARTS 64

__device__ float g_yqkv[NB * C_QKV * NPix];
__device__ float g_obuf[NB * 1024 * NPix];
__device__ float g_y2  [NB * C_MG * NPix];
__device__ float g_xr  [NB * C_IN * NPix];
__device__ float g_h1  [NB * C_F1 * NPix];
__device__ float g_y3  [NB * C_F2 * NPix];
__device__ float g_part[NPARTS * C_QKV * 2];
__device__ float g_sc_qkv[C_QKV], g_sh_qkv[C_QKV];
__device__ float g_sc_mg [C_MG ], g_sh_mg [C_MG ];
__device__ float g_sc_f1 [C_F1 ], g_sh_f1 [C_F1 ];
__device__ float g_sc_f2 [C_F2 ], g_sh_f2 [C_F2 ];
__device__ float g_wq[C_QKV * C_IN];
__device__ float g_wm[C_MG * 1024];
__device__ float g_w1[C_F1 * C_IN];
__device__ float g_w2[C_F2 * C_F1];

__device__ __forceinline__ float gelu_exact(float v) { return v * normcdff(v); }

__device__ __forceinline__ float f2tf(float f) {
    uint32_t r;
    asm("cvt.rna.tf32.f32 %0, %1;" : "=r"(r) : "f"(f));
    return __uint_as_float(r);
}

__device__ __forceinline__ void mma_tf32_16x8x8(float d[4],
                                                const uint32_t a[4],
                                                const uint32_t b[2])
{
    asm volatile(
        "mma.sync.aligned.m16n8k8.row.col.f32.tf32.tf32.f32 "
        "{%0,%1,%2,%3}, {%4,%5,%6,%7}, {%8,%9}, {%0,%1,%2,%3};"
        : "+f"(d[0]), "+f"(d[1]), "+f"(d[2]), "+f"(d[3])
        : "r"(a[0]), "r"(a[1]), "r"(a[2]), "r"(a[3]), "r"(b[0]), "r"(b[1]));
}

__device__ __forceinline__ void cp16(uint32_t saddr, const void* gptr) {
    asm volatile("cp.async.cg.shared.global [%0], [%1], 16;" :: "r"(saddr), "l"(gptr));
}
#define CP_COMMIT asm volatile("cp.async.commit_group;" ::: "memory")
#define CP_WAIT1  asm volatile("cp.async.wait_group 1;" ::: "memory")

// ---------------- weight pre-rounding (single launch) ----------------
__global__ void round_all(const float* __restrict__ w0, float* __restrict__ o0,
                          const float* __restrict__ w1, float* __restrict__ o1,
                          const float* __restrict__ w2, float* __restrict__ o2,
                          const float* __restrict__ w3, float* __restrict__ o3)
{
    int i = blockIdx.x * 256 + threadIdx.x;     // float4 index over all weights
    const float* w; float* o; int j = i;
    if (j < 147456)              { w = w0; o = o0; }
    else if ((j -= 147456) < 98304) { w = w1; o = o1; }
    else if ((j -=  98304) < 73728) { w = w2; o = o2; }
    else                          { j -= 73728; w = w3; o = o3; }
    float4 v = ((const float4*)w)[j];
    v.x = f2tf(v.x); v.y = f2tf(v.y); v.z = f2tf(v.z); v.w = f2tf(v.w);
    ((float4*)o)[j] = v;
}

// ---------------- tf32 GEMM + fused BN partial stats ----------------------
#define STG_F 8960
#define STG_B 35840
#define GEMM_SMEM (3 * STG_B)

__global__ void __launch_bounds__(256, 2) tf32_gemm(const float* __restrict__ A,
                                                    const float* __restrict__ Bg,
                                                    float* __restrict__ Cg,
                                                    float* __restrict__ part,
                                                    int M, int N, int K)
{
    extern __shared__ float sm[];
    const uint32_t sbase = (uint32_t)__cvta_generic_to_shared(sm);

    const int tid  = threadIdx.x;
    const int wid  = tid >> 5;
    const int lane = tid & 31;
    const int gid  = lane >> 2;
    const int tid4 = lane & 3;
    const int wm   = (wid & 1) * 64;
    const int wn   = (wid >> 1) * 32;

    const int mBase = blockIdx.x * 128, nBase = blockIdx.y * 128;
    const float* Bp = Bg + (size_t)blockIdx.z * K * N;
    float*       Cp = Cg + (size_t)blockIdx.z * M * N;

    const int nst = K >> 5;

#define ISSUE_STAGE(s_) do {                                                   \
        int _s = (s_);                                                         \
        uint32_t sa = sbase + (_s % 3) * STG_B;                                \
        uint32_t sb2 = sa + 18432;                                             \
        int _k0 = _s << 5;                                                     \
        _Pragma("unroll")                                                      \
        for (int t = 0; t < 4; ++t) {                                          \
            int c = tid + t * 256;                                             \
            int m = c >> 3, j = c & 7;                                         \
            cp16(sa + m * 144 + j * 16,                                        \
                 &A[(size_t)(mBase + m) * K + _k0 + (j << 2)]);                \
        }                                                                      \
        _Pragma("unroll")                                                      \
        for (int t = 0; t < 4; ++t) {                                          \
            int c = tid + t * 256;                                             \
            int k = c >> 5, j = c & 31;                                        \
            cp16(sb2 + k * 544 + j * 16,                                       \
                 &Bp[(size_t)(_k0 + k) * N + nBase + (j << 2)]);               \
        }                                                                      \
    } while (0)

    float d[4][4][4];
#pragma unroll
    for (int mi = 0; mi < 4; ++mi)
#pragma unroll
        for (int ni = 0; ni < 4; ++ni)
#pragma unroll
            for (int r = 0; r < 4; ++r) d[mi][ni][r] = 0.f;

    ISSUE_STAGE(0); CP_COMMIT;
    ISSUE_STAGE(1); CP_COMMIT;

    for (int s = 0; s < nst; ++s) {
        CP_WAIT1;
        __syncthreads();
        if (s + 2 < nst) ISSUE_STAGE(s + 2);
        CP_COMMIT;

        const float* As = sm + (s % 3) * STG_F;
        const float* Bs = As + 4608;

#pragma unroll
        for (int kk = 0; kk < 32; kk += 8) {
            uint32_t af[4][4], bf[4][2];
#pragma unroll
            for (int mi = 0; mi < 4; ++mi) {
                int mr = wm + mi * 16 + gid;
                af[mi][0] = __float_as_uint(As[mr * 36 + kk + tid4]);
                af[mi][1] = __float_as_uint(As[(mr + 8) * 36 + kk + tid4]);
                af[mi][2] = __float_as_uint(As[mr * 36 + kk + tid4 + 4]);
                af[mi][3] = __float_as_uint(As[(mr + 8) * 36 + kk + tid4 + 4]);
            }
#pragma unroll
            for (int ni = 0; ni < 4; ++ni) {
                int nc = wn + ni * 8 + gid;
                bf[ni][0] = __float_as_uint(Bs[(kk + tid4) * 136 + nc]);
                bf[ni][1] = __float_as_uint(Bs[(kk + tid4 + 4) * 136 + nc]);
            }
#pragma unroll
            for (int mi = 0; mi < 4; ++mi)
#pragma unroll
                for (int ni = 0; ni < 4; ++ni)
                    mma_tf32_16x8x8(d[mi][ni], af[mi], bf[ni]);
        }
    }
#undef ISSUE_STAGE

    float sl[4], ql[4], sh_[4], qh[4];
#pragma unroll
    for (int mi = 0; mi < 4; ++mi) {
        sl[mi] = ql[mi] = sh_[mi] = qh[mi] = 0.f;
        int row = mBase + wm + mi * 16 + gid;
#pragma unroll
        for (int ni = 0; ni < 4; ++ni) {
            int col = nBase + wn + ni * 8 + 2 * tid4;
            sl[mi] += d[mi][ni][0] + d[mi][ni][1];
            ql[mi] += d[mi][ni][0] * d[mi][ni][0] + d[mi][ni][1] * d[mi][ni][1];
            sh_[mi] += d[mi][ni][2] + d[mi][ni][3];
            qh[mi] += d[mi][ni][2] * d[mi][ni][2] + d[mi][ni][3] * d[mi][ni][3];
            *(float2*)&Cp[(size_t)row * N + col] =
                make_float2(d[mi][ni][0], d[mi][ni][1]);
            *(float2*)&Cp[(size_t)(row + 8) * N + col] =
                make_float2(d[mi][ni][2], d[mi][ni][3]);
        }
#pragma unroll
        for (int off = 1; off <= 2; off <<= 1) {
            sl[mi]  += __shfl_xor_sync(0xffffffffu, sl[mi],  off);
            ql[mi]  += __shfl_xor_sync(0xffffffffu, ql[mi],  off);
            sh_[mi] += __shfl_xor_sync(0xffffffffu, sh_[mi], off);
            qh[mi]  += __shfl_xor_sync(0xffffffffu, qh[mi],  off);
        }
    }
    __syncthreads();
    float* pb = sm;
    if (tid4 == 0) {
        int g = wid >> 1;
#pragma unroll
        for (int mi = 0; mi < 4; ++mi) {
            int lr = wm + mi * 16 + gid;
            pb[(g * 128 + lr) * 2 + 0]     = sl[mi];
            pb[(g * 128 + lr) * 2 + 1]     = ql[mi];
            pb[(g * 128 + lr + 8) * 2 + 0] = sh_[mi];
            pb[(g * 128 + lr + 8) * 2 + 1] = qh[mi];
        }
    }
    __syncthreads();
    if (tid < 128) {
        float s = 0.f, q = 0.f;
#pragma unroll
        for (int g = 0; g < 4; ++g) {
            s += pb[(g * 128 + tid) * 2 + 0];
            q += pb[(g * 128 + tid) * 2 + 1];
        }
        int pidx = blockIdx.y * gridDim.z + blockIdx.z;
        part[((size_t)pidx * M + mBase + tid) * 2 + 0] = s;
        part[((size_t)pidx * M + mBase + tid) * 2 + 1] = q;
    }
}

// ---------------- BN finalize ----------------
__global__ void bn_finalize(const float* __restrict__ part,
                            const float* __restrict__ gamma,
                            const float* __restrict__ beta,
                            float* __restrict__ scl, float* __restrict__ shf, int C)
{
    int c = blockIdx.x * 128 + threadIdx.x;
    if (c >= C) return;
    float s = 0.f, q = 0.f;
    for (int p = 0; p < NPARTS; ++p) {
        s += part[((size_t)p * C + c) * 2 + 0];
        q += part[((size_t)p * C + c) * 2 + 1];
    }
    const float invN = 1.f / (NB * NPix);
    float mean = s * invN;
    float var  = q * invN - mean * mean;
    float sc   = gamma[c] * rsqrtf(var + 1e-5f);
    scl[c] = sc;
    shf[c] = beta[c] - mean * sc;
}

// ---------------- fused flash attention (BN algebraically folded) ---------
// smem floats: Ks[32][68] @0 (2176), Vs2 float2[128][34] @2176 (8704 f),
// Ps[128][68] @10880 (8704), Qs aliases Ps, Os[128][132] aliases base.
#define FL_SMEM 78336

__global__ void __launch_bounds__(256) flash_attn(const float* __restrict__ yqkv,
                                                  const float* __restrict__ scl,
                                                  const float* __restrict__ shf,
                                                  float* __restrict__ obuf)
{
    extern __shared__ float fsm[];
    float*  Ks  = fsm;
    float2* Vs2 = (float2*)(fsm + 2176);
    float*  Ps  = fsm + 10880;
    float*  Qs  = Ps;
    float*  Os  = fsm;

    const int bh = blockIdx.y, b = bh >> 3, h = bh & 7;
    const int qBase = blockIdx.x * 128;
    const int tid = threadIdx.x, wid = tid >> 5, lane = tid & 31;
    const int gid = lane >> 2, tid4 = lane & 3;
    const float* base = yqkv + (size_t)b * C_QKV * NPix;

    // Q tile: q'' = (q*scq+shq) * sck * 1/sqrt(dk)  (K's additive BN term is
    // constant per query row -> softmax-invariant -> dropped)
    for (int i = tid; i < 32 * 128; i += 256) {
        int d = i >> 7, q = i & 127;
        int chq = h * 192 + d, chk = chq + DK;
        float fac = scl[chk] * 0.17677669529663687f;
        Qs[d * 136 + q] =
            f2tf((base[(size_t)chq * NPix + qBase + q] * scl[chq] + shf[chq]) * fac);
    }
    __syncthreads();

    uint32_t qf[4][4];
    const int mr = wid * 16 + gid;
#pragma unroll
    for (int ks = 0; ks < 4; ++ks) {
        qf[ks][0] = __float_as_uint(Qs[(ks * 8 + tid4) * 136 + mr]);
        qf[ks][1] = __float_as_uint(Qs[(ks * 8 + tid4) * 136 + mr + 8]);
        qf[ks][2] = __float_as_uint(Qs[(ks * 8 + tid4 + 4) * 136 + mr]);
        qf[ks][3] = __float_as_uint(Qs[(ks * 8 + tid4 + 4) * 136 + mr + 8]);
    }
    __syncthreads();

    float o[16][4];
#pragma unroll
    for (int nt = 0; nt < 16; ++nt)
#pragma unroll
        for (int r = 0; r < 4; ++r) o[nt][r] = 0.f;
    float m0 = -1e30f, m1 = -1e30f, l0 = 0.f, l1 = 0.f;

    for (int k0 = 0; k0 < NPix; k0 += 64) {
        // K tile: RAW copy [d][68]
        for (int i = tid; i < 32 * 16; i += 256) {
            int d = i >> 4, k4 = (i & 15) << 2;
            int ch = h * 192 + DK + d;
            *(float4*)&Ks[d * 68 + k4] =
                *(const float4*)&base[(size_t)ch * NPix + k0 + k4];
        }
        // V tile: RAW copy into (k, k+4) float2 pairs: Vs2[dv][k8*4+j]
        for (int i = tid; i < 1024; i += 256) {
            int k8 = i & 7, dv = i >> 3;
            int ch = h * 192 + 2 * DK + dv;
            const float* vp = &base[(size_t)ch * NPix + k0 + k8 * 8];
            float4 a = *(const float4*)vp;
            float4 c = *(const float4*)(vp + 4);
            float2* dst = &Vs2[dv * 34 + k8 * 4];
            dst[0] = make_float2(a.x, c.x);
            dst[1] = make_float2(a.y, c.y);
            dst[2] = make_float2(a.z, c.z);
            dst[3] = make_float2(a.w, c.w);
        }
        __syncthreads();

        // S = Q'' . K_raw
        float s[8][4];
#pragma unroll
        for (int ni = 0; ni < 8; ++ni)
#pragma unroll
            for (int r = 0; r < 4; ++r) s[ni][r] = 0.f;
#pragma unroll
        for (int ks = 0; ks < 4; ++ks) {
#pragma unroll
            for (int ni = 0; ni < 8; ++ni) {
                uint32_t bf[2];
                bf[0] = __float_as_uint(Ks[(ks * 8 + tid4) * 68 + ni * 8 + gid]);
                bf[1] = __float_as_uint(Ks[(ks * 8 + tid4 + 4) * 68 + ni * 8 + gid]);
                mma_tf32_16x8x8(s[ni], qf[ks], bf);
            }
        }

        float t0 = -1e30f, t1 = -1e30f;
#pragma unroll
        for (int ni = 0; ni < 8; ++ni) {
            t0 = fmaxf(t0, fmaxf(s[ni][0], s[ni][1]));
            t1 = fmaxf(t1, fmaxf(s[ni][2], s[ni][3]));
        }
        t0 = fmaxf(t0, __shfl_xor_sync(0xffffffffu, t0, 1));
        t0 = fmaxf(t0, __shfl_xor_sync(0xffffffffu, t0, 2));
        t1 = fmaxf(t1, __shfl_xor_sync(0xffffffffu, t1, 1));
        t1 = fmaxf(t1, __shfl_xor_sync(0xffffffffu, t1, 2));
        float mn0 = fmaxf(m0, t0), mn1 = fmaxf(m1, t1);
        float a0 = __expf(m0 - mn0), a1 = __expf(m1 - mn1);
        m0 = mn0; m1 = mn1;

        float ps0 = 0.f, ps1 = 0.f;
#pragma unroll
        for (int ni = 0; ni < 8; ++ni) {
            s[ni][0] = __expf(s[ni][0] - mn0);
            s[ni][1] = __expf(s[ni][1] - mn0);
            s[ni][2] = __expf(s[ni][2] - mn1);
            s[ni][3] = __expf(s[ni][3] - mn1);
            ps0 += s[ni][0] + s[ni][1];
            ps1 += s[ni][2] + s[ni][3];
        }
        ps0 += __shfl_xor_sync(0xffffffffu, ps0, 1);
        ps0 += __shfl_xor_sync(0xffffffffu, ps0, 2);
        ps1 += __shfl_xor_sync(0xffffffffu, ps1, 1);
        ps1 += __shfl_xor_sync(0xffffffffu, ps1, 2);
        l0 = l0 * a0 + ps0;
        l1 = l1 * a1 + ps1;

#pragma unroll
        for (int nt = 0; nt < 16; ++nt) {
            o[nt][0] *= a0; o[nt][1] *= a0;
            o[nt][2] *= a1; o[nt][3] *= a1;
        }

#pragma unroll
        for (int ni = 0; ni < 8; ++ni) {
            Ps[(wid * 16 + gid) * 68 + ni * 8 + 2 * tid4]         = s[ni][0];
            Ps[(wid * 16 + gid) * 68 + ni * 8 + 2 * tid4 + 1]     = s[ni][1];
            Ps[(wid * 16 + gid + 8) * 68 + ni * 8 + 2 * tid4]     = s[ni][2];
            Ps[(wid * 16 + gid + 8) * 68 + ni * 8 + 2 * tid4 + 1] = s[ni][3];
        }
        __syncwarp();

        // O_raw += P . V_raw (paired 64-bit V fragment loads)
#pragma unroll
        for (int kk = 0; kk < 8; ++kk) {
            uint32_t pf[4];
            pf[0] = __float_as_uint(Ps[(wid * 16 + gid) * 68 + kk * 8 + tid4]);
            pf[1] = __float_as_uint(Ps[(wid * 16 + gid + 8) * 68 + kk * 8 + tid4]);
            pf[2] = __float_as_uint(Ps[(wid * 16 + gid) * 68 + kk * 8 + tid4 + 4]);
            pf[3] = __float_as_uint(Ps[(wid * 16 + gid + 8) * 68 + kk * 8 + tid4 + 4]);
#pragma unroll
            for (int nt = 0; nt < 16; ++nt) {
                float2 vv = Vs2[(nt * 8 + gid) * 34 + kk * 4 + tid4];
                uint32_t vf[2] = { __float_as_uint(vv.x), __float_as_uint(vv.y) };
                mma_tf32_16x8x8(o[nt], pf, vf);
            }
        }
        __syncthreads();
    }

    // normalize (raw) + transpose; V's BN applied in final write
    float inv0 = 1.f / l0, inv1 = 1.f / l1;
    __syncthreads();
#pragma unroll
    for (int nt = 0; nt < 16; ++nt) {
        int dv = nt * 8 + 2 * tid4;
        int q  = wid * 16 + gid;
        Os[(size_t)dv * 132 + q]           = o[nt][0] * inv0;
        Os[(size_t)(dv + 1) * 132 + q]     = o[nt][1] * inv0;
        Os[(size_t)dv * 132 + q + 8]       = o[nt][2] * inv1;
        Os[(size_t)(dv + 1) * 132 + q + 8] = o[nt][3] * inv1;
    }
    __syncthreads();
    for (int i = tid; i < 128 * 32; i += 256) {
        int dv = i >> 5, q4 = (i & 31) << 2;
        int chv = h * 192 + 2 * DK + dv;
        float sc = scl[chv], sh = shf[chv];
        int ch = b * 1024 + h * 128 + dv;
        float4 v = *(float4*)&Os[dv * 132 + q4];
        v.x = gelu_exact(v.x * sc + sh); v.y = gelu_exact(v.y * sc + sh);
        v.z = gelu_exact(v.z * sc + sh); v.w = gelu_exact(v.w * sc + sh);
        *(float4*)&obuf[(size_t)ch * NPix + qBase + q4] = v;
    }
}

// ---------------- elementwise (float4) ----------------
__global__ void resadd_bn(const float* __restrict__ x, const float* __restrict__ y,
                          const float* __restrict__ scl, const float* __restrict__ shf,
                          float* __restrict__ o, int C, int total4)
{
    int i = blockIdx.x * 256 + threadIdx.x;
    if (i >= total4) return;
    int ch = (i >> 8) % C;
    float sc = scl[ch], sh = shf[ch];
    float4 a = ((const float4*)x)[i];
    float4 c = ((const float4*)y)[i];
    a.x += c.x * sc + sh; a.y += c.y * sc + sh;
    a.z += c.z * sc + sh; a.w += c.w * sc + sh;
    ((float4*)o)[i] = a;
}
__global__ void bn_gelu_inplace(float* __restrict__ y,
                                const float* __restrict__ scl,
                                const float* __restrict__ shf, int C, int total4)
{
    int i = blockIdx.x * 256 + threadIdx.x;
    if (i >= total4) return;
    int ch = (i >> 8) % C;
    float sc = scl[ch], sh = shf[ch];
    float4 v = ((float4*)y)[i];
    v.x = gelu_exact(v.x * sc + sh); v.y = gelu_exact(v.y * sc + sh);
    v.z = gelu_exact(v.z * sc + sh); v.w = gelu_exact(v.w * sc + sh);
    ((float4*)y)[i] = v;
}

// ---------------- host ----------------
extern "C" void kernel_launch(void* const* d_in, const int* in_sizes, int n_in,
                              void* d_out, int out_size)
{
    const float* x       = (const float*)d_in[0];
    const float* w_qkv   = (const float*)d_in[1];
    const float* gq      = (const float*)d_in[2];
    const float* bq      = (const float*)d_in[3];
    const float* w_merge = (const float*)d_in[4];
    const float* gm      = (const float*)d_in[5];
    const float* bm      = (const float*)d_in[6];
    const float* w_fc1   = (const float*)d_in[7];
    const float* g1      = (const float*)d_in[8];
    const float* b1      = (const float*)d_in[9];
    const float* w_fc2   = (const float*)d_in[10];
    const float* g2      = (const float*)d_in[11];
    const float* b2      = (const float*)d_in[12];
    float* out = (float*)d_out;

    float *yqkv, *obuf, *y2, *xr, *h1, *y3, *part;
    float *scq, *shq, *scm, *shm, *sc1, *sh1, *sc2, *sh2;
    float *wq, *wm, *w1, *w2;
    cudaGetSymbolAddress((void**)&yqkv, g_yqkv);
    cudaGetSymbolAddress((void**)&obuf, g_obuf);
    cudaGetSymbolAddress((void**)&y2,   g_y2);
    cudaGetSymbolAddress((void**)&xr,   g_xr);
    cudaGetSymbolAddress((void**)&h1,   g_h1);
    cudaGetSymbolAddress((void**)&y3,   g_y3);
    cudaGetSymbolAddress((void**)&part, g_part);
    cudaGetSymbolAddress((void**)&scq, g_sc_qkv);
    cudaGetSymbolAddress((void**)&shq, g_sh_qkv);
    cudaGetSymbolAddress((void**)&scm, g_sc_mg);
    cudaGetSymbolAddress((void**)&shm, g_sh_mg);
    cudaGetSymbolAddress((void**)&sc1, g_sc_f1);
    cudaGetSymbolAddress((void**)&sh1, g_sh_f1);
    cudaGetSymbolAddress((void**)&sc2, g_sc_f2);
    cudaGetSymbolAddress((void**)&sh2, g_sh_f2);
    cudaGetSymbolAddress((void**)&wq, g_wq);
    cudaGetSymbolAddress((void**)&wm, g_wm);
    cudaGetSymbolAddress((void**)&w1, g_w1);
    cudaGetSymbolAddress((void**)&w2, g_w2);

    cudaFuncSetAttribute(tf32_gemm, cudaFuncAttributeMaxDynamicSharedMemorySize, GEMM_SMEM);
    cudaFuncSetAttribute(flash_attn, cudaFuncAttributeMaxDynamicSharedMemorySize, FL_SMEM);

    round_all<<<1536, 256>>>(w_qkv, wq, w_merge, wm, w_fc1, w1, w_fc2, w2);

    tf32_gemm<<<dim3(C_QKV/128, NPix/128, NB), 256, GEMM_SMEM>>>(wq, x, yqkv, part, C_QKV, NPix, C_IN);
    bn_finalize<<<(C_QKV + 127) / 128, 128>>>(part, gq, bq, scq, shq, C_QKV);
    flash_attn<<<dim3(8, 64), 256, FL_SMEM>>>(yqkv, scq, shq, obuf);
    tf32_gemm<<<dim3(C_MG/128, NPix/128, NB), 256, GEMM_SMEM>>>(wm, obuf, y2, part, C_MG, NPix, 1024);
    bn_finalize<<<(C_MG + 127) / 128, 128>>>(part, gm, bm, scm, shm, C_MG);
    resadd_bn<<<(NB * C_IN * NPix / 4 + 255) / 256, 256>>>(x, y2, scm, shm, xr, C_MG, NB * C_IN * NPix / 4);
    tf32_gemm<<<dim3(C_F1/128, NPix/128, NB), 256, GEMM_SMEM>>>(w1, xr, h1, part, C_F1, NPix, C_IN);
    bn_finalize<<<(C_F1 + 127) / 128, 128>>>(part, g1, b1, sc1, sh1, C_F1);
    bn_gelu_inplace<<<(NB * C_F1 * NPix / 4 + 255) / 256, 256>>>(h1, sc1, sh1, C_F1, NB * C_F1 * NPix / 4);
    tf32_gemm<<<dim3(C_F2/128, NPix/128, NB), 256, GEMM_SMEM>>>(w2, h1, y3, part, C_F2, NPix, C_F1);
    bn_finalize<<<(C_F2 + 127) / 128, 128>>>(part, g2, b2, sc2, sh2, C_F2);
    resadd_bn<<<(NB * C_F2 * NPix / 4 + 255) / 256, 256>>>(xr, y3, sc2, sh2, out, C_F2, NB * C_F2 * NPix / 4);
}

// round 11
// speedup vs baseline: 3.5349x; 1.3244x over previous
#include <cuda_runtime.h>
#include <cstdint>
#include <math.h>

#define NB    8
#define NPix  1024
#define C_IN  384
#define C_QKV 1536
#define C_MG  384
#define C_F1  768
#define C_F2  384
#define DK    32
#define DV    128
#define NPARTS 64

__device__ float g_yqkv[NB * C_QKV * NPix];
__device__ float g_obuf[NB * 1024 * NPix];
__device__ float g_y2  [NB * C_MG * NPix];
__device__ float g_xr  [NB * C_IN * NPix];
__device__ float g_h1  [NB * C_F1 * NPix];
__device__ float g_y3  [NB * C_F2 * NPix];
__device__ float g_part[NPARTS * C_QKV * 2];
__device__ float g_sc_qkv[C_QKV], g_sh_qkv[C_QKV];
__device__ float g_sc_mg [C_MG ], g_sh_mg [C_MG ];
__device__ float g_sc_f1 [C_F1 ], g_sh_f1 [C_F1 ];
__device__ float g_sc_f2 [C_F2 ], g_sh_f2 [C_F2 ];
__device__ float g_wq[C_QKV * C_IN];
__device__ float g_wm[C_MG * 1024];
__device__ float g_w1[C_F1 * C_IN];
__device__ float g_w2[C_F2 * C_F1];

__device__ __forceinline__ float gelu_exact(float v) { return v * normcdff(v); }

__device__ __forceinline__ float f2tf(float f) {
    uint32_t r;
    asm("cvt.rna.tf32.f32 %0, %1;" : "=r"(r) : "f"(f));
    return __uint_as_float(r);
}

__device__ __forceinline__ void mma_tf32_16x8x8(float d[4],
                                                const uint32_t a[4],
                                                const uint32_t b[2])
{
    asm volatile(
        "mma.sync.aligned.m16n8k8.row.col.f32.tf32.tf32.f32 "
        "{%0,%1,%2,%3}, {%4,%5,%6,%7}, {%8,%9}, {%0,%1,%2,%3};"
        : "+f"(d[0]), "+f"(d[1]), "+f"(d[2]), "+f"(d[3])
        : "r"(a[0]), "r"(a[1]), "r"(a[2]), "r"(a[3]), "r"(b[0]), "r"(b[1]));
}

__device__ __forceinline__ void cp16(uint32_t saddr, const void* gptr) {
    asm volatile("cp.async.cg.shared.global [%0], [%1], 16;" :: "r"(saddr), "l"(gptr));
}
#define CP_COMMIT asm volatile("cp.async.commit_group;" ::: "memory")
#define CP_WAIT1  asm volatile("cp.async.wait_group 1;" ::: "memory")
#define CP_WAIT0  asm volatile("cp.async.wait_group 0;" ::: "memory")

// ---------------- weight pre-rounding (single launch) ----------------
__global__ void round_all(const float* __restrict__ w0, float* __restrict__ o0,
                          const float* __restrict__ w1, float* __restrict__ o1,
                          const float* __restrict__ w2, float* __restrict__ o2,
                          const float* __restrict__ w3, float* __restrict__ o3)
{
    int i = blockIdx.x * 256 + threadIdx.x;
    const float* w; float* o; int j = i;
    if (j < 147456)                 { w = w0; o = o0; }
    else if ((j -= 147456) < 98304) { w = w1; o = o1; }
    else if ((j -=  98304) < 73728) { w = w2; o = o2; }
    else                            { j -= 73728; w = w3; o = o3; }
    float4 v = ((const float4*)w)[j];
    v.x = f2tf(v.x); v.y = f2tf(v.y); v.z = f2tf(v.z); v.w = f2tf(v.w);
    ((float4*)o)[j] = v;
}

// ---------------- tf32 GEMM + fused BN partial stats ----------------------
#define STG_F 8960
#define STG_B 35840
#define GEMM_SMEM (3 * STG_B)

__global__ void __launch_bounds__(256, 2) tf32_gemm(const float* __restrict__ A,
                                                    const float* __restrict__ Bg,
                                                    float* __restrict__ Cg,
                                                    float* __restrict__ part,
                                                    int M, int N, int K)
{
    extern __shared__ float sm[];
    const uint32_t sbase = (uint32_t)__cvta_generic_to_shared(sm);

    const int tid  = threadIdx.x;
    const int wid  = tid >> 5;
    const int lane = tid & 31;
    const int gid  = lane >> 2;
    const int tid4 = lane & 3;
    const int wm   = (wid & 1) * 64;
    const int wn   = (wid >> 1) * 32;

    const int mBase = blockIdx.x * 128, nBase = blockIdx.y * 128;
    const float* Bp = Bg + (size_t)blockIdx.z * K * N;
    float*       Cp = Cg + (size_t)blockIdx.z * M * N;

    const int nst = K >> 5;

#define ISSUE_STAGE(s_) do {                                                   \
        int _s = (s_);                                                         \
        uint32_t sa = sbase + (_s % 3) * STG_B;                                \
        uint32_t sb2 = sa + 18432;                                             \
        int _k0 = _s << 5;                                                     \
        _Pragma("unroll")                                                      \
        for (int t = 0; t < 4; ++t) {                                          \
            int c = tid + t * 256;                                             \
            int m = c >> 3, j = c & 7;                                         \
            cp16(sa + m * 144 + j * 16,                                        \
                 &A[(size_t)(mBase + m) * K + _k0 + (j << 2)]);                \
        }                                                                      \
        _Pragma("unroll")                                                      \
        for (int t = 0; t < 4; ++t) {                                          \
            int c = tid + t * 256;                                             \
            int k = c >> 5, j = c & 31;                                        \
            cp16(sb2 + k * 544 + j * 16,                                       \
                 &Bp[(size_t)(_k0 + k) * N + nBase + (j << 2)]);               \
        }                                                                      \
    } while (0)

    float d[4][4][4];
#pragma unroll
    for (int mi = 0; mi < 4; ++mi)
#pragma unroll
        for (int ni = 0; ni < 4; ++ni)
#pragma unroll
            for (int r = 0; r < 4; ++r) d[mi][ni][r] = 0.f;

    ISSUE_STAGE(0); CP_COMMIT;
    ISSUE_STAGE(1); CP_COMMIT;

    for (int s = 0; s < nst; ++s) {
        CP_WAIT1;
        __syncthreads();
        if (s + 2 < nst) ISSUE_STAGE(s + 2);
        CP_COMMIT;

        const float* As = sm + (s % 3) * STG_F;
        const float* Bs = As + 4608;

#pragma unroll
        for (int kk = 0; kk < 32; kk += 8) {
            uint32_t af[4][4], bf[4][2];
#pragma unroll
            for (int mi = 0; mi < 4; ++mi) {
                int mr = wm + mi * 16 + gid;
                af[mi][0] = __float_as_uint(As[mr * 36 + kk + tid4]);
                af[mi][1] = __float_as_uint(As[(mr + 8) * 36 + kk + tid4]);
                af[mi][2] = __float_as_uint(As[mr * 36 + kk + tid4 + 4]);
                af[mi][3] = __float_as_uint(As[(mr + 8) * 36 + kk + tid4 + 4]);
            }
#pragma unroll
            for (int ni = 0; ni < 4; ++ni) {
                int nc = wn + ni * 8 + gid;
                bf[ni][0] = __float_as_uint(Bs[(kk + tid4) * 136 + nc]);
                bf[ni][1] = __float_as_uint(Bs[(kk + tid4 + 4) * 136 + nc]);
            }
#pragma unroll
            for (int mi = 0; mi < 4; ++mi)
#pragma unroll
                for (int ni = 0; ni < 4; ++ni)
                    mma_tf32_16x8x8(d[mi][ni], af[mi], bf[ni]);
        }
    }
#undef ISSUE_STAGE

    float sl[4], ql[4], sh_[4], qh[4];
#pragma unroll
    for (int mi = 0; mi < 4; ++mi) {
        sl[mi] = ql[mi] = sh_[mi] = qh[mi] = 0.f;
        int row = mBase + wm + mi * 16 + gid;
#pragma unroll
        for (int ni = 0; ni < 4; ++ni) {
            int col = nBase + wn + ni * 8 + 2 * tid4;
            sl[mi] += d[mi][ni][0] + d[mi][ni][1];
            ql[mi] += d[mi][ni][0] * d[mi][ni][0] + d[mi][ni][1] * d[mi][ni][1];
            sh_[mi] += d[mi][ni][2] + d[mi][ni][3];
            qh[mi] += d[mi][ni][2] * d[mi][ni][2] + d[mi][ni][3] * d[mi][ni][3];
            *(float2*)&Cp[(size_t)row * N + col] =
                make_float2(d[mi][ni][0], d[mi][ni][1]);
            *(float2*)&Cp[(size_t)(row + 8) * N + col] =
                make_float2(d[mi][ni][2], d[mi][ni][3]);
        }
#pragma unroll
        for (int off = 1; off <= 2; off <<= 1) {
            sl[mi]  += __shfl_xor_sync(0xffffffffu, sl[mi],  off);
            ql[mi]  += __shfl_xor_sync(0xffffffffu, ql[mi],  off);
            sh_[mi] += __shfl_xor_sync(0xffffffffu, sh_[mi], off);
            qh[mi]  += __shfl_xor_sync(0xffffffffu, qh[mi],  off);
        }
    }
    __syncthreads();
    float* pb = sm;
    if (tid4 == 0) {
        int g = wid >> 1;
#pragma unroll
        for (int mi = 0; mi < 4; ++mi) {
            int lr = wm + mi * 16 + gid;
            pb[(g * 128 + lr) * 2 + 0]     = sl[mi];
            pb[(g * 128 + lr) * 2 + 1]     = ql[mi];
            pb[(g * 128 + lr + 8) * 2 + 0] = sh_[mi];
            pb[(g * 128 + lr + 8) * 2 + 1] = qh[mi];
        }
    }
    __syncthreads();
    if (tid < 128) {
        float s = 0.f, q = 0.f;
#pragma unroll
        for (int g = 0; g < 4; ++g) {
            s += pb[(g * 128 + tid) * 2 + 0];
            q += pb[(g * 128 + tid) * 2 + 1];
        }
        int pidx = blockIdx.y * gridDim.z + blockIdx.z;
        part[((size_t)pidx * M + mBase + tid) * 2 + 0] = s;
        part[((size_t)pidx * M + mBase + tid) * 2 + 1] = q;
    }
}

// ---------------- BN finalize ----------------
__global__ void bn_finalize(const float* __restrict__ part,
                            const float* __restrict__ gamma,
                            const float* __restrict__ beta,
                            float* __restrict__ scl, float* __restrict__ shf, int C)
{
    int c = blockIdx.x * 128 + threadIdx.x;
    if (c >= C) return;
    float s = 0.f, q = 0.f;
    for (int p = 0; p < NPARTS; ++p) {
        s += part[((size_t)p * C + c) * 2 + 0];
        q += part[((size_t)p * C + c) * 2 + 1];
    }
    const float invN = 1.f / (NB * NPix);
    float mean = s * invN;
    float var  = q * invN - mean * mean;
    float sc   = gamma[c] * rsqrtf(var + 1e-5f);
    scl[c] = sc;
    shf[c] = beta[c] - mean * sc;
}

// ---------------- flash attention: cp.async double-buffered K/V -----------
// smem floats: stage s (s=0,1): Ks_s @ s*10880 [32][68], Vs_s @ +2176 [128][68]
// Ps @21760 [128][68] (Qs aliases Ps), Os [128][132] aliases @0.
#define FL_STG_F 10880
#define FL_SMEM  ((2 * FL_STG_F + 8704) * 4)

__global__ void __launch_bounds__(256) flash_attn(const float* __restrict__ yqkv,
                                                  const float* __restrict__ scl,
                                                  const float* __restrict__ shf,
                                                  float* __restrict__ obuf)
{
    extern __shared__ float fsm[];
    const uint32_t sbase = (uint32_t)__cvta_generic_to_shared(fsm);
    float* Ps = fsm + 2 * FL_STG_F;
    float* Qs = Ps;
    float* Os = fsm;

    const int bh = blockIdx.y, b = bh >> 3, h = bh & 7;
    const int qBase = blockIdx.x * 128;
    const int tid = threadIdx.x, wid = tid >> 5, lane = tid & 31;
    const int gid = lane >> 2, tid4 = lane & 3;
    const float* base = yqkv + (size_t)b * C_QKV * NPix;
    const float* kvbase = base + (size_t)(h * 192 + DK) * NPix;   // K rows then V rows

    // Q tile: q'' = (q*scq+shq) * sck / sqrt(dk); K's additive BN term is
    // softmax-invariant and dropped; V's BN applied in epilogue.
    for (int i = tid; i < 32 * 128; i += 256) {
        int d = i >> 7, q = i & 127;
        int chq = h * 192 + d, chk = chq + DK;
        float fac = scl[chk] * 0.17677669529663687f;
        Qs[d * 136 + q] =
            f2tf((base[(size_t)chq * NPix + qBase + q] * scl[chq] + shf[chq]) * fac);
    }
    __syncthreads();

    uint32_t qf[4][4];
    const int mr = wid * 16 + gid;
#pragma unroll
    for (int ks = 0; ks < 4; ++ks) {
        qf[ks][0] = __float_as_uint(Qs[(ks * 8 + tid4) * 136 + mr]);
        qf[ks][1] = __float_as_uint(Qs[(ks * 8 + tid4) * 136 + mr + 8]);
        qf[ks][2] = __float_as_uint(Qs[(ks * 8 + tid4 + 4) * 136 + mr]);
        qf[ks][3] = __float_as_uint(Qs[(ks * 8 + tid4 + 4) * 136 + mr + 8]);
    }

    // cp.async staging: 160 rows (32 K + 128 V) x 64 floats = 2560 16B chunks
    // = exactly 10 chunks per thread. Row r: 16 chunks (j = 0..15).
#define FL_ISSUE(i_) do {                                                      \
        int _k0 = (i_) << 6;                                                   \
        uint32_t sa = sbase + ((i_) & 1) * (FL_STG_F * 4);                     \
        _Pragma("unroll")                                                      \
        for (int t = 0; t < 10; ++t) {                                         \
            int c = tid + t * 256;                                             \
            int r = c >> 4, j = c & 15;                                        \
            cp16(sa + r * 272 + j * 16,                                        \
                 &kvbase[(size_t)r * NPix + _k0 + (j << 2)]);                  \
        }                                                                      \
    } while (0)

    float o[16][4];
#pragma unroll
    for (int nt = 0; nt < 16; ++nt)
#pragma unroll
        for (int r = 0; r < 4; ++r) o[nt][r] = 0.f;
    float m0 = -1e30f, m1 = -1e30f, l0 = 0.f, l1 = 0.f;

    FL_ISSUE(0); CP_COMMIT;

    for (int it = 0; it < 16; ++it) {
        __syncthreads();                 // all warps done with buffer (it+1)&1
        if (it + 1 < 16) { FL_ISSUE(it + 1); CP_COMMIT; CP_WAIT1; }
        else             { CP_WAIT0; }
        __syncthreads();                 // tile it visible to all

        const float* Ks = fsm + (it & 1) * FL_STG_F;        // [32][68]
        const float* Vs = Ks + 2176;                        // [128][68]

        // S = Q'' . K_raw
        float s[8][4];
#pragma unroll
        for (int ni = 0; ni < 8; ++ni)
#pragma unroll
            for (int r = 0; r < 4; ++r) s[ni][r] = 0.f;
#pragma unroll
        for (int ks = 0; ks < 4; ++ks) {
#pragma unroll
            for (int ni = 0; ni < 8; ++ni) {
                uint32_t bf[2];
                bf[0] = __float_as_uint(Ks[(ks * 8 + tid4) * 68 + ni * 8 + gid]);
                bf[1] = __float_as_uint(Ks[(ks * 8 + tid4 + 4) * 68 + ni * 8 + gid]);
                mma_tf32_16x8x8(s[ni], qf[ks], bf);
            }
        }

        float t0 = -1e30f, t1 = -1e30f;
#pragma unroll
        for (int ni = 0; ni < 8; ++ni) {
            t0 = fmaxf(t0, fmaxf(s[ni][0], s[ni][1]));
            t1 = fmaxf(t1, fmaxf(s[ni][2], s[ni][3]));
        }
        t0 = fmaxf(t0, __shfl_xor_sync(0xffffffffu, t0, 1));
        t0 = fmaxf(t0, __shfl_xor_sync(0xffffffffu, t0, 2));
        t1 = fmaxf(t1, __shfl_xor_sync(0xffffffffu, t1, 1));
        t1 = fmaxf(t1, __shfl_xor_sync(0xffffffffu, t1, 2));
        float mn0 = fmaxf(m0, t0), mn1 = fmaxf(m1, t1);
        float a0 = __expf(m0 - mn0), a1 = __expf(m1 - mn1);
        m0 = mn0; m1 = mn1;

        float ps0 = 0.f, ps1 = 0.f;
#pragma unroll
        for (int ni = 0; ni < 8; ++ni) {
            s[ni][0] = __expf(s[ni][0] - mn0);
            s[ni][1] = __expf(s[ni][1] - mn0);
            s[ni][2] = __expf(s[ni][2] - mn1);
            s[ni][3] = __expf(s[ni][3] - mn1);
            ps0 += s[ni][0] + s[ni][1];
            ps1 += s[ni][2] + s[ni][3];
        }
        ps0 += __shfl_xor_sync(0xffffffffu, ps0, 1);
        ps0 += __shfl_xor_sync(0xffffffffu, ps0, 2);
        ps1 += __shfl_xor_sync(0xffffffffu, ps1, 1);
        ps1 += __shfl_xor_sync(0xffffffffu, ps1, 2);
        l0 = l0 * a0 + ps0;
        l1 = l1 * a1 + ps1;

#pragma unroll
        for (int nt = 0; nt < 16; ++nt) {
            o[nt][0] *= a0; o[nt][1] *= a0;
            o[nt][2] *= a1; o[nt][3] *= a1;
        }

#pragma unroll
        for (int ni = 0; ni < 8; ++ni) {
            *(float2*)&Ps[(wid * 16 + gid) * 68 + ni * 8 + 2 * tid4] =
                make_float2(s[ni][0], s[ni][1]);
            *(float2*)&Ps[(wid * 16 + gid + 8) * 68 + ni * 8 + 2 * tid4] =
                make_float2(s[ni][2], s[ni][3]);
        }
        __syncwarp();

        // O_raw += P . V_raw  (B operand directly from [dv][k] rows)
#pragma unroll
        for (int kk = 0; kk < 8; ++kk) {
            uint32_t pf[4];
            pf[0] = __float_as_uint(Ps[(wid * 16 + gid) * 68 + kk * 8 + tid4]);
            pf[1] = __float_as_uint(Ps[(wid * 16 + gid + 8) * 68 + kk * 8 + tid4]);
            pf[2] = __float_as_uint(Ps[(wid * 16 + gid) * 68 + kk * 8 + tid4 + 4]);
            pf[3] = __float_as_uint(Ps[(wid * 16 + gid + 8) * 68 + kk * 8 + tid4 + 4]);
#pragma unroll
            for (int nt = 0; nt < 16; ++nt) {
                uint32_t vf[2];
                vf[0] = __float_as_uint(Vs[(nt * 8 + gid) * 68 + kk * 8 + tid4]);
                vf[1] = __float_as_uint(Vs[(nt * 8 + gid) * 68 + kk * 8 + tid4 + 4]);
                mma_tf32_16x8x8(o[nt], pf, vf);
            }
        }
    }
#undef FL_ISSUE

    // normalize + transpose; V's BN applied on final write
    float inv0 = 1.f / l0, inv1 = 1.f / l1;
    __syncthreads();
#pragma unroll
    for (int nt = 0; nt < 16; ++nt) {
        int dv = nt * 8 + 2 * tid4;
        int q  = wid * 16 + gid;
        Os[(size_t)dv * 132 + q]           = o[nt][0] * inv0;
        Os[(size_t)(dv + 1) * 132 + q]     = o[nt][1] * inv0;
        Os[(size_t)dv * 132 + q + 8]       = o[nt][2] * inv1;
        Os[(size_t)(dv + 1) * 132 + q + 8] = o[nt][3] * inv1;
    }
    __syncthreads();
    for (int i = tid; i < 128 * 32; i += 256) {
        int dv = i >> 5, q4 = (i & 31) << 2;
        int chv = h * 192 + 2 * DK + dv;
        float sc = scl[chv], sh = shf[chv];
        int ch = b * 1024 + h * 128 + dv;
        float4 v = *(float4*)&Os[dv * 132 + q4];
        v.x = gelu_exact(v.x * sc + sh); v.y = gelu_exact(v.y * sc + sh);
        v.z = gelu_exact(v.z * sc + sh); v.w = gelu_exact(v.w * sc + sh);
        *(float4*)&obuf[(size_t)ch * NPix + qBase + q4] = v;
    }
}

// ---------------- elementwise (float4) ----------------
__global__ void resadd_bn(const float* __restrict__ x, const float* __restrict__ y,
                          const float* __restrict__ scl, const float* __restrict__ shf,
                          float* __restrict__ o, int C, int total4)
{
    int i = blockIdx.x * 256 + threadIdx.x;
    if (i >= total4) return;
    int ch = (i >> 8) % C;
    float sc = scl[ch], sh = shf[ch];
    float4 a = ((const float4*)x)[i];
    float4 c = ((const float4*)y)[i];
    a.x += c.x * sc + sh; a.y += c.y * sc + sh;
    a.z += c.z * sc + sh; a.w += c.w * sc + sh;
    ((float4*)o)[i] = a;
}
__global__ void bn_gelu_inplace(float* __restrict__ y,
                                const float* __restrict__ scl,
                                const float* __restrict__ shf, int C, int total4)
{
    int i = blockIdx.x * 256 + threadIdx.x;
    if (i >= total4) return;
    int ch = (i >> 8) % C;
    float sc = scl[ch], sh = shf[ch];
    float4 v = ((float4*)y)[i];
    v.x = gelu_exact(v.x * sc + sh); v.y = gelu_exact(v.y * sc + sh);
    v.z = gelu_exact(v.z * sc + sh); v.w = gelu_exact(v.w * sc + sh);
    ((float4*)y)[i] = v;
}

// ---------------- host ----------------
extern "C" void kernel_launch(void* const* d_in, const int* in_sizes, int n_in,
                              void* d_out, int out_size)
{
    const float* x       = (const float*)d_in[0];
    const float* w_qkv   = (const float*)d_in[1];
    const float* gq      = (const float*)d_in[2];
    const float* bq      = (const float*)d_in[3];
    const float* w_merge = (const float*)d_in[4];
    const float* gm      = (const float*)d_in[5];
    const float* bm      = (const float*)d_in[6];
    const float* w_fc1   = (const float*)d_in[7];
    const float* g1      = (const float*)d_in[8];
    const float* b1      = (const float*)d_in[9];
    const float* w_fc2   = (const float*)d_in[10];
    const float* g2      = (const float*)d_in[11];
    const float* b2      = (const float*)d_in[12];
    float* out = (float*)d_out;

    float *yqkv, *obuf, *y2, *xr, *h1, *y3, *part;
    float *scq, *shq, *scm, *shm, *sc1, *sh1, *sc2, *sh2;
    float *wq, *wm, *w1, *w2;
    cudaGetSymbolAddress((void**)&yqkv, g_yqkv);
    cudaGetSymbolAddress((void**)&obuf, g_obuf);
    cudaGetSymbolAddress((void**)&y2,   g_y2);
    cudaGetSymbolAddress((void**)&xr,   g_xr);
    cudaGetSymbolAddress((void**)&h1,   g_h1);
    cudaGetSymbolAddress((void**)&y3,   g_y3);
    cudaGetSymbolAddress((void**)&part, g_part);
    cudaGetSymbolAddress((void**)&scq, g_sc_qkv);
    cudaGetSymbolAddress((void**)&shq, g_sh_qkv);
    cudaGetSymbolAddress((void**)&scm, g_sc_mg);
    cudaGetSymbolAddress((void**)&shm, g_sh_mg);
    cudaGetSymbolAddress((void**)&sc1, g_sc_f1);
    cudaGetSymbolAddress((void**)&sh1, g_sh_f1);
    cudaGetSymbolAddress((void**)&sc2, g_sc_f2);
    cudaGetSymbolAddress((void**)&sh2, g_sh_f2);
    cudaGetSymbolAddress((void**)&wq, g_wq);
    cudaGetSymbolAddress((void**)&wm, g_wm);
    cudaGetSymbolAddress((void**)&w1, g_w1);
    cudaGetSymbolAddress((void**)&w2, g_w2);

    cudaFuncSetAttribute(tf32_gemm, cudaFuncAttributeMaxDynamicSharedMemorySize, GEMM_SMEM);
    cudaFuncSetAttribute(flash_attn, cudaFuncAttributeMaxDynamicSharedMemorySize, FL_SMEM);

    round_all<<<1536, 256>>>(w_qkv, wq, w_merge, wm, w_fc1, w1, w_fc2, w2);

    tf32_gemm<<<dim3(C_QKV/128, NPix/128, NB), 256, GEMM_SMEM>>>(wq, x, yqkv, part, C_QKV, NPix, C_IN);
    bn_finalize<<<(C_QKV + 127) / 128, 128>>>(part, gq, bq, scq, shq, C_QKV);
    flash_attn<<<dim3(8, 64), 256, FL_SMEM>>>(yqkv, scq, shq, obuf);
    tf32_gemm<<<dim3(C_MG/128, NPix/128, NB), 256, GEMM_SMEM>>>(wm, obuf, y2, part, C_MG, NPix, 1024);
    bn_finalize<<<(C_MG + 127) / 128, 128>>>(part, gm, bm, scm, shm, C_MG);
    resadd_bn<<<(NB * C_IN * NPix / 4 + 255) / 256, 256>>>(x, y2, scm, shm, xr, C_MG, NB * C_IN * NPix / 4);
    tf32_gemm<<<dim3(C_F1/128, NPix/128, NB), 256, GEMM_SMEM>>>(w1, xr, h1, part, C_F1, NPix, C_IN);
    bn_finalize<<<(C_F1 + 127) / 128, 128>>>(part, g1, b1, sc1, sh1, C_F1);
    bn_gelu_inplace<<<(NB * C_F1 * NPix / 4 + 255) / 256, 256>>>(h1, sc1, sh1, C_F1, NB * C_F1 * NPix / 4);
    tf32_gemm<<<dim3(C_F2/128, NPix/128, NB), 256, GEMM_SMEM>>>(w2, h1, y3, part, C_F2, NPix, C_F1);
    bn_finalize<<<(C_F2 + 127) / 128, 128>>>(part, g2, b2, sc2, sh2, C_F2);
    resadd_bn<<<(NB * C_F2 * NPix / 4 + 255) / 256, 256>>>(xr, y3, sc2, sh2, out, C_F2, NB * C_F2 * NPix / 4);
}

// round 12
// speedup vs baseline: 3.8582x; 1.0915x over previous
#include <cuda_runtime.h>
#include <cuda_fp16.h>
#include <cstdint>
#include <math.h>

#define NB    8
#define NPix  1024
#define C_IN  384
#define C_QKV 1536
#define C_MG  384
#define C_F1  768
#define C_F2  384
#define DK    32
#define DV    128
#define NPARTS 64

__device__ float g_yqkv[NB * C_QKV * NPix];
__device__ __half g_vh[NB * 8 * 128 * NPix];
__device__ float g_obuf[NB * 1024 * NPix];
__device__ float g_y2  [NB * C_MG * NPix];
__device__ float g_xr  [NB * C_IN * NPix];
__device__ float g_h1  [NB * C_F1 * NPix];
__device__ float g_y3  [NB * C_F2 * NPix];
__device__ float g_part[NPARTS * C_QKV * 2];
__device__ float g_sc_qkv[C_QKV], g_sh_qkv[C_QKV];
__device__ float g_sc_mg [C_MG ], g_sh_mg [C_MG ];
__device__ float g_sc_f1 [C_F1 ], g_sh_f1 [C_F1 ];
__device__ float g_sc_f2 [C_F2 ], g_sh_f2 [C_F2 ];
__device__ float g_wq[C_QKV * C_IN];
__device__ float g_wm[C_MG * 1024];
__device__ float g_w1[C_F1 * C_IN];
__device__ float g_w2[C_F2 * C_F1];

__device__ __forceinline__ float gelu_exact(float v) { return v * normcdff(v); }

__device__ __forceinline__ float f2tf(float f) {
    uint32_t r;
    asm("cvt.rna.tf32.f32 %0, %1;" : "=r"(r) : "f"(f));
    return __uint_as_float(r);
}

__device__ __forceinline__ void mma_tf32_16x8x8(float d[4],
                                                const uint32_t a[4],
                                                const uint32_t b[2])
{
    asm volatile(
        "mma.sync.aligned.m16n8k8.row.col.f32.tf32.tf32.f32 "
        "{%0,%1,%2,%3}, {%4,%5,%6,%7}, {%8,%9}, {%0,%1,%2,%3};"
        : "+f"(d[0]), "+f"(d[1]), "+f"(d[2]), "+f"(d[3])
        : "r"(a[0]), "r"(a[1]), "r"(a[2]), "r"(a[3]), "r"(b[0]), "r"(b[1]));
}

__device__ __forceinline__ void mma_f16_16x8x16(float d[4], const uint32_t a[4],
                                                uint32_t b0, uint32_t b1)
{
    asm volatile(
        "mma.sync.aligned.m16n8k16.row.col.f32.f16.f16.f32 "
        "{%0,%1,%2,%3}, {%4,%5,%6,%7}, {%8,%9}, {%0,%1,%2,%3};"
        : "+f"(d[0]), "+f"(d[1]), "+f"(d[2]), "+f"(d[3])
        : "r"(a[0]), "r"(a[1]), "r"(a[2]), "r"(a[3]), "r"(b0), "r"(b1));
}

__device__ __forceinline__ void cp16(uint32_t saddr, const void* gptr) {
    asm volatile("cp.async.cg.shared.global [%0], [%1], 16;" :: "r"(saddr), "l"(gptr));
}
#define CP_COMMIT asm volatile("cp.async.commit_group;" ::: "memory")
#define CP_WAIT1  asm volatile("cp.async.wait_group 1;" ::: "memory")
#define CP_WAIT0  asm volatile("cp.async.wait_group 0;" ::: "memory")

// ---------------- weight pre-rounding (single launch) ----------------
__global__ void round_all(const float* __restrict__ w0, float* __restrict__ o0,
                          const float* __restrict__ w1, float* __restrict__ o1,
                          const float* __restrict__ w2, float* __restrict__ o2,
                          const float* __restrict__ w3, float* __restrict__ o3)
{
    int i = blockIdx.x * 256 + threadIdx.x;
    const float* w; float* o; int j = i;
    if (j < 147456)                 { w = w0; o = o0; }
    else if ((j -= 147456) < 98304) { w = w1; o = o1; }
    else if ((j -=  98304) < 73728) { w = w2; o = o2; }
    else                            { j -= 73728; w = w3; o = o3; }
    float4 v = ((const float4*)w)[j];
    v.x = f2tf(v.x); v.y = f2tf(v.y); v.z = f2tf(v.z); v.w = f2tf(v.w);
    ((float4*)o)[j] = v;
}

// ---------------- V -> half pre-pass (raw copy/convert) ----------------
// vh[((b*8+h)*128+dv)*1024 + pix] = yqkv[(b*1536 + h*192 + 64 + dv)*1024 + pix]
__global__ void v_to_half(const float* __restrict__ yqkv, __half* __restrict__ vh)
{
    int i = blockIdx.x * 256 + threadIdx.x;     // 8 floats each; 1,048,576 total
    int row = i >> 7;                           // 0..8191
    int col = (i & 127) << 3;
    int b = row >> 10, rem = row & 1023;
    int h = rem >> 7, dv = rem & 127;
    const float* src = yqkv + ((size_t)(b * 1536 + h * 192 + 2 * DK + dv)) * 1024 + col;
    float4 v0 = *(const float4*)src;
    float4 v1 = *(const float4*)(src + 4);
    __half2 h0 = __floats2half2_rn(v0.x, v0.y);
    __half2 h1 = __floats2half2_rn(v0.z, v0.w);
    __half2 h2 = __floats2half2_rn(v1.x, v1.y);
    __half2 h3 = __floats2half2_rn(v1.z, v1.w);
    __half2* dst = (__half2*)(vh + (size_t)row * 1024 + col);
    dst[0] = h0; dst[1] = h1; dst[2] = h2; dst[3] = h3;
}

// ---------------- tf32 GEMM + fused BN partial stats ----------------------
#define STG_F 8960
#define STG_B 35840
#define GEMM_SMEM (3 * STG_B)

__global__ void __launch_bounds__(256, 2) tf32_gemm(const float* __restrict__ A,
                                                    const float* __restrict__ Bg,
                                                    float* __restrict__ Cg,
                                                    float* __restrict__ part,
                                                    int M, int N, int K)
{
    extern __shared__ float sm[];
    const uint32_t sbase = (uint32_t)__cvta_generic_to_shared(sm);

    const int tid  = threadIdx.x;
    const int wid  = tid >> 5;
    const int lane = tid & 31;
    const int gid  = lane >> 2;
    const int tid4 = lane & 3;
    const int wm   = (wid & 1) * 64;
    const int wn   = (wid >> 1) * 32;

    const int mBase = blockIdx.x * 128, nBase = blockIdx.y * 128;
    const float* Bp = Bg + (size_t)blockIdx.z * K * N;
    float*       Cp = Cg + (size_t)blockIdx.z * M * N;

    const int nst = K >> 5;

#define ISSUE_STAGE(s_) do {                                                   \
        int _s = (s_);                                                         \
        uint32_t sa = sbase + (_s % 3) * STG_B;                                \
        uint32_t sb2 = sa + 18432;                                             \
        int _k0 = _s << 5;                                                     \
        _Pragma("unroll")                                                      \
        for (int t = 0; t < 4; ++t) {                                          \
            int c = tid + t * 256;                                             \
            int m = c >> 3, j = c & 7;                                         \
            cp16(sa + m * 144 + j * 16,                                        \
                 &A[(size_t)(mBase + m) * K + _k0 + (j << 2)]);                \
        }                                                                      \
        _Pragma("unroll")                                                      \
        for (int t = 0; t < 4; ++t) {                                          \
            int c = tid + t * 256;                                             \
            int k = c >> 5, j = c & 31;                                        \
            cp16(sb2 + k * 544 + j * 16,                                       \
                 &Bp[(size_t)(_k0 + k) * N + nBase + (j << 2)]);               \
        }                                                                      \
    } while (0)

    float d[4][4][4];
#pragma unroll
    for (int mi = 0; mi < 4; ++mi)
#pragma unroll
        for (int ni = 0; ni < 4; ++ni)
#pragma unroll
            for (int r = 0; r < 4; ++r) d[mi][ni][r] = 0.f;

    ISSUE_STAGE(0); CP_COMMIT;
    ISSUE_STAGE(1); CP_COMMIT;

    for (int s = 0; s < nst; ++s) {
        CP_WAIT1;
        __syncthreads();
        if (s + 2 < nst) ISSUE_STAGE(s + 2);
        CP_COMMIT;

        const float* As = sm + (s % 3) * STG_F;
        const float* Bs = As + 4608;

#pragma unroll
        for (int kk = 0; kk < 32; kk += 8) {
            uint32_t af[4][4], bf[4][2];
#pragma unroll
            for (int mi = 0; mi < 4; ++mi) {
                int mr = wm + mi * 16 + gid;
                af[mi][0] = __float_as_uint(As[mr * 36 + kk + tid4]);
                af[mi][1] = __float_as_uint(As[(mr + 8) * 36 + kk + tid4]);
                af[mi][2] = __float_as_uint(As[mr * 36 + kk + tid4 + 4]);
                af[mi][3] = __float_as_uint(As[(mr + 8) * 36 + kk + tid4 + 4]);
            }
#pragma unroll
            for (int ni = 0; ni < 4; ++ni) {
                int nc = wn + ni * 8 + gid;
                bf[ni][0] = __float_as_uint(Bs[(kk + tid4) * 136 + nc]);
                bf[ni][1] = __float_as_uint(Bs[(kk + tid4 + 4) * 136 + nc]);
            }
#pragma unroll
            for (int mi = 0; mi < 4; ++mi)
#pragma unroll
                for (int ni = 0; ni < 4; ++ni)
                    mma_tf32_16x8x8(d[mi][ni], af[mi], bf[ni]);
        }
    }
#undef ISSUE_STAGE

    float sl[4], ql[4], sh_[4], qh[4];
#pragma unroll
    for (int mi = 0; mi < 4; ++mi) {
        sl[mi] = ql[mi] = sh_[mi] = qh[mi] = 0.f;
        int row = mBase + wm + mi * 16 + gid;
#pragma unroll
        for (int ni = 0; ni < 4; ++ni) {
            int col = nBase + wn + ni * 8 + 2 * tid4;
            sl[mi] += d[mi][ni][0] + d[mi][ni][1];
            ql[mi] += d[mi][ni][0] * d[mi][ni][0] + d[mi][ni][1] * d[mi][ni][1];
            sh_[mi] += d[mi][ni][2] + d[mi][ni][3];
            qh[mi] += d[mi][ni][2] * d[mi][ni][2] + d[mi][ni][3] * d[mi][ni][3];
            *(float2*)&Cp[(size_t)row * N + col] =
                make_float2(d[mi][ni][0], d[mi][ni][1]);
            *(float2*)&Cp[(size_t)(row + 8) * N + col] =
                make_float2(d[mi][ni][2], d[mi][ni][3]);
        }
#pragma unroll
        for (int off = 1; off <= 2; off <<= 1) {
            sl[mi]  += __shfl_xor_sync(0xffffffffu, sl[mi],  off);
            ql[mi]  += __shfl_xor_sync(0xffffffffu, ql[mi],  off);
            sh_[mi] += __shfl_xor_sync(0xffffffffu, sh_[mi], off);
            qh[mi]  += __shfl_xor_sync(0xffffffffu, qh[mi],  off);
        }
    }
    __syncthreads();
    float* pb = sm;
    if (tid4 == 0) {
        int g = wid >> 1;
#pragma unroll
        for (int mi = 0; mi < 4; ++mi) {
            int lr = wm + mi * 16 + gid;
            pb[(g * 128 + lr) * 2 + 0]     = sl[mi];
            pb[(g * 128 + lr) * 2 + 1]     = ql[mi];
            pb[(g * 128 + lr + 8) * 2 + 0] = sh_[mi];
            pb[(g * 128 + lr + 8) * 2 + 1] = qh[mi];
        }
    }
    __syncthreads();
    if (tid < 128) {
        float s = 0.f, q = 0.f;
#pragma unroll
        for (int g = 0; g < 4; ++g) {
            s += pb[(g * 128 + tid) * 2 + 0];
            q += pb[(g * 128 + tid) * 2 + 1];
        }
        int pidx = blockIdx.y * gridDim.z + blockIdx.z;
        part[((size_t)pidx * M + mBase + tid) * 2 + 0] = s;
        part[((size_t)pidx * M + mBase + tid) * 2 + 1] = q;
    }
}

// ---------------- BN finalize ----------------
__global__ void bn_finalize(const float* __restrict__ part,
                            const float* __restrict__ gamma,
                            const float* __restrict__ beta,
                            float* __restrict__ scl, float* __restrict__ shf, int C)
{
    int c = blockIdx.x * 128 + threadIdx.x;
    if (c >= C) return;
    float s = 0.f, q = 0.f;
    for (int p = 0; p < NPARTS; ++p) {
        s += part[((size_t)p * C + c) * 2 + 0];
        q += part[((size_t)p * C + c) * 2 + 1];
    }
    const float invN = 1.f / (NB * NPix);
    float mean = s * invN;
    float var  = q * invN - mean * mean;
    float sc   = gamma[c] * rsqrtf(var + 1e-5f);
    scl[c] = sc;
    shf[c] = beta[c] - mean * sc;
}

// ---------------- flash attention: tf32 QK + fp16 PV, cp.async 2-stage ----
// stage (25088 B): K float [32][68] @0, V half [128 dv][128 B] @8704 (XOR-chunk-swizzled)
// Qs float [32][136] @50176 B. Os [128][132] floats aliases base @0.
#define FL_STG_B 25088
#define FL_SMEM  (2 * FL_STG_B + 17408)

__global__ void __launch_bounds__(256) flash_attn(const float* __restrict__ yqkv,
                                                  const __half* __restrict__ vh,
                                                  const float* __restrict__ scl,
                                                  const float* __restrict__ shf,
                                                  float* __restrict__ obuf)
{
    extern __shared__ float fsm[];
    const uint32_t sbase = (uint32_t)__cvta_generic_to_shared(fsm);
    float* Qs = fsm + 2 * FL_STG_B / 4;
    float* Os = fsm;

    const int bh = blockIdx.y, b = bh >> 3, h = bh & 7;
    const int qBase = blockIdx.x * 128;
    const int tid = threadIdx.x, wid = tid >> 5, lane = tid & 31;
    const int gid = lane >> 2, tid4 = lane & 3;
    const float* base = yqkv + (size_t)b * C_QKV * NPix;
    const float* kbase = base + (size_t)(h * 192 + DK) * NPix;
    const __half* vbase = vh + (size_t)(bh * 128) * NPix;

    // Q tile: q'' = (q*scq+shq) * sck / sqrt(dk); K's additive BN term is
    // softmax-invariant (dropped); V's BN applied in epilogue.
    for (int i = tid; i < 32 * 128; i += 256) {
        int d = i >> 7, q = i & 127;
        int chq = h * 192 + d, chk = chq + DK;
        float fac = scl[chk] * 0.17677669529663687f;
        Qs[d * 136 + q] =
            f2tf((base[(size_t)chq * NPix + qBase + q] * scl[chq] + shf[chq]) * fac);
    }
    __syncthreads();

    uint32_t qf[4][4];
    const int mr = wid * 16 + gid;
#pragma unroll
    for (int ks = 0; ks < 4; ++ks) {
        qf[ks][0] = __float_as_uint(Qs[(ks * 8 + tid4) * 136 + mr]);
        qf[ks][1] = __float_as_uint(Qs[(ks * 8 + tid4) * 136 + mr + 8]);
        qf[ks][2] = __float_as_uint(Qs[(ks * 8 + tid4 + 4) * 136 + mr]);
        qf[ks][3] = __float_as_uint(Qs[(ks * 8 + tid4 + 4) * 136 + mr + 8]);
    }

    // staging per tile: K 512 chunks (2/thread) + V 1024 chunks (4/thread)
#define FL_ISSUE(i_) do {                                                      \
        int _k0 = (i_) << 6;                                                   \
        uint32_t sa = sbase + ((i_) & 1) * FL_STG_B;                           \
        _Pragma("unroll")                                                      \
        for (int t = 0; t < 2; ++t) {                                          \
            int c = tid + t * 256;                                             \
            int r = c >> 4, j = c & 15;                                        \
            cp16(sa + r * 272 + j * 16,                                        \
                 &kbase[(size_t)r * NPix + _k0 + (j << 2)]);                   \
        }                                                                      \
        _Pragma("unroll")                                                      \
        for (int t = 0; t < 4; ++t) {                                          \
            int c = tid + t * 256;                                             \
            int dv = c >> 3, j = c & 7;                                        \
            cp16(sa + 8704 + dv * 128 + ((j ^ (dv & 7)) << 4),                 \
                 &vbase[(size_t)dv * NPix + _k0 + (j << 3)]);                  \
        }                                                                      \
    } while (0)

    float o[16][4];
#pragma unroll
    for (int nt = 0; nt < 16; ++nt)
#pragma unroll
        for (int r = 0; r < 4; ++r) o[nt][r] = 0.f;
    float m0 = -1e30f, m1 = -1e30f, l0 = 0.f, l1 = 0.f;

    FL_ISSUE(0); CP_COMMIT;

    for (int it = 0; it < 16; ++it) {
        __syncthreads();
        if (it + 1 < 16) { FL_ISSUE(it + 1); CP_COMMIT; CP_WAIT1; }
        else             { CP_WAIT0; }
        __syncthreads();

        const float* Ks = fsm + (it & 1) * (FL_STG_B / 4);          // [32][68]
        const char*  Vc = (const char*)fsm + (it & 1) * FL_STG_B + 8704;

        // S = Q'' . K_raw (tf32)
        float s[8][4];
#pragma unroll
        for (int ni = 0; ni < 8; ++ni)
#pragma unroll
            for (int r = 0; r < 4; ++r) s[ni][r] = 0.f;
#pragma unroll
        for (int ks = 0; ks < 4; ++ks) {
#pragma unroll
            for (int ni = 0; ni < 8; ++ni) {
                uint32_t bf[2];
                bf[0] = __float_as_uint(Ks[(ks * 8 + tid4) * 68 + ni * 8 + gid]);
                bf[1] = __float_as_uint(Ks[(ks * 8 + tid4 + 4) * 68 + ni * 8 + gid]);
                mma_tf32_16x8x8(s[ni], qf[ks], bf);
            }
        }

        // online softmax
        float t0 = -1e30f, t1 = -1e30f;
#pragma unroll
        for (int ni = 0; ni < 8; ++ni) {
            t0 = fmaxf(t0, fmaxf(s[ni][0], s[ni][1]));
            t1 = fmaxf(t1, fmaxf(s[ni][2], s[ni][3]));
        }
        t0 = fmaxf(t0, __shfl_xor_sync(0xffffffffu, t0, 1));
        t0 = fmaxf(t0, __shfl_xor_sync(0xffffffffu, t0, 2));
        t1 = fmaxf(t1, __shfl_xor_sync(0xffffffffu, t1, 1));
        t1 = fmaxf(t1, __shfl_xor_sync(0xffffffffu, t1, 2));
        float mn0 = fmaxf(m0, t0), mn1 = fmaxf(m1, t1);
        float a0 = __expf(m0 - mn0), a1 = __expf(m1 - mn1);
        m0 = mn0; m1 = mn1;

        float ps0 = 0.f, ps1 = 0.f;
#pragma unroll
        for (int ni = 0; ni < 8; ++ni) {
            s[ni][0] = __expf(s[ni][0] - mn0);
            s[ni][1] = __expf(s[ni][1] - mn0);
            s[ni][2] = __expf(s[ni][2] - mn1);
            s[ni][3] = __expf(s[ni][3] - mn1);
            ps0 += s[ni][0] + s[ni][1];
            ps1 += s[ni][2] + s[ni][3];
        }
        ps0 += __shfl_xor_sync(0xffffffffu, ps0, 1);
        ps0 += __shfl_xor_sync(0xffffffffu, ps0, 2);
        ps1 += __shfl_xor_sync(0xffffffffu, ps1, 1);
        ps1 += __shfl_xor_sync(0xffffffffu, ps1, 2);
        l0 = l0 * a0 + ps0;
        l1 = l1 * a1 + ps1;

#pragma unroll
        for (int nt = 0; nt < 16; ++nt) {
            o[nt][0] *= a0; o[nt][1] *= a0;
            o[nt][2] *= a1; o[nt][3] *= a1;
        }

        // O += P . V  (fp16 m16n8k16; P packed straight from S fragments)
#pragma unroll
        for (int j = 0; j < 4; ++j) {
            uint32_t af[4];
            asm("cvt.rn.f16x2.f32 %0, %1, %2;" : "=r"(af[0]) : "f"(s[2*j][1]),   "f"(s[2*j][0]));
            asm("cvt.rn.f16x2.f32 %0, %1, %2;" : "=r"(af[1]) : "f"(s[2*j][3]),   "f"(s[2*j][2]));
            asm("cvt.rn.f16x2.f32 %0, %1, %2;" : "=r"(af[2]) : "f"(s[2*j+1][1]), "f"(s[2*j+1][0]));
            asm("cvt.rn.f16x2.f32 %0, %1, %2;" : "=r"(af[3]) : "f"(s[2*j+1][3]), "f"(s[2*j+1][2]));
#pragma unroll
            for (int nt = 0; nt < 16; ++nt) {
                int dv = nt * 8 + gid;
                uint32_t b0 = *(const uint32_t*)(Vc + dv * 128 + (((2*j)     ^ (dv & 7)) << 4) + 4 * tid4);
                uint32_t b1 = *(const uint32_t*)(Vc + dv * 128 + (((2*j + 1) ^ (dv & 7)) << 4) + 4 * tid4);
                mma_f16_16x8x16(o[nt], af, b0, b1);
            }
        }
    }
#undef FL_ISSUE

    // normalize + transpose; V's BN applied on final write
    float inv0 = 1.f / l0, inv1 = 1.f / l1;
    __syncthreads();
#pragma unroll
    for (int nt = 0; nt < 16; ++nt) {
        int dv = nt * 8 + 2 * tid4;
        int q  = wid * 16 + gid;
        Os[(size_t)dv * 132 + q]           = o[nt][0] * inv0;
        Os[(size_t)(dv + 1) * 132 + q]     = o[nt][1] * inv0;
        Os[(size_t)dv * 132 + q + 8]       = o[nt][2] * inv1;
        Os[(size_t)(dv + 1) * 132 + q + 8] = o[nt][3] * inv1;
    }
    __syncthreads();
    for (int i = tid; i < 128 * 32; i += 256) {
        int dv = i >> 5, q4 = (i & 31) << 2;
        int chv = h * 192 + 2 * DK + dv;
        float sc = scl[chv], sh = shf[chv];
        int ch = b * 1024 + h * 128 + dv;
        float4 v = *(float4*)&Os[dv * 132 + q4];
        v.x = gelu_exact(v.x * sc + sh); v.y = gelu_exact(v.y * sc + sh);
        v.z = gelu_exact(v.z * sc + sh); v.w = gelu_exact(v.w * sc + sh);
        *(float4*)&obuf[(size_t)ch * NPix + qBase + q4] = v;
    }
}

// ---------------- elementwise (float4) ----------------
__global__ void resadd_bn(const float* __restrict__ x, const float* __restrict__ y,
                          const float* __restrict__ scl, const float* __restrict__ shf,
                          float* __restrict__ o, int C, int total4)
{
    int i = blockIdx.x * 256 + threadIdx.x;
    if (i >= total4) return;
    int ch = (i >> 8) % C;
    float sc = scl[ch], sh = shf[ch];
    float4 a = ((const float4*)x)[i];
    float4 c = ((const float4*)y)[i];
    a.x += c.x * sc + sh; a.y += c.y * sc + sh;
    a.z += c.z * sc + sh; a.w += c.w * sc + sh;
    ((float4*)o)[i] = a;
}
__global__ void bn_gelu_inplace(float* __restrict__ y,
                                const float* __restrict__ scl,
                                const float* __restrict__ shf, int C, int total4)
{
    int i = blockIdx.x * 256 + threadIdx.x;
    if (i >= total4) return;
    int ch = (i >> 8) % C;
    float sc = scl[ch], sh = shf[ch];
    float4 v = ((float4*)y)[i];
    v.x = gelu_exact(v.x * sc + sh); v.y = gelu_exact(v.y * sc + sh);
    v.z = gelu_exact(v.z * sc + sh); v.w = gelu_exact(v.w * sc + sh);
    ((float4*)y)[i] = v;
}

// ---------------- host ----------------
extern "C" void kernel_launch(void* const* d_in, const int* in_sizes, int n_in,
                              void* d_out, int out_size)
{
    const float* x       = (const float*)d_in[0];
    const float* w_qkv   = (const float*)d_in[1];
    const float* gq      = (const float*)d_in[2];
    const float* bq      = (const float*)d_in[3];
    const float* w_merge = (const float*)d_in[4];
    const float* gm      = (const float*)d_in[5];
    const float* bm      = (const float*)d_in[6];
    const float* w_fc1   = (const float*)d_in[7];
    const float* g1      = (const float*)d_in[8];
    const float* b1      = (const float*)d_in[9];
    const float* w_fc2   = (const float*)d_in[10];
    const float* g2      = (const float*)d_in[11];
    const float* b2      = (const float*)d_in[12];
    float* out = (float*)d_out;

    float *yqkv, *obuf, *y2, *xr, *h1, *y3, *part;
    __half* vh;
    float *scq, *shq, *scm, *shm, *sc1, *sh1, *sc2, *sh2;
    float *wq, *wm, *w1, *w2;
    cudaGetSymbolAddress((void**)&yqkv, g_yqkv);
    cudaGetSymbolAddress((void**)&vh,   g_vh);
    cudaGetSymbolAddress((void**)&obuf, g_obuf);
    cudaGetSymbolAddress((void**)&y2,   g_y2);
    cudaGetSymbolAddress((void**)&xr,   g_xr);
    cudaGetSymbolAddress((void**)&h1,   g_h1);
    cudaGetSymbolAddress((void**)&y3,   g_y3);
    cudaGetSymbolAddress((void**)&part, g_part);
    cudaGetSymbolAddress((void**)&scq, g_sc_qkv);
    cudaGetSymbolAddress((void**)&shq, g_sh_qkv);
    cudaGetSymbolAddress((void**)&scm, g_sc_mg);
    cudaGetSymbolAddress((void**)&shm, g_sh_mg);
    cudaGetSymbolAddress((void**)&sc1, g_sc_f1);
    cudaGetSymbolAddress((void**)&sh1, g_sh_f1);
    cudaGetSymbolAddress((void**)&sc2, g_sc_f2);
    cudaGetSymbolAddress((void**)&sh2, g_sh_f2);
    cudaGetSymbolAddress((void**)&wq, g_wq);
    cudaGetSymbolAddress((void**)&wm, g_wm);
    cudaGetSymbolAddress((void**)&w1, g_w1);
    cudaGetSymbolAddress((void**)&w2, g_w2);

    cudaFuncSetAttribute(tf32_gemm, cudaFuncAttributeMaxDynamicSharedMemorySize, GEMM_SMEM);
    cudaFuncSetAttribute(flash_attn, cudaFuncAttributeMaxDynamicSharedMemorySize, FL_SMEM);

    round_all<<<1536, 256>>>(w_qkv, wq, w_merge, wm, w_fc1, w1, w_fc2, w2);

    tf32_gemm<<<dim3(C_QKV/128, NPix/128, NB), 256, GEMM_SMEM>>>(wq, x, yqkv, part, C_QKV, NPix, C_IN);
    v_to_half<<<4096, 256>>>(yqkv, vh);
    bn_finalize<<<(C_QKV + 127) / 128, 128>>>(part, gq, bq, scq, shq, C_QKV);
    flash_attn<<<dim3(8, 64), 256, FL_SMEM>>>(yqkv, vh, scq, shq, obuf);
    tf32_gemm<<<dim3(C_MG/128, NPix/128, NB), 256, GEMM_SMEM>>>(wm, obuf, y2, part, C_MG, NPix, 1024);
    bn_finalize<<<(C_MG + 127) / 128, 128>>>(part, gm, bm, scm, shm, C_MG);
    resadd_bn<<<(NB * C_IN * NPix / 4 + 255) / 256, 256>>>(x, y2, scm, shm, xr, C_MG, NB * C_IN * NPix / 4);
    tf32_gemm<<<dim3(C_F1/128, NPix/128, NB), 256, GEMM_SMEM>>>(w1, xr, h1, part, C_F1, NPix, C_IN);
    bn_finalize<<<(C_F1 + 127) / 128, 128>>>(part, g1, b1, sc1, sh1, C_F1);
    bn_gelu_inplace<<<(NB * C_F1 * NPix / 4 + 255) / 256, 256>>>(h1, sc1, sh1, C_F1, NB * C_F1 * NPix / 4);
    tf32_gemm<<<dim3(C_F2/128, NPix/128, NB), 256, GEMM_SMEM>>>(w2, h1, y3, part, C_F2, NPix, C_F1);
    bn_finalize<<<(C_F2 + 127) / 128, 128>>>(part, g2, b2, sc2, sh2, C_F2);
    resadd_bn<<<(NB * C_F2 * NPix / 4 + 255) / 256, 256>>>(xr, y3, sc2, sh2, out, C_F2, NB * C_F2 * NPix / 4);
}

// round 13
// speedup vs baseline: 4.9671x; 1.2874x over previous
#include <cuda_runtime.h>
#include <cuda_fp16.h>
#include <cstdint>
#include <math.h>

#define NB    8
#define NPix  1024
#define C_IN  384
#define C_QKV 1536
#define C_MG  384
#define C_F1  768
#define C_F2  384
#define DK    32
#define DV    128
#define NPARTS 64

__device__ float  g_yqkv[NB * C_QKV * NPix];
__device__ __half g_vh[NB * 8 * 128 * NPix];
__device__ __half g_obuf[NB * 1024 * NPix];
__device__ float  g_y2 [NB * C_MG * NPix];
__device__ float  g_xr [NB * C_IN * NPix];
__device__ __half g_xrh[NB * C_IN * NPix];
__device__ __half g_xh [NB * C_IN * NPix];
__device__ float  g_h1 [NB * C_F1 * NPix];
__device__ __half g_h1h[NB * C_F1 * NPix];
__device__ float  g_y3 [NB * C_F2 * NPix];
__device__ float  g_part[NPARTS * C_QKV * 2];
__device__ float  g_sc_qkv[C_QKV], g_sh_qkv[C_QKV];
__device__ float  g_sc_mg [C_MG ], g_sh_mg [C_MG ];
__device__ float  g_sc_f1 [C_F1 ], g_sh_f1 [C_F1 ];
__device__ float  g_sc_f2 [C_F2 ], g_sh_f2 [C_F2 ];
__device__ __half g_wq[C_QKV * C_IN];
__device__ __half g_wm[C_MG * 1024];
__device__ __half g_w1[C_F1 * C_IN];
__device__ __half g_w2[C_F2 * C_F1];

__device__ __forceinline__ float gelu_exact(float v) { return v * normcdff(v); }

__device__ __forceinline__ float f2tf(float f) {
    uint32_t r;
    asm("cvt.rna.tf32.f32 %0, %1;" : "=r"(r) : "f"(f));
    return __uint_as_float(r);
}

__device__ __forceinline__ void mma_tf32_16x8x8(float d[4],
                                                const uint32_t a[4],
                                                const uint32_t b[2])
{
    asm volatile(
        "mma.sync.aligned.m16n8k8.row.col.f32.tf32.tf32.f32 "
        "{%0,%1,%2,%3}, {%4,%5,%6,%7}, {%8,%9}, {%0,%1,%2,%3};"
        : "+f"(d[0]), "+f"(d[1]), "+f"(d[2]), "+f"(d[3])
        : "r"(a[0]), "r"(a[1]), "r"(a[2]), "r"(a[3]), "r"(b[0]), "r"(b[1]));
}

__device__ __forceinline__ void mma_f16_16x8x16(float d[4], const uint32_t a[4],
                                                uint32_t b0, uint32_t b1)
{
    asm volatile(
        "mma.sync.aligned.m16n8k16.row.col.f32.f16.f16.f32 "
        "{%0,%1,%2,%3}, {%4,%5,%6,%7}, {%8,%9}, {%0,%1,%2,%3};"
        : "+f"(d[0]), "+f"(d[1]), "+f"(d[2]), "+f"(d[3])
        : "r"(a[0]), "r"(a[1]), "r"(a[2]), "r"(a[3]), "r"(b0), "r"(b1));
}

__device__ __forceinline__ void ldm_x4(uint32_t r[4], uint32_t addr) {
    asm volatile("ldmatrix.sync.aligned.m8n8.x4.shared.b16 {%0,%1,%2,%3}, [%4];"
                 : "=r"(r[0]), "=r"(r[1]), "=r"(r[2]), "=r"(r[3]) : "r"(addr));
}
__device__ __forceinline__ void ldm_x4t(uint32_t r[4], uint32_t addr) {
    asm volatile("ldmatrix.sync.aligned.m8n8.x4.trans.shared.b16 {%0,%1,%2,%3}, [%4];"
                 : "=r"(r[0]), "=r"(r[1]), "=r"(r[2]), "=r"(r[3]) : "r"(addr));
}

__device__ __forceinline__ void cp16(uint32_t saddr, const void* gptr) {
    asm volatile("cp.async.cg.shared.global [%0], [%1], 16;" :: "r"(saddr), "l"(gptr));
}
#define CP_COMMIT asm volatile("cp.async.commit_group;" ::: "memory")
#define CP_WAIT1  asm volatile("cp.async.wait_group 1;" ::: "memory")
#define CP_WAIT0  asm volatile("cp.async.wait_group 0;" ::: "memory")

// ---------------- weight fp32 -> fp16 (single launch) ----------------
__global__ void round_all(const float* __restrict__ w0, __half* __restrict__ o0,
                          const float* __restrict__ w1, __half* __restrict__ o1,
                          const float* __restrict__ w2, __half* __restrict__ o2,
                          const float* __restrict__ w3, __half* __restrict__ o3)
{
    int i = blockIdx.x * 256 + threadIdx.x;
    const float* w; __half* o; int j = i;
    if (j < 147456)                 { w = w0; o = o0; }
    else if ((j -= 147456) < 98304) { w = w1; o = o1; }
    else if ((j -=  98304) < 73728) { w = w2; o = o2; }
    else                            { j -= 73728; w = w3; o = o3; }
    float4 v = ((const float4*)w)[j];
    __half2* d = (__half2*)o + 2 * j;
    d[0] = __floats2half2_rn(v.x, v.y);
    d[1] = __floats2half2_rn(v.z, v.w);
}

// ---------------- fp32 -> fp16 copy ----------------
__global__ void f2h(const float* __restrict__ src, __half* __restrict__ dst, int n4)
{
    int i = blockIdx.x * 256 + threadIdx.x;
    if (i >= n4) return;
    float4 v = ((const float4*)src)[i];
    __half2* d = (__half2*)dst + 2 * i;
    d[0] = __floats2half2_rn(v.x, v.y);
    d[1] = __floats2half2_rn(v.z, v.w);
}

// ---------------- V -> half pre-pass ----------------
__global__ void v_to_half(const float* __restrict__ yqkv, __half* __restrict__ vh)
{
    int i = blockIdx.x * 256 + threadIdx.x;
    int row = i >> 7;
    int col = (i & 127) << 3;
    int b = row >> 10, rem = row & 1023;
    int h = rem >> 7, dv = rem & 127;
    const float* src = yqkv + ((size_t)(b * 1536 + h * 192 + 2 * DK + dv)) * 1024 + col;
    float4 v0 = *(const float4*)src;
    float4 v1 = *(const float4*)(src + 4);
    __half2* dst = (__half2*)(vh + (size_t)row * 1024 + col);
    dst[0] = __floats2half2_rn(v0.x, v0.y);
    dst[1] = __floats2half2_rn(v0.z, v0.w);
    dst[2] = __floats2half2_rn(v1.x, v1.y);
    dst[3] = __floats2half2_rn(v1.z, v1.w);
}

// ---------------- fp16 GEMM + fused BN partial stats ----------------------
// C[b](M,N) = A(M,K) * B[b](K,N), A/B half, C fp32. 128x128 tile, BK=32.
// A smem [m][32] half pitch 80 B; B smem [k][128] half pitch 272 B.
// Fragments via ldmatrix (A: x4, B: x4.trans). 3-stage cp.async ring.
#define F16_STG_B 18944
#define GEMM_SMEM (3 * F16_STG_B)

__global__ void __launch_bounds__(256, 2) f16_gemm(const __half* __restrict__ A,
                                                   const __half* __restrict__ Bg,
                                                   float* __restrict__ Cg,
                                                   float* __restrict__ part,
                                                   int M, int N, int K)
{
    extern __shared__ char smc[];
    const uint32_t sbase = (uint32_t)__cvta_generic_to_shared(smc);
    float* sm = (float*)smc;

    const int tid  = threadIdx.x;
    const int wid  = tid >> 5;
    const int lane = tid & 31;
    const int gid  = lane >> 2;
    const int tid4 = lane & 3;
    const int wm   = (wid & 1) * 64;
    const int wn   = (wid >> 1) * 32;

    const int mBase = blockIdx.x * 128, nBase = blockIdx.y * 128;
    const __half* Bp = Bg + (size_t)blockIdx.z * K * N;
    float*        Cp = Cg + (size_t)blockIdx.z * M * N;

    const int nst = K >> 5;

    // ldmatrix lane address offsets (within stage)
    const int lt = lane >> 3, lr = lane & 7;
    uint32_t aoff[4];
#pragma unroll
    for (int mi = 0; mi < 4; ++mi)
        aoff[mi] = (uint32_t)((wm + mi * 16 + (lt & 1) * 8 + lr) * 80 + (lt >> 1) * 16);
    uint32_t boff[2];
#pragma unroll
    for (int nip = 0; nip < 2; ++nip)
        boff[nip] = (uint32_t)(10240 + ((lt & 1) * 8 + lr) * 272 +
                               (wn + nip * 16 + (lt >> 1) * 8) * 2);

#define ISSUE_STAGE(s_) do {                                                   \
        int _s = (s_);                                                         \
        uint32_t sa = sbase + (_s % 3) * F16_STG_B;                            \
        int _k0 = _s << 5;                                                     \
        _Pragma("unroll")                                                      \
        for (int t = 0; t < 2; ++t) {                                          \
            int c = tid + t * 256;                                             \
            int m = c >> 2, j = c & 3;                                         \
            cp16(sa + m * 80 + j * 16,                                         \
                 &A[(size_t)(mBase + m) * K + _k0 + (j << 3)]);                \
        }                                                                      \
        _Pragma("unroll")                                                      \
        for (int t = 0; t < 2; ++t) {                                          \
            int c = tid + t * 256;                                             \
            int k = c >> 4, j = c & 15;                                        \
            cp16(sa + 10240 + k * 272 + j * 16,                                \
                 &Bp[(size_t)(_k0 + k) * N + nBase + (j << 3)]);               \
        }                                                                      \
    } while (0)

    float d[4][4][4];
#pragma unroll
    for (int mi = 0; mi < 4; ++mi)
#pragma unroll
        for (int ni = 0; ni < 4; ++ni)
#pragma unroll
            for (int r = 0; r < 4; ++r) d[mi][ni][r] = 0.f;

    ISSUE_STAGE(0); CP_COMMIT;
    ISSUE_STAGE(1); CP_COMMIT;

    for (int s = 0; s < nst; ++s) {
        CP_WAIT1;
        __syncthreads();
        if (s + 2 < nst) ISSUE_STAGE(s + 2);
        CP_COMMIT;

        uint32_t stg = sbase + (s % 3) * F16_STG_B;

#pragma unroll
        for (int ks = 0; ks < 2; ++ks) {
            uint32_t af[4][4];
#pragma unroll
            for (int mi = 0; mi < 4; ++mi)
                ldm_x4(af[mi], stg + aoff[mi] + ks * 32);
            uint32_t bf0[4], bf1[4];
            ldm_x4t(bf0, stg + boff[0] + ks * 4352);
            ldm_x4t(bf1, stg + boff[1] + ks * 4352);
#pragma unroll
            for (int mi = 0; mi < 4; ++mi) {
                mma_f16_16x8x16(d[mi][0], af[mi], bf0[0], bf0[1]);
                mma_f16_16x8x16(d[mi][1], af[mi], bf0[2], bf0[3]);
                mma_f16_16x8x16(d[mi][2], af[mi], bf1[0], bf1[1]);
                mma_f16_16x8x16(d[mi][3], af[mi], bf1[2], bf1[3]);
            }
        }
    }
#undef ISSUE_STAGE

    // ---- store C + per-row BN partials ----
    float sl[4], ql[4], sh_[4], qh[4];
#pragma unroll
    for (int mi = 0; mi < 4; ++mi) {
        sl[mi] = ql[mi] = sh_[mi] = qh[mi] = 0.f;
        int row = mBase + wm + mi * 16 + gid;
#pragma unroll
        for (int ni = 0; ni < 4; ++ni) {
            int col = nBase + wn + ni * 8 + 2 * tid4;
            sl[mi] += d[mi][ni][0] + d[mi][ni][1];
            ql[mi] += d[mi][ni][0] * d[mi][ni][0] + d[mi][ni][1] * d[mi][ni][1];
            sh_[mi] += d[mi][ni][2] + d[mi][ni][3];
            qh[mi] += d[mi][ni][2] * d[mi][ni][2] + d[mi][ni][3] * d[mi][ni][3];
            *(float2*)&Cp[(size_t)row * N + col] =
                make_float2(d[mi][ni][0], d[mi][ni][1]);
            *(float2*)&Cp[(size_t)(row + 8) * N + col] =
                make_float2(d[mi][ni][2], d[mi][ni][3]);
        }
#pragma unroll
        for (int off = 1; off <= 2; off <<= 1) {
            sl[mi]  += __shfl_xor_sync(0xffffffffu, sl[mi],  off);
            ql[mi]  += __shfl_xor_sync(0xffffffffu, ql[mi],  off);
            sh_[mi] += __shfl_xor_sync(0xffffffffu, sh_[mi], off);
            qh[mi]  += __shfl_xor_sync(0xffffffffu, qh[mi],  off);
        }
    }
    __syncthreads();
    float* pb = sm;
    if (tid4 == 0) {
        int g = wid >> 1;
#pragma unroll
        for (int mi = 0; mi < 4; ++mi) {
            int lr2 = wm + mi * 16 + gid;
            pb[(g * 128 + lr2) * 2 + 0]     = sl[mi];
            pb[(g * 128 + lr2) * 2 + 1]     = ql[mi];
            pb[(g * 128 + lr2 + 8) * 2 + 0] = sh_[mi];
            pb[(g * 128 + lr2 + 8) * 2 + 1] = qh[mi];
        }
    }
    __syncthreads();
    if (tid < 128) {
        float s = 0.f, q = 0.f;
#pragma unroll
        for (int g = 0; g < 4; ++g) {
            s += pb[(g * 128 + tid) * 2 + 0];
            q += pb[(g * 128 + tid) * 2 + 1];
        }
        int pidx = blockIdx.y * gridDim.z + blockIdx.z;
        part[((size_t)pidx * M + mBase + tid) * 2 + 0] = s;
        part[((size_t)pidx * M + mBase + tid) * 2 + 1] = q;
    }
}

// ---------------- BN finalize ----------------
__global__ void bn_finalize(const float* __restrict__ part,
                            const float* __restrict__ gamma,
                            const float* __restrict__ beta,
                            float* __restrict__ scl, float* __restrict__ shf, int C)
{
    int c = blockIdx.x * 128 + threadIdx.x;
    if (c >= C) return;
    float s = 0.f, q = 0.f;
    for (int p = 0; p < NPARTS; ++p) {
        s += part[((size_t)p * C + c) * 2 + 0];
        q += part[((size_t)p * C + c) * 2 + 1];
    }
    const float invN = 1.f / (NB * NPix);
    float mean = s * invN;
    float var  = q * invN - mean * mean;
    float sc   = gamma[c] * rsqrtf(var + 1e-5f);
    scl[c] = sc;
    shf[c] = beta[c] - mean * sc;
}

// ---------------- flash attention (unchanged core; half obuf out) ---------
#define FL_STG_B 25088
#define FL_SMEM  (2 * FL_STG_B + 17408)

__global__ void __launch_bounds__(256) flash_attn(const float* __restrict__ yqkv,
                                                  const __half* __restrict__ vh,
                                                  const float* __restrict__ scl,
                                                  const float* __restrict__ shf,
                                                  __half* __restrict__ obuf)
{
    extern __shared__ float fsm[];
    const uint32_t sbase = (uint32_t)__cvta_generic_to_shared(fsm);
    float* Qs = fsm + 2 * FL_STG_B / 4;
    float* Os = fsm;

    const int bh = blockIdx.y, b = bh >> 3, h = bh & 7;
    const int qBase = blockIdx.x * 128;
    const int tid = threadIdx.x, wid = tid >> 5, lane = tid & 31;
    const int gid = lane >> 2, tid4 = lane & 3;
    const float* base = yqkv + (size_t)b * C_QKV * NPix;
    const float* kbase = base + (size_t)(h * 192 + DK) * NPix;
    const __half* vbase = vh + (size_t)(bh * 128) * NPix;

    for (int i = tid; i < 32 * 128; i += 256) {
        int d = i >> 7, q = i & 127;
        int chq = h * 192 + d, chk = chq + DK;
        float fac = scl[chk] * 0.17677669529663687f;
        Qs[d * 136 + q] =
            f2tf((base[(size_t)chq * NPix + qBase + q] * scl[chq] + shf[chq]) * fac);
    }
    __syncthreads();

    uint32_t qf[4][4];
    const int mr = wid * 16 + gid;
#pragma unroll
    for (int ks = 0; ks < 4; ++ks) {
        qf[ks][0] = __float_as_uint(Qs[(ks * 8 + tid4) * 136 + mr]);
        qf[ks][1] = __float_as_uint(Qs[(ks * 8 + tid4) * 136 + mr + 8]);
        qf[ks][2] = __float_as_uint(Qs[(ks * 8 + tid4 + 4) * 136 + mr]);
        qf[ks][3] = __float_as_uint(Qs[(ks * 8 + tid4 + 4) * 136 + mr + 8]);
    }

#define FL_ISSUE(i_) do {                                                      \
        int _k0 = (i_) << 6;                                                   \
        uint32_t sa = sbase + ((i_) & 1) * FL_STG_B;                           \
        _Pragma("unroll")                                                      \
        for (int t = 0; t < 2; ++t) {                                          \
            int c = tid + t * 256;                                             \
            int r = c >> 4, j = c & 15;                                        \
            cp16(sa + r * 272 + j * 16,                                        \
                 &kbase[(size_t)r * NPix + _k0 + (j << 2)]);                   \
        }                                                                      \
        _Pragma("unroll")                                                      \
        for (int t = 0; t < 4; ++t) {                                          \
            int c = tid + t * 256;                                             \
            int dv = c >> 3, j = c & 7;                                        \
            cp16(sa + 8704 + dv * 128 + ((j ^ (dv & 7)) << 4),                 \
                 &vbase[(size_t)dv * NPix + _k0 + (j << 3)]);                  \
        }                                                                      \
    } while (0)

    float o[16][4];
#pragma unroll
    for (int nt = 0; nt < 16; ++nt)
#pragma unroll
        for (int r = 0; r < 4; ++r) o[nt][r] = 0.f;
    float m0 = -1e30f, m1 = -1e30f, l0 = 0.f, l1 = 0.f;

    FL_ISSUE(0); CP_COMMIT;

    for (int it = 0; it < 16; ++it) {
        __syncthreads();
        if (it + 1 < 16) { FL_ISSUE(it + 1); CP_COMMIT; CP_WAIT1; }
        else             { CP_WAIT0; }
        __syncthreads();

        const float* Ks = fsm + (it & 1) * (FL_STG_B / 4);
        const char*  Vc = (const char*)fsm + (it & 1) * FL_STG_B + 8704;

        float s[8][4];
#pragma unroll
        for (int ni = 0; ni < 8; ++ni)
#pragma unroll
            for (int r = 0; r < 4; ++r) s[ni][r] = 0.f;
#pragma unroll
        for (int ks = 0; ks < 4; ++ks) {
#pragma unroll
            for (int ni = 0; ni < 8; ++ni) {
                uint32_t bf[2];
                bf[0] = __float_as_uint(Ks[(ks * 8 + tid4) * 68 + ni * 8 + gid]);
                bf[1] = __float_as_uint(Ks[(ks * 8 + tid4 + 4) * 68 + ni * 8 + gid]);
                mma_tf32_16x8x8(s[ni], qf[ks], bf);
            }
        }

        float t0 = -1e30f, t1 = -1e30f;
#pragma unroll
        for (int ni = 0; ni < 8; ++ni) {
            t0 = fmaxf(t0, fmaxf(s[ni][0], s[ni][1]));
            t1 = fmaxf(t1, fmaxf(s[ni][2], s[ni][3]));
        }
        t0 = fmaxf(t0, __shfl_xor_sync(0xffffffffu, t0, 1));
        t0 = fmaxf(t0, __shfl_xor_sync(0xffffffffu, t0, 2));
        t1 = fmaxf(t1, __shfl_xor_sync(0xffffffffu, t1, 1));
        t1 = fmaxf(t1, __shfl_xor_sync(0xffffffffu, t1, 2));
        float mn0 = fmaxf(m0, t0), mn1 = fmaxf(m1, t1);
        float a0 = __expf(m0 - mn0), a1 = __expf(m1 - mn1);
        m0 = mn0; m1 = mn1;

        float ps0 = 0.f, ps1 = 0.f;
#pragma unroll
        for (int ni = 0; ni < 8; ++ni) {
            s[ni][0] = __expf(s[ni][0] - mn0);
            s[ni][1] = __expf(s[ni][1] - mn0);
            s[ni][2] = __expf(s[ni][2] - mn1);
            s[ni][3] = __expf(s[ni][3] - mn1);
            ps0 += s[ni][0] + s[ni][1];
            ps1 += s[ni][2] + s[ni][3];
        }
        ps0 += __shfl_xor_sync(0xffffffffu, ps0, 1);
        ps0 += __shfl_xor_sync(0xffffffffu, ps0, 2);
        ps1 += __shfl_xor_sync(0xffffffffu, ps1, 1);
        ps1 += __shfl_xor_sync(0xffffffffu, ps1, 2);
        l0 = l0 * a0 + ps0;
        l1 = l1 * a1 + ps1;

#pragma unroll
        for (int nt = 0; nt < 16; ++nt) {
            o[nt][0] *= a0; o[nt][1] *= a0;
            o[nt][2] *= a1; o[nt][3] *= a1;
        }

#pragma unroll
        for (int j = 0; j < 4; ++j) {
            uint32_t af[4];
            asm("cvt.rn.f16x2.f32 %0, %1, %2;" : "=r"(af[0]) : "f"(s[2*j][1]),   "f"(s[2*j][0]));
            asm("cvt.rn.f16x2.f32 %0, %1, %2;" : "=r"(af[1]) : "f"(s[2*j][3]),   "f"(s[2*j][2]));
            asm("cvt.rn.f16x2.f32 %0, %1, %2;" : "=r"(af[2]) : "f"(s[2*j+1][1]), "f"(s[2*j+1][0]));
            asm("cvt.rn.f16x2.f32 %0, %1, %2;" : "=r"(af[3]) : "f"(s[2*j+1][3]), "f"(s[2*j+1][2]));
#pragma unroll
            for (int nt = 0; nt < 16; ++nt) {
                int dv = nt * 8 + gid;
                uint32_t b0 = *(const uint32_t*)(Vc + dv * 128 + (((2*j)     ^ (dv & 7)) << 4) + 4 * tid4);
                uint32_t b1 = *(const uint32_t*)(Vc + dv * 128 + (((2*j + 1) ^ (dv & 7)) << 4) + 4 * tid4);
                mma_f16_16x8x16(o[nt], af, b0, b1);
            }
        }
    }
#undef FL_ISSUE

    float inv0 = 1.f / l0, inv1 = 1.f / l1;
    __syncthreads();
#pragma unroll
    for (int nt = 0; nt < 16; ++nt) {
        int dv = nt * 8 + 2 * tid4;
        int q  = wid * 16 + gid;
        Os[(size_t)dv * 132 + q]           = o[nt][0] * inv0;
        Os[(size_t)(dv + 1) * 132 + q]     = o[nt][1] * inv0;
        Os[(size_t)dv * 132 + q + 8]       = o[nt][2] * inv1;
        Os[(size_t)(dv + 1) * 132 + q + 8] = o[nt][3] * inv1;
    }
    __syncthreads();
    for (int i = tid; i < 128 * 32; i += 256) {
        int dv = i >> 5, q4 = (i & 31) << 2;
        int chv = h * 192 + 2 * DK + dv;
        float sc = scl[chv], sh = shf[chv];
        int ch = b * 1024 + h * 128 + dv;
        float4 v = *(float4*)&Os[dv * 132 + q4];
        v.x = gelu_exact(v.x * sc + sh); v.y = gelu_exact(v.y * sc + sh);
        v.z = gelu_exact(v.z * sc + sh); v.w = gelu_exact(v.w * sc + sh);
        __half2* dst = (__half2*)(obuf + (size_t)ch * NPix + qBase + q4);
        dst[0] = __floats2half2_rn(v.x, v.y);
        dst[1] = __floats2half2_rn(v.z, v.w);
    }
}

// ---------------- elementwise ----------------
__global__ void resadd_bn_dual(const float* __restrict__ x, const float* __restrict__ y,
                               const float* __restrict__ scl, const float* __restrict__ shf,
                               float* __restrict__ o, __half* __restrict__ oh,
                               int C, int total4)
{
    int i = blockIdx.x * 256 + threadIdx.x;
    if (i >= total4) return;
    int ch = (i >> 8) % C;
    float sc = scl[ch], sh = shf[ch];
    float4 a = ((const float4*)x)[i];
    float4 c = ((const float4*)y)[i];
    a.x += c.x * sc + sh; a.y += c.y * sc + sh;
    a.z += c.z * sc + sh; a.w += c.w * sc + sh;
    ((float4*)o)[i] = a;
    __half2* d = (__half2*)oh + 2 * i;
    d[0] = __floats2half2_rn(a.x, a.y);
    d[1] = __floats2half2_rn(a.z, a.w);
}
__global__ void resadd_bn(const float* __restrict__ x, const float* __restrict__ y,
                          const float* __restrict__ scl, const float* __restrict__ shf,
                          float* __restrict__ o, int C, int total4)
{
    int i = blockIdx.x * 256 + threadIdx.x;
    if (i >= total4) return;
    int ch = (i >> 8) % C;
    float sc = scl[ch], sh = shf[ch];
    float4 a = ((const float4*)x)[i];
    float4 c = ((const float4*)y)[i];
    a.x += c.x * sc + sh; a.y += c.y * sc + sh;
    a.z += c.z * sc + sh; a.w += c.w * sc + sh;
    ((float4*)o)[i] = a;
}
__global__ void bn_gelu_half(const float* __restrict__ y, __half* __restrict__ oh,
                             const float* __restrict__ scl,
                             const float* __restrict__ shf, int C, int total4)
{
    int i = blockIdx.x * 256 + threadIdx.x;
    if (i >= total4) return;
    int ch = (i >> 8) % C;
    float sc = scl[ch], sh = shf[ch];
    float4 v = ((const float4*)y)[i];
    v.x = gelu_exact(v.x * sc + sh); v.y = gelu_exact(v.y * sc + sh);
    v.z = gelu_exact(v.z * sc + sh); v.w = gelu_exact(v.w * sc + sh);
    __half2* d = (__half2*)oh + 2 * i;
    d[0] = __floats2half2_rn(v.x, v.y);
    d[1] = __floats2half2_rn(v.z, v.w);
}

// ---------------- host ----------------
extern "C" void kernel_launch(void* const* d_in, const int* in_sizes, int n_in,
                              void* d_out, int out_size)
{
    const float* x       = (const float*)d_in[0];
    const float* w_qkv   = (const float*)d_in[1];
    const float* gq      = (const float*)d_in[2];
    const float* bq      = (const float*)d_in[3];
    const float* w_merge = (const float*)d_in[4];
    const float* gm      = (const float*)d_in[5];
    const float* bm      = (const float*)d_in[6];
    const float* w_fc1   = (const float*)d_in[7];
    const float* g1      = (const float*)d_in[8];
    const float* b1      = (const float*)d_in[9];
    const float* w_fc2   = (const float*)d_in[10];
    const float* g2      = (const float*)d_in[11];
    const float* b2      = (const float*)d_in[12];
    float* out = (float*)d_out;

    float *yqkv, *y2, *xr, *h1, *y3, *part;
    __half *vh, *obuf, *xh, *xrh, *h1h, *wq, *wm, *w1, *w2;
    float *scq, *shq, *scm, *shm, *sc1, *sh1, *sc2, *sh2;
    cudaGetSymbolAddress((void**)&yqkv, g_yqkv);
    cudaGetSymbolAddress((void**)&vh,   g_vh);
    cudaGetSymbolAddress((void**)&obuf, g_obuf);
    cudaGetSymbolAddress((void**)&y2,   g_y2);
    cudaGetSymbolAddress((void**)&xr,   g_xr);
    cudaGetSymbolAddress((void**)&xrh,  g_xrh);
    cudaGetSymbolAddress((void**)&xh,   g_xh);
    cudaGetSymbolAddress((void**)&h1,   g_h1);
    cudaGetSymbolAddress((void**)&h1h,  g_h1h);
    cudaGetSymbolAddress((void**)&y3,   g_y3);
    cudaGetSymbolAddress((void**)&part, g_part);
    cudaGetSymbolAddress((void**)&scq, g_sc_qkv);
    cudaGetSymbolAddress((void**)&shq, g_sh_qkv);
    cudaGetSymbolAddress((void**)&scm, g_sc_mg);
    cudaGetSymbolAddress((void**)&shm, g_sh_mg);
    cudaGetSymbolAddress((void**)&sc1, g_sc_f1);
    cudaGetSymbolAddress((void**)&sh1, g_sh_f1);
    cudaGetSymbolAddress((void**)&sc2, g_sc_f2);
    cudaGetSymbolAddress((void**)&sh2, g_sh_f2);
    cudaGetSymbolAddress((void**)&wq, g_wq);
    cudaGetSymbolAddress((void**)&wm, g_wm);
    cudaGetSymbolAddress((void**)&w1, g_w1);
    cudaGetSymbolAddress((void**)&w2, g_w2);

    cudaFuncSetAttribute(f16_gemm, cudaFuncAttributeMaxDynamicSharedMemorySize, GEMM_SMEM);
    cudaFuncSetAttribute(flash_attn, cudaFuncAttributeMaxDynamicSharedMemorySize, FL_SMEM);

    round_all<<<1536, 256>>>(w_qkv, wq, w_merge, wm, w_fc1, w1, w_fc2, w2);
    f2h<<<(NB * C_IN * NPix / 4 + 255) / 256, 256>>>(x, xh, NB * C_IN * NPix / 4);

    f16_gemm<<<dim3(C_QKV/128, NPix/128, NB), 256, GEMM_SMEM>>>(wq, xh, yqkv, part, C_QKV, NPix, C_IN);
    v_to_half<<<4096, 256>>>(yqkv, vh);
    bn_finalize<<<(C_QKV + 127) / 128, 128>>>(part, gq, bq, scq, shq, C_QKV);
    flash_attn<<<dim3(8, 64), 256, FL_SMEM>>>(yqkv, vh, scq, shq, obuf);
    f16_gemm<<<dim3(C_MG/128, NPix/128, NB), 256, GEMM_SMEM>>>(wm, obuf, y2, part, C_MG, NPix, 1024);
    bn_finalize<<<(C_MG + 127) / 128, 128>>>(part, gm, bm, scm, shm, C_MG);
    resadd_bn_dual<<<(NB * C_IN * NPix / 4 + 255) / 256, 256>>>(x, y2, scm, shm, xr, xrh, C_MG, NB * C_IN * NPix / 4);
    f16_gemm<<<dim3(C_F1/128, NPix/128, NB), 256, GEMM_SMEM>>>(w1, xrh, h1, part, C_F1, NPix, C_IN);
    bn_finalize<<<(C_F1 + 127) / 128, 128>>>(part, g1, b1, sc1, sh1, C_F1);
    bn_gelu_half<<<(NB * C_F1 * NPix / 4 + 255) / 256, 256>>>(h1, h1h, sc1, sh1, C_F1, NB * C_F1 * NPix / 4);
    f16_gemm<<<dim3(C_F2/128, NPix/128, NB), 256, GEMM_SMEM>>>(w2, h1h, y3, part, C_F2, NPix, C_F1);
    bn_finalize<<<(C_F2 + 127) / 128, 128>>>(part, g2, b2, sc2, sh2, C_F2);
    resadd_bn<<<(NB * C_F2 * NPix / 4 + 255) / 256, 256>>>(xr, y3, sc2, sh2, out, C_F2, NB * C_F2 * NPix / 4);
}

// round 14
// speedup vs baseline: 6.1151x; 1.2311x over previous
#include <cuda_runtime.h>
#include <cuda_fp16.h>
#include <cstdint>
#include <math.h>

#define NB    8
#define NPix  1024
#define C_IN  384
#define C_QKV 1536
#define C_MG  384
#define C_F1  768
#define C_F2  384
#define DK    32
#define DV    128
#define NPARTS 64

__device__ float  g_yqkv[NB * C_QKV * NPix];
__device__ __half g_kh[NB * 8 * 32 * NPix];
__device__ __half g_vh[NB * 8 * 128 * NPix];
__device__ __half g_obuf[NB * 1024 * NPix];
__device__ float  g_y2 [NB * C_MG * NPix];
__device__ float  g_xr [NB * C_IN * NPix];
__device__ __half g_xrh[NB * C_IN * NPix];
__device__ __half g_xh [NB * C_IN * NPix];
__device__ float  g_h1 [NB * C_F1 * NPix];
__device__ __half g_h1h[NB * C_F1 * NPix];
__device__ float  g_y3 [NB * C_F2 * NPix];
__device__ float  g_part[NPARTS * C_QKV * 2];
__device__ float  g_sc_qkv[C_QKV], g_sh_qkv[C_QKV];
__device__ float  g_sc_mg [C_MG ], g_sh_mg [C_MG ];
__device__ float  g_sc_f1 [C_F1 ], g_sh_f1 [C_F1 ];
__device__ float  g_sc_f2 [C_F2 ], g_sh_f2 [C_F2 ];
__device__ __half g_wq[C_QKV * C_IN];
__device__ __half g_wm[C_MG * 1024];
__device__ __half g_w1[C_F1 * C_IN];
__device__ __half g_w2[C_F2 * C_F1];

__device__ __forceinline__ float gelu_exact(float v) { return v * normcdff(v); }

__device__ __forceinline__ void mma_f16_16x8x16(float d[4], const uint32_t a[4],
                                                uint32_t b0, uint32_t b1)
{
    asm volatile(
        "mma.sync.aligned.m16n8k16.row.col.f32.f16.f16.f32 "
        "{%0,%1,%2,%3}, {%4,%5,%6,%7}, {%8,%9}, {%0,%1,%2,%3};"
        : "+f"(d[0]), "+f"(d[1]), "+f"(d[2]), "+f"(d[3])
        : "r"(a[0]), "r"(a[1]), "r"(a[2]), "r"(a[3]), "r"(b0), "r"(b1));
}

__device__ __forceinline__ void ldm_x4(uint32_t r[4], uint32_t addr) {
    asm volatile("ldmatrix.sync.aligned.m8n8.x4.shared.b16 {%0,%1,%2,%3}, [%4];"
                 : "=r"(r[0]), "=r"(r[1]), "=r"(r[2]), "=r"(r[3]) : "r"(addr));
}
__device__ __forceinline__ void ldm_x4t(uint32_t r[4], uint32_t addr) {
    asm volatile("ldmatrix.sync.aligned.m8n8.x4.trans.shared.b16 {%0,%1,%2,%3}, [%4];"
                 : "=r"(r[0]), "=r"(r[1]), "=r"(r[2]), "=r"(r[3]) : "r"(addr));
}

__device__ __forceinline__ void cp16(uint32_t saddr, const void* gptr) {
    asm volatile("cp.async.cg.shared.global [%0], [%1], 16;" :: "r"(saddr), "l"(gptr));
}
#define CP_COMMIT asm volatile("cp.async.commit_group;" ::: "memory")
#define CP_WAIT1  asm volatile("cp.async.wait_group 1;" ::: "memory")
#define CP_WAIT0  asm volatile("cp.async.wait_group 0;" ::: "memory")

// ---------------- weight fp32 -> fp16 (single launch) ----------------
__global__ void round_all(const float* __restrict__ w0, __half* __restrict__ o0,
                          const float* __restrict__ w1, __half* __restrict__ o1,
                          const float* __restrict__ w2, __half* __restrict__ o2,
                          const float* __restrict__ w3, __half* __restrict__ o3)
{
    int i = blockIdx.x * 256 + threadIdx.x;
    const float* w; __half* o; int j = i;
    if (j < 147456)                 { w = w0; o = o0; }
    else if ((j -= 147456) < 98304) { w = w1; o = o1; }
    else if ((j -=  98304) < 73728) { w = w2; o = o2; }
    else                            { j -= 73728; w = w3; o = o3; }
    float4 v = ((const float4*)w)[j];
    __half2* d = (__half2*)o + 2 * j;
    d[0] = __floats2half2_rn(v.x, v.y);
    d[1] = __floats2half2_rn(v.z, v.w);
}

__global__ void f2h(const float* __restrict__ src, __half* __restrict__ dst, int n4)
{
    int i = blockIdx.x * 256 + threadIdx.x;
    if (i >= n4) return;
    float4 v = ((const float4*)src)[i];
    __half2* d = (__half2*)dst + 2 * i;
    d[0] = __floats2half2_rn(v.x, v.y);
    d[1] = __floats2half2_rn(v.z, v.w);
}

// ---------------- K,V -> half pre-pass ----------------
// kh: [bh*32 + d][1024], vh: [bh*128 + dv][1024]
__global__ void kv_to_half(const float* __restrict__ yqkv,
                           __half* __restrict__ kh, __half* __restrict__ vh)
{
    int i = blockIdx.x * 256 + threadIdx.x;   // 8 halves each; rows = 2048 K + 8192 V
    int row = i >> 7;
    int col = (i & 127) << 3;
    const float* src;
    __half* dst;
    if (row < 2048) {
        int bh = row >> 5, d = row & 31;
        int b = bh >> 3, h = bh & 7;
        src = yqkv + ((size_t)(b * 1536 + h * 192 + DK + d)) * 1024 + col;
        dst = kh + (size_t)row * 1024 + col;
    } else {
        int r = row - 2048;
        int bh = r >> 7, dv = r & 127;
        int b = bh >> 3, h = bh & 7;
        src = yqkv + ((size_t)(b * 1536 + h * 192 + 2 * DK + dv)) * 1024 + col;
        dst = vh + (size_t)r * 1024 + col;
    }
    float4 v0 = *(const float4*)src;
    float4 v1 = *(const float4*)(src + 4);
    __half2* d2 = (__half2*)dst;
    d2[0] = __floats2half2_rn(v0.x, v0.y);
    d2[1] = __floats2half2_rn(v0.z, v0.w);
    d2[2] = __floats2half2_rn(v1.x, v1.y);
    d2[3] = __floats2half2_rn(v1.z, v1.w);
}

// ---------------- fp16 GEMM + fused BN partial stats ----------------------
#define F16_STG_B 18944
#define GEMM_SMEM (3 * F16_STG_B)

__global__ void __launch_bounds__(256, 2) f16_gemm(const __half* __restrict__ A,
                                                   const __half* __restrict__ Bg,
                                                   float* __restrict__ Cg,
                                                   float* __restrict__ part,
                                                   int M, int N, int K)
{
    extern __shared__ char smc[];
    const uint32_t sbase = (uint32_t)__cvta_generic_to_shared(smc);
    float* sm = (float*)smc;

    const int tid  = threadIdx.x;
    const int wid  = tid >> 5;
    const int lane = tid & 31;
    const int gid  = lane >> 2;
    const int tid4 = lane & 3;
    const int wm   = (wid & 1) * 64;
    const int wn   = (wid >> 1) * 32;

    const int mBase = blockIdx.x * 128, nBase = blockIdx.y * 128;
    const __half* Bp = Bg + (size_t)blockIdx.z * K * N;
    float*        Cp = Cg + (size_t)blockIdx.z * M * N;

    const int nst = K >> 5;

    const int lt = lane >> 3, lr = lane & 7;
    uint32_t aoff[4];
#pragma unroll
    for (int mi = 0; mi < 4; ++mi)
        aoff[mi] = (uint32_t)((wm + mi * 16 + (lt & 1) * 8 + lr) * 80 + (lt >> 1) * 16);
    uint32_t boff[2];
#pragma unroll
    for (int nip = 0; nip < 2; ++nip)
        boff[nip] = (uint32_t)(10240 + ((lt & 1) * 8 + lr) * 272 +
                               (wn + nip * 16 + (lt >> 1) * 8) * 2);

#define ISSUE_STAGE(s_) do {                                                   \
        int _s = (s_);                                                         \
        uint32_t sa = sbase + (_s % 3) * F16_STG_B;                            \
        int _k0 = _s << 5;                                                     \
        _Pragma("unroll")                                                      \
        for (int t = 0; t < 2; ++t) {                                          \
            int c = tid + t * 256;                                             \
            int m = c >> 2, j = c & 3;                                         \
            cp16(sa + m * 80 + j * 16,                                         \
                 &A[(size_t)(mBase + m) * K + _k0 + (j << 3)]);                \
        }                                                                      \
        _Pragma("unroll")                                                      \
        for (int t = 0; t < 2; ++t) {                                          \
            int c = tid + t * 256;                                             \
            int k = c >> 4, j = c & 15;                                        \
            cp16(sa + 10240 + k * 272 + j * 16,                                \
                 &Bp[(size_t)(_k0 + k) * N + nBase + (j << 3)]);               \
        }                                                                      \
    } while (0)

    float d[4][4][4];
#pragma unroll
    for (int mi = 0; mi < 4; ++mi)
#pragma unroll
        for (int ni = 0; ni < 4; ++ni)
#pragma unroll
            for (int r = 0; r < 4; ++r) d[mi][ni][r] = 0.f;

    ISSUE_STAGE(0); CP_COMMIT;
    ISSUE_STAGE(1); CP_COMMIT;

    for (int s = 0; s < nst; ++s) {
        CP_WAIT1;
        __syncthreads();
        if (s + 2 < nst) ISSUE_STAGE(s + 2);
        CP_COMMIT;

        uint32_t stg = sbase + (s % 3) * F16_STG_B;

#pragma unroll
        for (int ks = 0; ks < 2; ++ks) {
            uint32_t af[4][4];
#pragma unroll
            for (int mi = 0; mi < 4; ++mi)
                ldm_x4(af[mi], stg + aoff[mi] + ks * 32);
            uint32_t bf0[4], bf1[4];
            ldm_x4t(bf0, stg + boff[0] + ks * 4352);
            ldm_x4t(bf1, stg + boff[1] + ks * 4352);
#pragma unroll
            for (int mi = 0; mi < 4; ++mi) {
                mma_f16_16x8x16(d[mi][0], af[mi], bf0[0], bf0[1]);
                mma_f16_16x8x16(d[mi][1], af[mi], bf0[2], bf0[3]);
                mma_f16_16x8x16(d[mi][2], af[mi], bf1[0], bf1[1]);
                mma_f16_16x8x16(d[mi][3], af[mi], bf1[2], bf1[3]);
            }
        }
    }
#undef ISSUE_STAGE

    float sl[4], ql[4], sh_[4], qh[4];
#pragma unroll
    for (int mi = 0; mi < 4; ++mi) {
        sl[mi] = ql[mi] = sh_[mi] = qh[mi] = 0.f;
        int row = mBase + wm + mi * 16 + gid;
#pragma unroll
        for (int ni = 0; ni < 4; ++ni) {
            int col = nBase + wn + ni * 8 + 2 * tid4;
            sl[mi] += d[mi][ni][0] + d[mi][ni][1];
            ql[mi] += d[mi][ni][0] * d[mi][ni][0] + d[mi][ni][1] * d[mi][ni][1];
            sh_[mi] += d[mi][ni][2] + d[mi][ni][3];
            qh[mi] += d[mi][ni][2] * d[mi][ni][2] + d[mi][ni][3] * d[mi][ni][3];
            *(float2*)&Cp[(size_t)row * N + col] =
                make_float2(d[mi][ni][0], d[mi][ni][1]);
            *(float2*)&Cp[(size_t)(row + 8) * N + col] =
                make_float2(d[mi][ni][2], d[mi][ni][3]);
        }
#pragma unroll
        for (int off = 1; off <= 2; off <<= 1) {
            sl[mi]  += __shfl_xor_sync(0xffffffffu, sl[mi],  off);
            ql[mi]  += __shfl_xor_sync(0xffffffffu, ql[mi],  off);
            sh_[mi] += __shfl_xor_sync(0xffffffffu, sh_[mi], off);
            qh[mi]  += __shfl_xor_sync(0xffffffffu, qh[mi],  off);
        }
    }
    __syncthreads();
    float* pb = sm;
    if (tid4 == 0) {
        int g = wid >> 1;
#pragma unroll
        for (int mi = 0; mi < 4; ++mi) {
            int lr2 = wm + mi * 16 + gid;
            pb[(g * 128 + lr2) * 2 + 0]     = sl[mi];
            pb[(g * 128 + lr2) * 2 + 1]     = ql[mi];
            pb[(g * 128 + lr2 + 8) * 2 + 0] = sh_[mi];
            pb[(g * 128 + lr2 + 8) * 2 + 1] = qh[mi];
        }
    }
    __syncthreads();
    if (tid < 128) {
        float s = 0.f, q = 0.f;
#pragma unroll
        for (int g = 0; g < 4; ++g) {
            s += pb[(g * 128 + tid) * 2 + 0];
            q += pb[(g * 128 + tid) * 2 + 1];
        }
        int pidx = blockIdx.y * gridDim.z + blockIdx.z;
        part[((size_t)pidx * M + mBase + tid) * 2 + 0] = s;
        part[((size_t)pidx * M + mBase + tid) * 2 + 1] = q;
    }
}

// ---------------- BN finalize ----------------
__global__ void bn_finalize(const float* __restrict__ part,
                            const float* __restrict__ gamma,
                            const float* __restrict__ beta,
                            float* __restrict__ scl, float* __restrict__ shf, int C)
{
    int c = blockIdx.x * 128 + threadIdx.x;
    if (c >= C) return;
    float s = 0.f, q = 0.f;
    for (int p = 0; p < NPARTS; ++p) {
        s += part[((size_t)p * C + c) * 2 + 0];
        q += part[((size_t)p * C + c) * 2 + 1];
    }
    const float invN = 1.f / (NB * NPix);
    float mean = s * invN;
    float var  = q * invN - mean * mean;
    float sc   = gamma[c] * rsqrtf(var + 1e-5f);
    scl[c] = sc;
    shf[c] = beta[c] - mean * sc;
}

// ---------------- flash attention: all-fp16 MMAs, cp.async 2-stage --------
// stage (20992 B): K half [32][72h, pitch 144B] @0, V half [128][128B] @4608 (XOR swizzle)
// Qh half [32][136h, pitch 272B] @41984 (8704 B). Os fp32 [128][132] aliases @0.
#define FL_STG_B 20992
#define FL_QH_OFF (2 * FL_STG_B)
#define FL_SMEM 67584

__global__ void __launch_bounds__(256) flash_attn(const float* __restrict__ yqkv,
                                                  const __half* __restrict__ kh,
                                                  const __half* __restrict__ vh,
                                                  const float* __restrict__ scl,
                                                  const float* __restrict__ shf,
                                                  __half* __restrict__ obuf)
{
    extern __shared__ float fsm[];
    const uint32_t sbase = (uint32_t)__cvta_generic_to_shared(fsm);
    __half* Qh = (__half*)((char*)fsm + FL_QH_OFF);
    float* Os = fsm;

    const int bh = blockIdx.y, b = bh >> 3, h = bh & 7;
    const int qBase = blockIdx.x * 128;
    const int tid = threadIdx.x, wid = tid >> 5, lane = tid & 31;
    const int gid = lane >> 2, tid4 = lane & 3;
    const int lt = lane >> 3, lr = lane & 7;
    const float* base = yqkv + (size_t)b * C_QKV * NPix;
    const __half* khb = kh + (size_t)(bh * 32) * NPix;
    const __half* vbase = vh + (size_t)(bh * 128) * NPix;

#define FL_ISSUE(i_) do {                                                      \
        int _k0 = (i_) << 6;                                                   \
        uint32_t sa = sbase + ((i_) & 1) * FL_STG_B;                           \
        {                                                                      \
            int r = tid >> 3, j = tid & 7;                                     \
            cp16(sa + r * 144 + j * 16,                                        \
                 &khb[(size_t)r * NPix + _k0 + (j << 3)]);                     \
        }                                                                      \
        _Pragma("unroll")                                                      \
        for (int t = 0; t < 4; ++t) {                                          \
            int c = tid + t * 256;                                             \
            int dv = c >> 3, j = c & 7;                                        \
            cp16(sa + 4608 + dv * 128 + ((j ^ (dv & 7)) << 4),                 \
                 &vbase[(size_t)dv * NPix + _k0 + (j << 3)]);                  \
        }                                                                      \
    } while (0)

    FL_ISSUE(0); CP_COMMIT;

    // Q tile: q'' = (q*scq+shq) * sck / sqrt(dk), fp16 in Qh[d][q]
    for (int i = tid; i < 32 * 128; i += 256) {
        int d = i >> 7, q = i & 127;
        int chq = h * 192 + d, chk = chq + DK;
        float fac = scl[chk] * 0.17677669529663687f;
        Qh[d * 136 + q] =
            __float2half((base[(size_t)chq * NPix + qBase + q] * scl[chq] + shf[chq]) * fac);
    }
    __syncthreads();

    // preload A-fragments (Q): ldmatrix.trans of [d][q], a = {r0,r2,r1,r3}
    uint32_t qf[2][4];
    {
        uint32_t qaddr = sbase + FL_QH_OFF + ((lt & 1) * 8 + lr) * 272 +
                         (wid * 16 + (lt >> 1) * 8) * 2;
#pragma unroll
        for (int ks = 0; ks < 2; ++ks) {
            uint32_t r[4];
            ldm_x4t(r, qaddr + ks * 16 * 272);
            qf[ks][0] = r[0]; qf[ks][1] = r[2]; qf[ks][2] = r[1]; qf[ks][3] = r[3];
        }
    }

    const uint32_t kldm = ((lt & 1) * 8 + lr) * 144 + (lt >> 1) * 16;

    float o[16][4];
#pragma unroll
    for (int nt = 0; nt < 16; ++nt)
#pragma unroll
        for (int r = 0; r < 4; ++r) o[nt][r] = 0.f;
    float m0 = -1e30f, m1 = -1e30f, l0 = 0.f, l1 = 0.f;

    for (int it = 0; it < 16; ++it) {
        __syncthreads();
        if (it + 1 < 16) { FL_ISSUE(it + 1); CP_COMMIT; CP_WAIT1; }
        else             { CP_WAIT0; }
        __syncthreads();

        uint32_t sK = sbase + (it & 1) * FL_STG_B;
        const char* Vc = (const char*)fsm + (it & 1) * FL_STG_B + 4608;

        // S = Q . K (fp16 k16), keys in groups of 16 per ldmatrix
        float s[8][4];
#pragma unroll
        for (int ni = 0; ni < 8; ++ni)
#pragma unroll
            for (int r = 0; r < 4; ++r) s[ni][r] = 0.f;
#pragma unroll
        for (int ks = 0; ks < 2; ++ks) {
#pragma unroll
            for (int g4 = 0; g4 < 4; ++g4) {
                uint32_t kb[4];
                ldm_x4t(kb, sK + kldm + ks * 2304 + g4 * 32);
                mma_f16_16x8x16(s[g4 * 2],     qf[ks], kb[0], kb[1]);
                mma_f16_16x8x16(s[g4 * 2 + 1], qf[ks], kb[2], kb[3]);
            }
        }

        // online softmax
        float t0 = -1e30f, t1 = -1e30f;
#pragma unroll
        for (int ni = 0; ni < 8; ++ni) {
            t0 = fmaxf(t0, fmaxf(s[ni][0], s[ni][1]));
            t1 = fmaxf(t1, fmaxf(s[ni][2], s[ni][3]));
        }
        t0 = fmaxf(t0, __shfl_xor_sync(0xffffffffu, t0, 1));
        t0 = fmaxf(t0, __shfl_xor_sync(0xffffffffu, t0, 2));
        t1 = fmaxf(t1, __shfl_xor_sync(0xffffffffu, t1, 1));
        t1 = fmaxf(t1, __shfl_xor_sync(0xffffffffu, t1, 2));
        float mn0 = fmaxf(m0, t0), mn1 = fmaxf(m1, t1);
        float a0 = __expf(m0 - mn0), a1 = __expf(m1 - mn1);
        m0 = mn0; m1 = mn1;

        float ps0 = 0.f, ps1 = 0.f;
#pragma unroll
        for (int ni = 0; ni < 8; ++ni) {
            s[ni][0] = __expf(s[ni][0] - mn0);
            s[ni][1] = __expf(s[ni][1] - mn0);
            s[ni][2] = __expf(s[ni][2] - mn1);
            s[ni][3] = __expf(s[ni][3] - mn1);
            ps0 += s[ni][0] + s[ni][1];
            ps1 += s[ni][2] + s[ni][3];
        }
        ps0 += __shfl_xor_sync(0xffffffffu, ps0, 1);
        ps0 += __shfl_xor_sync(0xffffffffu, ps0, 2);
        ps1 += __shfl_xor_sync(0xffffffffu, ps1, 1);
        ps1 += __shfl_xor_sync(0xffffffffu, ps1, 2);
        l0 = l0 * a0 + ps0;
        l1 = l1 * a1 + ps1;

#pragma unroll
        for (int nt = 0; nt < 16; ++nt) {
            o[nt][0] *= a0; o[nt][1] *= a0;
            o[nt][2] *= a1; o[nt][3] *= a1;
        }

        // O += P . V (fp16; P packed from S fragments, never touches smem)
#pragma unroll
        for (int j = 0; j < 4; ++j) {
            uint32_t af[4];
            asm("cvt.rn.f16x2.f32 %0, %1, %2;" : "=r"(af[0]) : "f"(s[2*j][1]),   "f"(s[2*j][0]));
            asm("cvt.rn.f16x2.f32 %0, %1, %2;" : "=r"(af[1]) : "f"(s[2*j][3]),   "f"(s[2*j][2]));
            asm("cvt.rn.f16x2.f32 %0, %1, %2;" : "=r"(af[2]) : "f"(s[2*j+1][1]), "f"(s[2*j+1][0]));
            asm("cvt.rn.f16x2.f32 %0, %1, %2;" : "=r"(af[3]) : "f"(s[2*j+1][3]), "f"(s[2*j+1][2]));
#pragma unroll
            for (int nt = 0; nt < 16; ++nt) {
                int dv = nt * 8 + gid;
                uint32_t b0 = *(const uint32_t*)(Vc + dv * 128 + (((2*j)     ^ (dv & 7)) << 4) + 4 * tid4);
                uint32_t b1 = *(const uint32_t*)(Vc + dv * 128 + (((2*j + 1) ^ (dv & 7)) << 4) + 4 * tid4);
                mma_f16_16x8x16(o[nt], af, b0, b1);
            }
        }
    }
#undef FL_ISSUE

    // normalize + transpose; V's BN applied on final write
    float inv0 = 1.f / l0, inv1 = 1.f / l1;
    __syncthreads();
#pragma unroll
    for (int nt = 0; nt < 16; ++nt) {
        int dv = nt * 8 + 2 * tid4;
        int q  = wid * 16 + gid;
        Os[(size_t)dv * 132 + q]           = o[nt][0] * inv0;
        Os[(size_t)(dv + 1) * 132 + q]     = o[nt][1] * inv0;
        Os[(size_t)dv * 132 + q + 8]       = o[nt][2] * inv1;
        Os[(size_t)(dv + 1) * 132 + q + 8] = o[nt][3] * inv1;
    }
    __syncthreads();
    for (int i = tid; i < 128 * 32; i += 256) {
        int dv = i >> 5, q4 = (i & 31) << 2;
        int chv = h * 192 + 2 * DK + dv;
        float sc = scl[chv], sh = shf[chv];
        int ch = b * 1024 + h * 128 + dv;
        float4 v = *(float4*)&Os[dv * 132 + q4];
        v.x = gelu_exact(v.x * sc + sh); v.y = gelu_exact(v.y * sc + sh);
        v.z = gelu_exact(v.z * sc + sh); v.w = gelu_exact(v.w * sc + sh);
        __half2* dst = (__half2*)(obuf + (size_t)ch * NPix + qBase + q4);
        dst[0] = __floats2half2_rn(v.x, v.y);
        dst[1] = __floats2half2_rn(v.z, v.w);
    }
}

// ---------------- elementwise ----------------
__global__ void resadd_bn_dual(const float* __restrict__ x, const float* __restrict__ y,
                               const float* __restrict__ scl, const float* __restrict__ shf,
                               float* __restrict__ o, __half* __restrict__ oh,
                               int C, int total4)
{
    int i = blockIdx.x * 256 + threadIdx.x;
    if (i >= total4) return;
    int ch = (i >> 8) % C;
    float sc = scl[ch], sh = shf[ch];
    float4 a = ((const float4*)x)[i];
    float4 c = ((const float4*)y)[i];
    a.x += c.x * sc + sh; a.y += c.y * sc + sh;
    a.z += c.z * sc + sh; a.w += c.w * sc + sh;
    ((float4*)o)[i] = a;
    __half2* d = (__half2*)oh + 2 * i;
    d[0] = __floats2half2_rn(a.x, a.y);
    d[1] = __floats2half2_rn(a.z, a.w);
}
__global__ void resadd_bn(const float* __restrict__ x, const float* __restrict__ y,
                          const float* __restrict__ scl, const float* __restrict__ shf,
                          float* __restrict__ o, int C, int total4)
{
    int i = blockIdx.x * 256 + threadIdx.x;
    if (i >= total4) return;
    int ch = (i >> 8) % C;
    float sc = scl[ch], sh = shf[ch];
    float4 a = ((const float4*)x)[i];
    float4 c = ((const float4*)y)[i];
    a.x += c.x * sc + sh; a.y += c.y * sc + sh;
    a.z += c.z * sc + sh; a.w += c.w * sc + sh;
    ((float4*)o)[i] = a;
}
__global__ void bn_gelu_half(const float* __restrict__ y, __half* __restrict__ oh,
                             const float* __restrict__ scl,
                             const float* __restrict__ shf, int C, int total4)
{
    int i = blockIdx.x * 256 + threadIdx.x;
    if (i >= total4) return;
    int ch = (i >> 8) % C;
    float sc = scl[ch], sh = shf[ch];
    float4 v = ((const float4*)y)[i];
    v.x = gelu_exact(v.x * sc + sh); v.y = gelu_exact(v.y * sc + sh);
    v.z = gelu_exact(v.z * sc + sh); v.w = gelu_exact(v.w * sc + sh);
    __half2* d = (__half2*)oh + 2 * i;
    d[0] = __floats2half2_rn(v.x, v.y);
    d[1] = __floats2half2_rn(v.z, v.w);
}

// ---------------- host ----------------
extern "C" void kernel_launch(void* const* d_in, const int* in_sizes, int n_in,
                              void* d_out, int out_size)
{
    const float* x       = (const float*)d_in[0];
    const float* w_qkv   = (const float*)d_in[1];
    const float* gq      = (const float*)d_in[2];
    const float* bq      = (const float*)d_in[3];
    const float* w_merge = (const float*)d_in[4];
    const float* gm      = (const float*)d_in[5];
    const float* bm      = (const float*)d_in[6];
    const float* w_fc1   = (const float*)d_in[7];
    const float* g1      = (const float*)d_in[8];
    const float* b1      = (const float*)d_in[9];
    const float* w_fc2   = (const float*)d_in[10];
    const float* g2      = (const float*)d_in[11];
    const float* b2      = (const float*)d_in[12];
    float* out = (float*)d_out;

    float *yqkv, *y2, *xr, *h1, *y3, *part;
    __half *kh, *vh, *obuf, *xh, *xrh, *h1h, *wq, *wm, *w1, *w2;
    float *scq, *shq, *scm, *shm, *sc1, *sh1, *sc2, *sh2;
    cudaGetSymbolAddress((void**)&yqkv, g_yqkv);
    cudaGetSymbolAddress((void**)&kh,   g_kh);
    cudaGetSymbolAddress((void**)&vh,   g_vh);
    cudaGetSymbolAddress((void**)&obuf, g_obuf);
    cudaGetSymbolAddress((void**)&y2,   g_y2);
    cudaGetSymbolAddress((void**)&xr,   g_xr);
    cudaGetSymbolAddress((void**)&xrh,  g_xrh);
    cudaGetSymbolAddress((void**)&xh,   g_xh);
    cudaGetSymbolAddress((void**)&h1,   g_h1);
    cudaGetSymbolAddress((void**)&h1h,  g_h1h);
    cudaGetSymbolAddress((void**)&y3,   g_y3);
    cudaGetSymbolAddress((void**)&part, g_part);
    cudaGetSymbolAddress((void**)&scq, g_sc_qkv);
    cudaGetSymbolAddress((void**)&shq, g_sh_qkv);
    cudaGetSymbolAddress((void**)&scm, g_sc_mg);
    cudaGetSymbolAddress((void**)&shm, g_sh_mg);
    cudaGetSymbolAddress((void**)&sc1, g_sc_f1);
    cudaGetSymbolAddress((void**)&sh1, g_sh_f1);
    cudaGetSymbolAddress((void**)&sc2, g_sc_f2);
    cudaGetSymbolAddress((void**)&sh2, g_sh_f2);
    cudaGetSymbolAddress((void**)&wq, g_wq);
    cudaGetSymbolAddress((void**)&wm, g_wm);
    cudaGetSymbolAddress((void**)&w1, g_w1);
    cudaGetSymbolAddress((void**)&w2, g_w2);

    cudaFuncSetAttribute(f16_gemm, cudaFuncAttributeMaxDynamicSharedMemorySize, GEMM_SMEM);
    cudaFuncSetAttribute(flash_attn, cudaFuncAttributeMaxDynamicSharedMemorySize, FL_SMEM);

    round_all<<<1536, 256>>>(w_qkv, wq, w_merge, wm, w_fc1, w1, w_fc2, w2);
    f2h<<<(NB * C_IN * NPix / 4 + 255) / 256, 256>>>(x, xh, NB * C_IN * NPix / 4);

    f16_gemm<<<dim3(C_QKV/128, NPix/128, NB), 256, GEMM_SMEM>>>(wq, xh, yqkv, part, C_QKV, NPix, C_IN);
    kv_to_half<<<5120, 256>>>(yqkv, kh, vh);
    bn_finalize<<<(C_QKV + 127) / 128, 128>>>(part, gq, bq, scq, shq, C_QKV);
    flash_attn<<<dim3(8, 64), 256, FL_SMEM>>>(yqkv, kh, vh, scq, shq, obuf);
    f16_gemm<<<dim3(C_MG/128, NPix/128, NB), 256, GEMM_SMEM>>>(wm, obuf, y2, part, C_MG, NPix, 1024);
    bn_finalize<<<(C_MG + 127) / 128, 128>>>(part, gm, bm, scm, shm, C_MG);
    resadd_bn_dual<<<(NB * C_IN * NPix / 4 + 255) / 256, 256>>>(x, y2, scm, shm, xr, xrh, C_MG, NB * C_IN * NPix / 4);
    f16_gemm<<<dim3(C_F1/128, NPix/128, NB), 256, GEMM_SMEM>>>(w1, xrh, h1, part, C_F1, NPix, C_IN);
    bn_finalize<<<(C_F1 + 127) / 128, 128>>>(part, g1, b1, sc1, sh1, C_F1);
    bn_gelu_half<<<(NB * C_F1 * NPix / 4 + 255) / 256, 256>>>(h1, h1h, sc1, sh1, C_F1, NB * C_F1 * NPix / 4);
    f16_gemm<<<dim3(C_F2/128, NPix/128, NB), 256, GEMM_SMEM>>>(w2, h1h, y3, part, C_F2, NPix, C_F1);
    bn_finalize<<<(C_F2 + 127) / 128, 128>>>(part, g2, b2, sc2, sh2, C_F2);
    resadd_bn<<<(NB * C_F2 * NPix / 4 + 255) / 256, 256>>>(xr, y3, sc2, sh2, out, C_F2, NB * C_F2 * NPix / 4);
}

// round 15
// speedup vs baseline: 6.4229x; 1.0503x over previous
#include <cuda_runtime.h>
#include <cuda_fp16.h>
#include <cstdint>
#include <math.h>

#define NB    8
#define NPix  1024
#define C_IN  384
#define C_QKV 1536
#define C_MG  384
#define C_F1  768
#define C_F2  384
#define DK    32
#define DV    128
#define NPARTS 64

__device__ __half g_qh[NB * 8 * 32 * NPix];
__device__ __half g_kh[NB * 8 * 32 * NPix];
__device__ __half g_vh[NB * 8 * 128 * NPix];
__device__ __half g_obuf[NB * 1024 * NPix];
__device__ float  g_y2 [NB * C_MG * NPix];
__device__ float  g_xr [NB * C_IN * NPix];
__device__ __half g_xrh[NB * C_IN * NPix];
__device__ __half g_xh [NB * C_IN * NPix];
__device__ float  g_h1 [NB * C_F1 * NPix];
__device__ __half g_h1h[NB * C_F1 * NPix];
__device__ float  g_y3 [NB * C_F2 * NPix];
__device__ float  g_part[NPARTS * C_QKV * 2];
__device__ float  g_sc_qkv[C_QKV], g_sh_qkv[C_QKV];
__device__ float  g_sc_mg [C_MG ], g_sh_mg [C_MG ];
__device__ float  g_sc_f1 [C_F1 ], g_sh_f1 [C_F1 ];
__device__ float  g_sc_f2 [C_F2 ], g_sh_f2 [C_F2 ];
__device__ __half g_wq[C_QKV * C_IN];
__device__ __half g_wm[C_MG * 1024];
__device__ __half g_w1[C_F1 * C_IN];
__device__ __half g_w2[C_F2 * C_F1];

__device__ __forceinline__ float gelu_exact(float v) { return v * normcdff(v); }

__device__ __forceinline__ float ex2f(float x) {
    float r;
    asm("ex2.approx.f32 %0, %1;" : "=f"(r) : "f"(x));
    return r;
}

__device__ __forceinline__ void mma_f16_16x8x16(float d[4], const uint32_t a[4],
                                                uint32_t b0, uint32_t b1)
{
    asm volatile(
        "mma.sync.aligned.m16n8k16.row.col.f32.f16.f16.f32 "
        "{%0,%1,%2,%3}, {%4,%5,%6,%7}, {%8,%9}, {%0,%1,%2,%3};"
        : "+f"(d[0]), "+f"(d[1]), "+f"(d[2]), "+f"(d[3])
        : "r"(a[0]), "r"(a[1]), "r"(a[2]), "r"(a[3]), "r"(b0), "r"(b1));
}

__device__ __forceinline__ void ldm_x4(uint32_t r[4], uint32_t addr) {
    asm volatile("ldmatrix.sync.aligned.m8n8.x4.shared.b16 {%0,%1,%2,%3}, [%4];"
                 : "=r"(r[0]), "=r"(r[1]), "=r"(r[2]), "=r"(r[3]) : "r"(addr));
}
__device__ __forceinline__ void ldm_x4t(uint32_t r[4], uint32_t addr) {
    asm volatile("ldmatrix.sync.aligned.m8n8.x4.trans.shared.b16 {%0,%1,%2,%3}, [%4];"
                 : "=r"(r[0]), "=r"(r[1]), "=r"(r[2]), "=r"(r[3]) : "r"(addr));
}

__device__ __forceinline__ void cp16(uint32_t saddr, const void* gptr) {
    asm volatile("cp.async.cg.shared.global [%0], [%1], 16;" :: "r"(saddr), "l"(gptr));
}
#define CP_COMMIT asm volatile("cp.async.commit_group;" ::: "memory")
#define CP_WAIT1  asm volatile("cp.async.wait_group 1;" ::: "memory")
#define CP_WAIT0  asm volatile("cp.async.wait_group 0;" ::: "memory")

// ---------------- weight fp32 -> fp16 (single launch) ----------------
__global__ void round_all(const float* __restrict__ w0, __half* __restrict__ o0,
                          const float* __restrict__ w1, __half* __restrict__ o1,
                          const float* __restrict__ w2, __half* __restrict__ o2,
                          const float* __restrict__ w3, __half* __restrict__ o3)
{
    int i = blockIdx.x * 256 + threadIdx.x;
    const float* w; __half* o; int j = i;
    if (j < 147456)                 { w = w0; o = o0; }
    else if ((j -= 147456) < 98304) { w = w1; o = o1; }
    else if ((j -=  98304) < 73728) { w = w2; o = o2; }
    else                            { j -= 73728; w = w3; o = o3; }
    float4 v = ((const float4*)w)[j];
    __half2* d = (__half2*)o + 2 * j;
    d[0] = __floats2half2_rn(v.x, v.y);
    d[1] = __floats2half2_rn(v.z, v.w);
}

__global__ void f2h(const float* __restrict__ src, __half* __restrict__ dst, int n4)
{
    int i = blockIdx.x * 256 + threadIdx.x;
    if (i >= n4) return;
    float4 v = ((const float4*)src)[i];
    __half2* d = (__half2*)dst + 2 * i;
    d[0] = __floats2half2_rn(v.x, v.y);
    d[1] = __floats2half2_rn(v.z, v.w);
}

// ---------------- fp16 GEMM + fused BN partial stats -----------------------
// Normal mode (qh==0): Cg fp32 [M,N].
// QKV mode (qh!=0): rows remapped to qh/kh/vh half buffers per channel type.
#define F16_STG_B 18944
#define GEMM_SMEM (3 * F16_STG_B)

__global__ void __launch_bounds__(256, 2) f16_gemm(const __half* __restrict__ A,
                                                   const __half* __restrict__ Bg,
                                                   float* __restrict__ Cg,
                                                   float* __restrict__ part,
                                                   __half* __restrict__ qh,
                                                   __half* __restrict__ kh,
                                                   __half* __restrict__ vh,
                                                   int M, int N, int K)
{
    extern __shared__ char smc[];
    const uint32_t sbase = (uint32_t)__cvta_generic_to_shared(smc);
    float* sm = (float*)smc;

    const int tid  = threadIdx.x;
    const int wid  = tid >> 5;
    const int lane = tid & 31;
    const int gid  = lane >> 2;
    const int tid4 = lane & 3;
    const int wm   = (wid & 1) * 64;
    const int wn   = (wid >> 1) * 32;

    const int mBase = blockIdx.x * 128, nBase = blockIdx.y * 128;
    const __half* Bp = Bg + (size_t)blockIdx.z * K * N;
    float*        Cp = Cg + (size_t)blockIdx.z * M * N;

    const int nst = K >> 5;

    const int lt = lane >> 3, lr = lane & 7;
    uint32_t aoff[4];
#pragma unroll
    for (int mi = 0; mi < 4; ++mi)
        aoff[mi] = (uint32_t)((wm + mi * 16 + (lt & 1) * 8 + lr) * 80 + (lt >> 1) * 16);
    uint32_t boff[2];
#pragma unroll
    for (int nip = 0; nip < 2; ++nip)
        boff[nip] = (uint32_t)(10240 + ((lt & 1) * 8 + lr) * 272 +
                               (wn + nip * 16 + (lt >> 1) * 8) * 2);

#define ISSUE_STAGE(s_) do {                                                   \
        int _s = (s_);                                                         \
        uint32_t sa = sbase + (_s % 3) * F16_STG_B;                            \
        int _k0 = _s << 5;                                                     \
        _Pragma("unroll")                                                      \
        for (int t = 0; t < 2; ++t) {                                          \
            int c = tid + t * 256;                                             \
            int m = c >> 2, j = c & 3;                                         \
            cp16(sa + m * 80 + j * 16,                                         \
                 &A[(size_t)(mBase + m) * K + _k0 + (j << 3)]);                \
        }                                                                      \
        _Pragma("unroll")                                                      \
        for (int t = 0; t < 2; ++t) {                                          \
            int c = tid + t * 256;                                             \
            int k = c >> 4, j = c & 15;                                        \
            cp16(sa + 10240 + k * 272 + j * 16,                                \
                 &Bp[(size_t)(_k0 + k) * N + nBase + (j << 3)]);               \
        }                                                                      \
    } while (0)

    float d[4][4][4];
#pragma unroll
    for (int mi = 0; mi < 4; ++mi)
#pragma unroll
        for (int ni = 0; ni < 4; ++ni)
#pragma unroll
            for (int r = 0; r < 4; ++r) d[mi][ni][r] = 0.f;

    ISSUE_STAGE(0); CP_COMMIT;
    ISSUE_STAGE(1); CP_COMMIT;

    for (int s = 0; s < nst; ++s) {
        CP_WAIT1;
        __syncthreads();
        if (s + 2 < nst) ISSUE_STAGE(s + 2);
        CP_COMMIT;

        uint32_t stg = sbase + (s % 3) * F16_STG_B;

#pragma unroll
        for (int ks = 0; ks < 2; ++ks) {
            uint32_t af[4][4];
#pragma unroll
            for (int mi = 0; mi < 4; ++mi)
                ldm_x4(af[mi], stg + aoff[mi] + ks * 32);
            uint32_t bf0[4], bf1[4];
            ldm_x4t(bf0, stg + boff[0] + ks * 4352);
            ldm_x4t(bf1, stg + boff[1] + ks * 4352);
#pragma unroll
            for (int mi = 0; mi < 4; ++mi) {
                mma_f16_16x8x16(d[mi][0], af[mi], bf0[0], bf0[1]);
                mma_f16_16x8x16(d[mi][1], af[mi], bf0[2], bf0[3]);
                mma_f16_16x8x16(d[mi][2], af[mi], bf1[0], bf1[1]);
                mma_f16_16x8x16(d[mi][3], af[mi], bf1[2], bf1[3]);
            }
        }
    }
#undef ISSUE_STAGE

    float sl[4], ql[4], sh_[4], qh_[4];
#pragma unroll
    for (int mi = 0; mi < 4; ++mi) {
        sl[mi] = ql[mi] = sh_[mi] = qh_[mi] = 0.f;
        int rowl = wm + mi * 16 + gid;
        if (qh) {
            // remap rows to q/k/v half buffers
            int m0 = mBase + rowl, m1 = m0 + 8;
            int h0 = m0 / 192, r0 = m0 % 192;
            int h1r = m1 / 192, r1 = m1 % 192;
            size_t bh0 = (size_t)(blockIdx.z * 8 + h0);
            size_t bh1 = (size_t)(blockIdx.z * 8 + h1r);
            __half* p0 = (r0 < 32) ? qh + (bh0 * 32 + r0) * NPix
                        : (r0 < 64) ? kh + (bh0 * 32 + r0 - 32) * NPix
                                    : vh + (bh0 * 128 + r0 - 64) * NPix;
            __half* p1 = (r1 < 32) ? qh + (bh1 * 32 + r1) * NPix
                        : (r1 < 64) ? kh + (bh1 * 32 + r1 - 32) * NPix
                                    : vh + (bh1 * 128 + r1 - 64) * NPix;
#pragma unroll
            for (int ni = 0; ni < 4; ++ni) {
                int col = nBase + wn + ni * 8 + 2 * tid4;
                sl[mi] += d[mi][ni][0] + d[mi][ni][1];
                ql[mi] += d[mi][ni][0] * d[mi][ni][0] + d[mi][ni][1] * d[mi][ni][1];
                sh_[mi] += d[mi][ni][2] + d[mi][ni][3];
                qh_[mi] += d[mi][ni][2] * d[mi][ni][2] + d[mi][ni][3] * d[mi][ni][3];
                *(__half2*)(p0 + col) = __floats2half2_rn(d[mi][ni][0], d[mi][ni][1]);
                *(__half2*)(p1 + col) = __floats2half2_rn(d[mi][ni][2], d[mi][ni][3]);
            }
        } else {
            int row = mBase + rowl;
#pragma unroll
            for (int ni = 0; ni < 4; ++ni) {
                int col = nBase + wn + ni * 8 + 2 * tid4;
                sl[mi] += d[mi][ni][0] + d[mi][ni][1];
                ql[mi] += d[mi][ni][0] * d[mi][ni][0] + d[mi][ni][1] * d[mi][ni][1];
                sh_[mi] += d[mi][ni][2] + d[mi][ni][3];
                qh_[mi] += d[mi][ni][2] * d[mi][ni][2] + d[mi][ni][3] * d[mi][ni][3];
                *(float2*)&Cp[(size_t)row * N + col] =
                    make_float2(d[mi][ni][0], d[mi][ni][1]);
                *(float2*)&Cp[(size_t)(row + 8) * N + col] =
                    make_float2(d[mi][ni][2], d[mi][ni][3]);
            }
        }
#pragma unroll
        for (int off = 1; off <= 2; off <<= 1) {
            sl[mi]  += __shfl_xor_sync(0xffffffffu, sl[mi],  off);
            ql[mi]  += __shfl_xor_sync(0xffffffffu, ql[mi],  off);
            sh_[mi] += __shfl_xor_sync(0xffffffffu, sh_[mi], off);
            qh_[mi] += __shfl_xor_sync(0xffffffffu, qh_[mi], off);
        }
    }
    __syncthreads();
    float* pb = sm;
    if (tid4 == 0) {
        int g = wid >> 1;
#pragma unroll
        for (int mi = 0; mi < 4; ++mi) {
            int lr2 = wm + mi * 16 + gid;
            pb[(g * 128 + lr2) * 2 + 0]     = sl[mi];
            pb[(g * 128 + lr2) * 2 + 1]     = ql[mi];
            pb[(g * 128 + lr2 + 8) * 2 + 0] = sh_[mi];
            pb[(g * 128 + lr2 + 8) * 2 + 1] = qh_[mi];
        }
    }
    __syncthreads();
    if (tid < 128) {
        float s = 0.f, q = 0.f;
#pragma unroll
        for (int g = 0; g < 4; ++g) {
            s += pb[(g * 128 + tid) * 2 + 0];
            q += pb[(g * 128 + tid) * 2 + 1];
        }
        int pidx = blockIdx.y * gridDim.z + blockIdx.z;
        part[((size_t)pidx * M + mBase + tid) * 2 + 0] = s;
        part[((size_t)pidx * M + mBase + tid) * 2 + 1] = q;
    }
}

// ---------------- BN finalize ----------------
__global__ void bn_finalize(const float* __restrict__ part,
                            const float* __restrict__ gamma,
                            const float* __restrict__ beta,
                            float* __restrict__ scl, float* __restrict__ shf, int C)
{
    int c = blockIdx.x * 128 + threadIdx.x;
    if (c >= C) return;
    float s = 0.f, q = 0.f;
    for (int p = 0; p < NPARTS; ++p) {
        s += part[((size_t)p * C + c) * 2 + 0];
        q += part[((size_t)p * C + c) * 2 + 1];
    }
    const float invN = 1.f / (NB * NPix);
    float mean = s * invN;
    float var  = q * invN - mean * mean;
    float sc   = gamma[c] * rsqrtf(var + 1e-5f);
    scl[c] = sc;
    shf[c] = beta[c] - mean * sc;
}

// ---------------- flash attention: all-fp16 MMAs, exp2 softmax ------------
#define FL_STG_B 20992
#define FL_QH_OFF (2 * FL_STG_B)
#define FL_SMEM 67584

__global__ void __launch_bounds__(256) flash_attn(const __half* __restrict__ qhg,
                                                  const __half* __restrict__ kh,
                                                  const __half* __restrict__ vh,
                                                  const float* __restrict__ scl,
                                                  const float* __restrict__ shf,
                                                  __half* __restrict__ obuf)
{
    extern __shared__ float fsm[];
    const uint32_t sbase = (uint32_t)__cvta_generic_to_shared(fsm);
    __half* Qh = (__half*)((char*)fsm + FL_QH_OFF);
    float* Os = fsm;

    const int bh = blockIdx.y, b = bh >> 3, h = bh & 7;
    const int qBase = blockIdx.x * 128;
    const int tid = threadIdx.x, wid = tid >> 5, lane = tid & 31;
    const int gid = lane >> 2, tid4 = lane & 3;
    const int lt = lane >> 3, lr = lane & 7;
    const __half* qhb = qhg + (size_t)(bh * 32) * NPix;
    const __half* khb = kh + (size_t)(bh * 32) * NPix;
    const __half* vbase = vh + (size_t)(bh * 128) * NPix;

#define FL_ISSUE(i_) do {                                                      \
        int _k0 = (i_) << 6;                                                   \
        uint32_t sa = sbase + ((i_) & 1) * FL_STG_B;                           \
        {                                                                      \
            int r = tid >> 3, j = tid & 7;                                     \
            cp16(sa + r * 144 + j * 16,                                        \
                 &khb[(size_t)r * NPix + _k0 + (j << 3)]);                     \
        }                                                                      \
        _Pragma("unroll")                                                      \
        for (int t = 0; t < 4; ++t) {                                          \
            int c = tid + t * 256;                                             \
            int dv = c >> 3, j = c & 7;                                        \
            cp16(sa + 4608 + dv * 128 + ((j ^ (dv & 7)) << 4),                 \
                 &vbase[(size_t)dv * NPix + _k0 + (j << 3)]);                  \
        }                                                                      \
    } while (0)

    FL_ISSUE(0); CP_COMMIT;

    // Q tile: q'' = (q*scq+shq) * sck * log2(e)/sqrt(dk)  (exp2 softmax)
    for (int i = tid; i < 32 * 128; i += 256) {
        int d = i >> 7, q = i & 127;
        int chq = h * 192 + d, chk = chq + DK;
        float fac = scl[chk] * 0.17677669529663687f * 1.4426950408889634f;
        float qv = __half2float(qhb[(size_t)d * NPix + qBase + q]);
        Qh[d * 136 + q] = __float2half((qv * scl[chq] + shf[chq]) * fac);
    }
    __syncthreads();

    uint32_t qf[2][4];
    {
        uint32_t qaddr = sbase + FL_QH_OFF + ((lt & 1) * 8 + lr) * 272 +
                         (wid * 16 + (lt >> 1) * 8) * 2;
#pragma unroll
        for (int ks = 0; ks < 2; ++ks) {
            uint32_t r[4];
            ldm_x4t(r, qaddr + ks * 16 * 272);
            qf[ks][0] = r[0]; qf[ks][1] = r[2]; qf[ks][2] = r[1]; qf[ks][3] = r[3];
        }
    }

    const uint32_t kldm = ((lt & 1) * 8 + lr) * 144 + (lt >> 1) * 16;

    float o[16][4];
#pragma unroll
    for (int nt = 0; nt < 16; ++nt)
#pragma unroll
        for (int r = 0; r < 4; ++r) o[nt][r] = 0.f;
    float m0 = -1e30f, m1 = -1e30f, l0 = 0.f, l1 = 0.f;

    for (int it = 0; it < 16; ++it) {
        __syncthreads();
        if (it + 1 < 16) { FL_ISSUE(it + 1); CP_COMMIT; CP_WAIT1; }
        else             { CP_WAIT0; }
        __syncthreads();

        uint32_t sK = sbase + (it & 1) * FL_STG_B;
        const char* Vc = (const char*)fsm + (it & 1) * FL_STG_B + 4608;

        float s[8][4];
#pragma unroll
        for (int ni = 0; ni < 8; ++ni)
#pragma unroll
            for (int r = 0; r < 4; ++r) s[ni][r] = 0.f;
#pragma unroll
        for (int ks = 0; ks < 2; ++ks) {
#pragma unroll
            for (int g4 = 0; g4 < 4; ++g4) {
                uint32_t kb[4];
                ldm_x4t(kb, sK + kldm + ks * 2304 + g4 * 32);
                mma_f16_16x8x16(s[g4 * 2],     qf[ks], kb[0], kb[1]);
                mma_f16_16x8x16(s[g4 * 2 + 1], qf[ks], kb[2], kb[3]);
            }
        }

        float t0 = -1e30f, t1 = -1e30f;
#pragma unroll
        for (int ni = 0; ni < 8; ++ni) {
            t0 = fmaxf(t0, fmaxf(s[ni][0], s[ni][1]));
            t1 = fmaxf(t1, fmaxf(s[ni][2], s[ni][3]));
        }
        t0 = fmaxf(t0, __shfl_xor_sync(0xffffffffu, t0, 1));
        t0 = fmaxf(t0, __shfl_xor_sync(0xffffffffu, t0, 2));
        t1 = fmaxf(t1, __shfl_xor_sync(0xffffffffu, t1, 1));
        t1 = fmaxf(t1, __shfl_xor_sync(0xffffffffu, t1, 2));
        float mn0 = fmaxf(m0, t0), mn1 = fmaxf(m1, t1);
        float a0 = ex2f(m0 - mn0), a1 = ex2f(m1 - mn1);
        m0 = mn0; m1 = mn1;

        float ps0 = 0.f, ps1 = 0.f;
#pragma unroll
        for (int ni = 0; ni < 8; ++ni) {
            s[ni][0] = ex2f(s[ni][0] - mn0);
            s[ni][1] = ex2f(s[ni][1] - mn0);
            s[ni][2] = ex2f(s[ni][2] - mn1);
            s[ni][3] = ex2f(s[ni][3] - mn1);
            ps0 += s[ni][0] + s[ni][1];
            ps1 += s[ni][2] + s[ni][3];
        }
        ps0 += __shfl_xor_sync(0xffffffffu, ps0, 1);
        ps0 += __shfl_xor_sync(0xffffffffu, ps0, 2);
        ps1 += __shfl_xor_sync(0xffffffffu, ps1, 1);
        ps1 += __shfl_xor_sync(0xffffffffu, ps1, 2);
        l0 = l0 * a0 + ps0;
        l1 = l1 * a1 + ps1;

#pragma unroll
        for (int nt = 0; nt < 16; ++nt) {
            o[nt][0] *= a0; o[nt][1] *= a0;
            o[nt][2] *= a1; o[nt][3] *= a1;
        }

#pragma unroll
        for (int j = 0; j < 4; ++j) {
            uint32_t af[4];
            asm("cvt.rn.f16x2.f32 %0, %1, %2;" : "=r"(af[0]) : "f"(s[2*j][1]),   "f"(s[2*j][0]));
            asm("cvt.rn.f16x2.f32 %0, %1, %2;" : "=r"(af[1]) : "f"(s[2*j][3]),   "f"(s[2*j][2]));
            asm("cvt.rn.f16x2.f32 %0, %1, %2;" : "=r"(af[2]) : "f"(s[2*j+1][1]), "f"(s[2*j+1][0]));
            asm("cvt.rn.f16x2.f32 %0, %1, %2;" : "=r"(af[3]) : "f"(s[2*j+1][3]), "f"(s[2*j+1][2]));
#pragma unroll
            for (int nt = 0; nt < 16; ++nt) {
                int dv = nt * 8 + gid;
                uint32_t b0 = *(const uint32_t*)(Vc + dv * 128 + (((2*j)     ^ (dv & 7)) << 4) + 4 * tid4);
                uint32_t b1 = *(const uint32_t*)(Vc + dv * 128 + (((2*j + 1) ^ (dv & 7)) << 4) + 4 * tid4);
                mma_f16_16x8x16(o[nt], af, b0, b1);
            }
        }
    }
#undef FL_ISSUE

    float inv0 = 1.f / l0, inv1 = 1.f / l1;
    __syncthreads();
#pragma unroll
    for (int nt = 0; nt < 16; ++nt) {
        int dv = nt * 8 + 2 * tid4;
        int q  = wid * 16 + gid;
        Os[(size_t)dv * 132 + q]           = o[nt][0] * inv0;
        Os[(size_t)(dv + 1) * 132 + q]     = o[nt][1] * inv0;
        Os[(size_t)dv * 132 + q + 8]       = o[nt][2] * inv1;
        Os[(size_t)(dv + 1) * 132 + q + 8] = o[nt][3] * inv1;
    }
    __syncthreads();
    for (int i = tid; i < 128 * 32; i += 256) {
        int dv = i >> 5, q4 = (i & 31) << 2;
        int chv = h * 192 + 2 * DK + dv;
        float sc = scl[chv], sh = shf[chv];
        int ch = b * 1024 + h * 128 + dv;
        float4 v = *(float4*)&Os[dv * 132 + q4];
        v.x = gelu_exact(v.x * sc + sh); v.y = gelu_exact(v.y * sc + sh);
        v.z = gelu_exact(v.z * sc + sh); v.w = gelu_exact(v.w * sc + sh);
        __half2* dst = (__half2*)(obuf + (size_t)ch * NPix + qBase + q4);
        dst[0] = __floats2half2_rn(v.x, v.y);
        dst[1] = __floats2half2_rn(v.z, v.w);
    }
}

// ---------------- elementwise ----------------
__global__ void resadd_bn_dual(const float* __restrict__ x, const float* __restrict__ y,
                               const float* __restrict__ scl, const float* __restrict__ shf,
                               float* __restrict__ o, __half* __restrict__ oh,
                               int C, int total4)
{
    int i = blockIdx.x * 256 + threadIdx.x;
    if (i >= total4) return;
    int ch = (i >> 8) % C;
    float sc = scl[ch], sh = shf[ch];
    float4 a = ((const float4*)x)[i];
    float4 c = ((const float4*)y)[i];
    a.x += c.x * sc + sh; a.y += c.y * sc + sh;
    a.z += c.z * sc + sh; a.w += c.w * sc + sh;
    ((float4*)o)[i] = a;
    __half2* d = (__half2*)oh + 2 * i;
    d[0] = __floats2half2_rn(a.x, a.y);
    d[1] = __floats2half2_rn(a.z, a.w);
}
__global__ void resadd_bn(const float* __restrict__ x, const float* __restrict__ y,
                          const float* __restrict__ scl, const float* __restrict__ shf,
                          float* __restrict__ o, int C, int total4)
{
    int i = blockIdx.x * 256 + threadIdx.x;
    if (i >= total4) return;
    int ch = (i >> 8) % C;
    float sc = scl[ch], sh = shf[ch];
    float4 a = ((const float4*)x)[i];
    float4 c = ((const float4*)y)[i];
    a.x += c.x * sc + sh; a.y += c.y * sc + sh;
    a.z += c.z * sc + sh; a.w += c.w * sc + sh;
    ((float4*)o)[i] = a;
}
__global__ void bn_gelu_half(const float* __restrict__ y, __half* __restrict__ oh,
                             const float* __restrict__ scl,
                             const float* __restrict__ shf, int C, int total4)
{
    int i = blockIdx.x * 256 + threadIdx.x;
    if (i >= total4) return;
    int ch = (i >> 8) % C;
    float sc = scl[ch], sh = shf[ch];
    float4 v = ((const float4*)y)[i];
    v.x = gelu_exact(v.x * sc + sh); v.y = gelu_exact(v.y * sc + sh);
    v.z = gelu_exact(v.z * sc + sh); v.w = gelu_exact(v.w * sc + sh);
    __half2* d = (__half2*)oh + 2 * i;
    d[0] = __floats2half2_rn(v.x, v.y);
    d[1] = __floats2half2_rn(v.z, v.w);
}

// ---------------- host ----------------
extern "C" void kernel_launch(void* const* d_in, const int* in_sizes, int n_in,
                              void* d_out, int out_size)
{
    const float* x       = (const float*)d_in[0];
    const float* w_qkv   = (const float*)d_in[1];
    const float* gq      = (const float*)d_in[2];
    const float* bq      = (const float*)d_in[3];
    const float* w_merge = (const float*)d_in[4];
    const float* gm      = (const float*)d_in[5];
    const float* bm      = (const float*)d_in[6];
    const float* w_fc1   = (const float*)d_in[7];
    const float* g1      = (const float*)d_in[8];
    const float* b1      = (const float*)d_in[9];
    const float* w_fc2   = (const float*)d_in[10];
    const float* g2      = (const float*)d_in[11];
    const float* b2      = (const float*)d_in[12];
    float* out = (float*)d_out;

    float *y2, *xr, *h1, *y3, *part;
    __half *qh, *kh, *vh, *obuf, *xh, *xrh, *h1h, *wq, *wm, *w1, *w2;
    float *scq, *shq, *scm, *shm, *sc1, *sh1, *sc2, *sh2;
    cudaGetSymbolAddress((void**)&qh,   g_qh);
    cudaGetSymbolAddress((void**)&kh,   g_kh);
    cudaGetSymbolAddress((void**)&vh,   g_vh);
    cudaGetSymbolAddress((void**)&obuf, g_obuf);
    cudaGetSymbolAddress((void**)&y2,   g_y2);
    cudaGetSymbolAddress((void**)&xr,   g_xr);
    cudaGetSymbolAddress((void**)&xrh,  g_xrh);
    cudaGetSymbolAddress((void**)&xh,   g_xh);
    cudaGetSymbolAddress((void**)&h1,   g_h1);
    cudaGetSymbolAddress((void**)&h1h,  g_h1h);
    cudaGetSymbolAddress((void**)&y3,   g_y3);
    cudaGetSymbolAddress((void**)&part, g_part);
    cudaGetSymbolAddress((void**)&scq, g_sc_qkv);
    cudaGetSymbolAddress((void**)&shq, g_sh_qkv);
    cudaGetSymbolAddress((void**)&scm, g_sc_mg);
    cudaGetSymbolAddress((void**)&shm, g_sh_mg);
    cudaGetSymbolAddress((void**)&sc1, g_sc_f1);
    cudaGetSymbolAddress((void**)&sh1, g_sh_f1);
    cudaGetSymbolAddress((void**)&sc2, g_sc_f2);
    cudaGetSymbolAddress((void**)&sh2, g_sh_f2);
    cudaGetSymbolAddress((void**)&wq, g_wq);
    cudaGetSymbolAddress((void**)&wm, g_wm);
    cudaGetSymbolAddress((void**)&w1, g_w1);
    cudaGetSymbolAddress((void**)&w2, g_w2);

    cudaFuncSetAttribute(f16_gemm, cudaFuncAttributeMaxDynamicSharedMemorySize, GEMM_SMEM);
    cudaFuncSetAttribute(flash_attn, cudaFuncAttributeMaxDynamicSharedMemorySize, FL_SMEM);

    round_all<<<1536, 256>>>(w_qkv, wq, w_merge, wm, w_fc1, w1, w_fc2, w2);
    f2h<<<(NB * C_IN * NPix / 4 + 255) / 256, 256>>>(x, xh, NB * C_IN * NPix / 4);

    f16_gemm<<<dim3(C_QKV/128, NPix/128, NB), 256, GEMM_SMEM>>>(wq, xh, nullptr, part, qh, kh, vh, C_QKV, NPix, C_IN);
    bn_finalize<<<(C_QKV + 127) / 128, 128>>>(part, gq, bq, scq, shq, C_QKV);
    flash_attn<<<dim3(8, 64), 256, FL_SMEM>>>(qh, kh, vh, scq, shq, obuf);
    f16_gemm<<<dim3(C_MG/128, NPix/128, NB), 256, GEMM_SMEM>>>(wm, obuf, y2, part, nullptr, nullptr, nullptr, C_MG, NPix, 1024);
    bn_finalize<<<(C_MG + 127) / 128, 128>>>(part, gm, bm, scm, shm, C_MG);
    resadd_bn_dual<<<(NB * C_IN * NPix / 4 + 255) / 256, 256>>>(x, y2, scm, shm, xr, xrh, C_MG, NB * C_IN * NPix / 4);
    f16_gemm<<<dim3(C_F1/128, NPix/128, NB), 256, GEMM_SMEM>>>(w1, xrh, h1, part, nullptr, nullptr, nullptr, C_F1, NPix, C_IN);
    bn_finalize<<<(C_F1 + 127) / 128, 128>>>(part, g1, b1, sc1, sh1, C_F1);
    bn_gelu_half<<<(NB * C_F1 * NPix / 4 + 255) / 256, 256>>>(h1, h1h, sc1, sh1, C_F1, NB * C_F1 * NPix / 4);
    f16_gemm<<<dim3(C_F2/128, NPix/128, NB), 256, GEMM_SMEM>>>(w2, h1h, y3, part, nullptr, nullptr, nullptr, C_F2, NPix, C_F1);
    bn_finalize<<<(C_F2 + 127) / 128, 128>>>(part, g2, b2, sc2, sh2, C_F2);
    resadd_bn<<<(NB * C_F2 * NPix / 4 + 255) / 256, 256>>>(xr, y3, sc2, sh2, out, C_F2, NB * C_F2 * NPix / 4);
}